// round 1
// baseline (speedup 1.0000x reference)
#include <cuda_runtime.h>
#include <math.h>

// Problem constants
#define R      4096      // B*T
#define D      1024
#define DKD    256       // DK
#define NKEYS  32768
#define DM     256
#define KN     8         // K_NEIGHBORS
#define FF     (KN*DM)   // 2048
#define CAP    512
#define MAXKEEP 64
#define CUT_LG  131.0f   // exact-logit prune cut below row max
#define DELTA_S 7.0f     // scan-score threshold (== 140 logits; lg = (2s - q2)/0.1)

// scan tiling
#define TM 16
#define TN 256
#define SPLITS 8

// ---------------- scratch (static device globals; no allocation) ----------------
__device__ float g_q[R * DKD];
__device__ float g_q2[R];
__device__ float g_k2[NKEYS];
__device__ int   g_cidx[R * CAP];
__device__ int   g_cnt[R];
__device__ float g_nearest[(size_t)R * FF];

// ordered-float encoding for unsigned atomicMax
__device__ __forceinline__ unsigned fenc(float f) {
    unsigned u = __float_as_uint(f);
    return (u & 0x80000000u) ? ~u : (u | 0x80000000u);
}
__device__ __forceinline__ float fdec(unsigned e) {
    return __uint_as_float((e & 0x80000000u) ? (e & 0x7fffffffu) : ~e);
}

// ---------------- init: zero candidate counters ----------------
__global__ void init_cnt_kernel(int* __restrict__ cnt) {
    int i = blockIdx.x * blockDim.x + threadIdx.x;
    if (i < R) cnt[i] = 0;
}

// ---------------- row sum of squares (k2 and q2) ----------------
__global__ void rowsumsq_kernel(const float* __restrict__ src, float* __restrict__ dst, int cols) {
    int row  = blockIdx.x * 8 + (threadIdx.x >> 5);
    int lane = threadIdx.x & 31;
    const float* p = src + (size_t)row * cols;
    float s = 0.f;
    for (int e = lane; e < cols; e += 32) { float v = p[e]; s = fmaf(v, v, s); }
    #pragma unroll
    for (int o = 16; o; o >>= 1) s += __shfl_xor_sync(0xffffffffu, s, o);
    if (lane == 0) dst[row] = s;
}

// ---------------- generic tiled GEMM: C[m][n] = sum_k A[m][k]*B[n][k] + bias[n] ----------------
// block tile 64x64, k-chunk 16, 256 threads, 4x4 micro tile. M,N multiple of 64, K multiple of 16.
__global__ void gemm_tn_kernel(const float* __restrict__ A, const float* __restrict__ B,
                               const float* __restrict__ bias, float* __restrict__ C,
                               int M, int N, int K) {
    __shared__ float As[16][64];
    __shared__ float Bs[16][64];
    int m0 = blockIdx.x * 64, n0 = blockIdx.y * 64;
    int tid = threadIdx.x;
    int tx = tid & 15, ty = tid >> 4;
    int lr = tid >> 2;             // 0..63
    int lc = (tid & 3) * 4;        // 0,4,8,12
    float acc[4][4] = {};
    for (int k0 = 0; k0 < K; k0 += 16) {
        __syncthreads();
        float4 av = *(const float4*)&A[(size_t)(m0 + lr) * K + k0 + lc];
        float4 bv = *(const float4*)&B[(size_t)(n0 + lr) * K + k0 + lc];
        As[lc + 0][lr] = av.x; As[lc + 1][lr] = av.y; As[lc + 2][lr] = av.z; As[lc + 3][lr] = av.w;
        Bs[lc + 0][lr] = bv.x; Bs[lc + 1][lr] = bv.y; Bs[lc + 2][lr] = bv.z; Bs[lc + 3][lr] = bv.w;
        __syncthreads();
        #pragma unroll
        for (int kk = 0; kk < 16; kk++) {
            float4 a = *(const float4*)&As[kk][ty * 4];
            float4 b = *(const float4*)&Bs[kk][tx * 4];
            acc[0][0] = fmaf(a.x, b.x, acc[0][0]); acc[0][1] = fmaf(a.x, b.y, acc[0][1]);
            acc[0][2] = fmaf(a.x, b.z, acc[0][2]); acc[0][3] = fmaf(a.x, b.w, acc[0][3]);
            acc[1][0] = fmaf(a.y, b.x, acc[1][0]); acc[1][1] = fmaf(a.y, b.y, acc[1][1]);
            acc[1][2] = fmaf(a.y, b.z, acc[1][2]); acc[1][3] = fmaf(a.y, b.w, acc[1][3]);
            acc[2][0] = fmaf(a.z, b.x, acc[2][0]); acc[2][1] = fmaf(a.z, b.y, acc[2][1]);
            acc[2][2] = fmaf(a.z, b.z, acc[2][2]); acc[2][3] = fmaf(a.z, b.w, acc[2][3]);
            acc[3][0] = fmaf(a.w, b.x, acc[3][0]); acc[3][1] = fmaf(a.w, b.y, acc[3][1]);
            acc[3][2] = fmaf(a.w, b.z, acc[3][2]); acc[3][3] = fmaf(a.w, b.w, acc[3][3]);
        }
    }
    #pragma unroll
    for (int i = 0; i < 4; i++) {
        #pragma unroll
        for (int j = 0; j < 4; j++) {
            int n = n0 + tx * 4 + j;
            C[(size_t)(m0 + ty * 4 + i) * N + n] = acc[i][j] + bias[n];
        }
    }
}

// ---------------- scan: fused qk GEMM + online candidate selection ----------------
// grid (R/TM, SPLITS), 256 threads. score s = q.k - 0.5*k2 (monotone in logit per row).
__global__ void scan_kernel(const float* __restrict__ keys, const float* __restrict__ qbuf,
                            const float* __restrict__ k2buf, int* __restrict__ cnt,
                            int* __restrict__ cidx) {
    __shared__ float    qsh[DKD * TM];     // qsh[d][t]
    __shared__ float    ksh[16 * TN];      // ksh[dd][key]
    __shared__ float    k2h[TN];           // 0.5*k2
    __shared__ unsigned smax[TM];
    int tid  = threadIdx.x;
    int tok0 = blockIdx.x * TM;
    int keybase = blockIdx.y * (NKEYS / SPLITS);

    for (int i = tid; i < TM * DKD; i += 256) {
        int t = i >> 8, d = i & 255;
        qsh[d * TM + t] = qbuf[(size_t)(tok0 + t) * DKD + d];
    }
    if (tid < TM) smax[tid] = fenc(-1e30f);

    int ty = tid >> 6, tx = tid & 63;
    const int ntiles = (NKEYS / SPLITS) / TN;
    for (int kt = 0; kt < ntiles; kt++) {
        int key0 = keybase + kt * TN;
        __syncthreads();                    // protect k2h reuse
        k2h[tid] = 0.5f * k2buf[key0 + tid];   // blockDim == TN
        float acc[4][4] = {};
        for (int dc = 0; dc < DKD; dc += 16) {
            __syncthreads();
            {
                int kk = tid >> 2, dd = (tid & 3) * 4;
                #pragma unroll
                for (int p = 0; p < 4; p++) {
                    int kr = kk + p * 64;
                    float4 v = *(const float4*)&keys[(size_t)(key0 + kr) * DKD + dc + dd];
                    ksh[(dd + 0) * TN + kr] = v.x;
                    ksh[(dd + 1) * TN + kr] = v.y;
                    ksh[(dd + 2) * TN + kr] = v.z;
                    ksh[(dd + 3) * TN + kr] = v.w;
                }
            }
            __syncthreads();
            #pragma unroll
            for (int dd = 0; dd < 16; dd++) {
                float4 a = *(const float4*)&qsh[(dc + dd) * TM + ty * 4];
                float4 b = *(const float4*)&ksh[dd * TN + tx * 4];
                acc[0][0] = fmaf(a.x, b.x, acc[0][0]); acc[0][1] = fmaf(a.x, b.y, acc[0][1]);
                acc[0][2] = fmaf(a.x, b.z, acc[0][2]); acc[0][3] = fmaf(a.x, b.w, acc[0][3]);
                acc[1][0] = fmaf(a.y, b.x, acc[1][0]); acc[1][1] = fmaf(a.y, b.y, acc[1][1]);
                acc[1][2] = fmaf(a.y, b.z, acc[1][2]); acc[1][3] = fmaf(a.y, b.w, acc[1][3]);
                acc[2][0] = fmaf(a.z, b.x, acc[2][0]); acc[2][1] = fmaf(a.z, b.y, acc[2][1]);
                acc[2][2] = fmaf(a.z, b.z, acc[2][2]); acc[2][3] = fmaf(a.z, b.w, acc[2][3]);
                acc[3][0] = fmaf(a.w, b.x, acc[3][0]); acc[3][1] = fmaf(a.w, b.y, acc[3][1]);
                acc[3][2] = fmaf(a.w, b.z, acc[3][2]); acc[3][3] = fmaf(a.w, b.w, acc[3][3]);
            }
        }
        // epilogue: scores, per-token running max, collect candidates
        float s[4][4];
        float tmax[4];
        #pragma unroll
        for (int i = 0; i < 4; i++) {
            tmax[i] = -1e30f;
            #pragma unroll
            for (int j = 0; j < 4; j++) {
                s[i][j] = acc[i][j] - k2h[tx * 4 + j];
                tmax[i] = fmaxf(tmax[i], s[i][j]);
            }
        }
        #pragma unroll
        for (int i = 0; i < 4; i++) {
            float m = tmax[i];
            #pragma unroll
            for (int o = 16; o; o >>= 1) m = fmaxf(m, __shfl_xor_sync(0xffffffffu, m, o));
            if ((tid & 31) == 0) atomicMax(&smax[ty * 4 + i], fenc(m));
        }
        __syncthreads();
        #pragma unroll
        for (int i = 0; i < 4; i++) {
            float th = fdec(smax[ty * 4 + i]) - DELTA_S;
            int tok = tok0 + ty * 4 + i;
            #pragma unroll
            for (int j = 0; j < 4; j++) {
                if (s[i][j] > th) {
                    int pos = atomicAdd(&cnt[tok], 1);
                    if (pos < CAP) cidx[(size_t)tok * CAP + pos] = key0 + tx * 4 + j;
                }
            }
        }
    }
}

// ---------------- exact rescore + 8-round softmax recursion + gather ----------------
// one block (256 threads) per token
__global__ void recurse_kernel(const float* __restrict__ keys, const float* __restrict__ vals,
                               const float* __restrict__ qbuf, const float* __restrict__ q2buf,
                               const float* __restrict__ k2buf, const int* __restrict__ cnt,
                               const int* __restrict__ cidx, float* __restrict__ nearest) {
    __shared__ float    qrow[DKD];
    __shared__ float    lg_all[CAP];
    __shared__ int      keep_idx[MAXKEEP];
    __shared__ float    keep_lg[MAXKEEP];
    __shared__ float    wmat[KN][MAXKEEP];
    __shared__ unsigned s_maxenc;
    __shared__ int      s_nkeep;

    int tok = blockIdx.x, tid = threadIdx.x;
    int lane = tid & 31, wid = tid >> 5;
    int n = min(cnt[tok], CAP);

    qrow[tid] = qbuf[(size_t)tok * DKD + tid];
    if (tid == 0) { s_maxenc = fenc(-1e30f); s_nkeep = 0; }
    __syncthreads();

    float q2 = q2buf[tok];
    // exact fp32 rescore of candidates (one warp per candidate, round-robin)
    for (int c = wid; c < n; c += 8) {
        int ki = cidx[(size_t)tok * CAP + c];
        const float* kp = keys + (size_t)ki * DKD;
        float p = 0.f;
        #pragma unroll
        for (int e = 0; e < 8; e++) { int d = lane + e * 32; p = fmaf(qrow[d], kp[d], p); }
        #pragma unroll
        for (int o = 16; o; o >>= 1) p += __shfl_xor_sync(0xffffffffu, p, o);
        if (lane == 0) {
            float lg = -(q2 - 2.0f * p + k2buf[ki]) / 0.1f;
            lg_all[c] = lg;
            atomicMax(&s_maxenc, fenc(lg));
        }
    }
    __syncthreads();
    float cut = fdec(s_maxenc) - CUT_LG;
    for (int c = tid; c < n; c += 256) {
        if (lg_all[c] >= cut) {
            int pos = atomicAdd(&s_nkeep, 1);
            if (pos < MAXKEEP) {
                keep_idx[pos] = cidx[(size_t)tok * CAP + c];
                keep_lg[pos]  = lg_all[c];
            }
        }
    }
    __syncthreads();
    int nk = min(s_nkeep, MAXKEEP);
    // sort kept candidates by key index -> deterministic summation order
    if (tid == 0) {
        for (int a = 1; a < nk; a++) {
            int ia = keep_idx[a]; float la = keep_lg[a];
            int b = a - 1;
            while (b >= 0 && keep_idx[b] > ia) {
                keep_idx[b + 1] = keep_idx[b]; keep_lg[b + 1] = keep_lg[b]; b--;
            }
            keep_idx[b + 1] = ia; keep_lg[b + 1] = la;
        }
    }
    __syncthreads();
    // 8-round continuous k-NN recursion on candidates (warp 0)
    if (wid == 0) {
        for (int k = 0; k < KN; k++) {
            float lm = -1e30f;
            for (int c = lane; c < nk; c += 32) lm = fmaxf(lm, keep_lg[c]);
            #pragma unroll
            for (int o = 16; o; o >>= 1) lm = fmaxf(lm, __shfl_xor_sync(0xffffffffu, lm, o));
            float zs = 0.f;
            for (int c = lane; c < nk; c += 32) {
                float p = expf(keep_lg[c] - lm);
                wmat[k][c] = p;
                zs += p;
            }
            #pragma unroll
            for (int o = 16; o; o >>= 1) zs += __shfl_xor_sync(0xffffffffu, zs, o);
            float inv = 1.0f / zs;
            for (int c = lane; c < nk; c += 32) {
                float w = wmat[k][c] * inv;
                wmat[k][c] = w;
                keep_lg[c] += log1pf(-w + 1e-6f);
            }
            __syncwarp();
        }
    }
    __syncthreads();
    // gather: each thread owns one DM feature, vals rows read once
    float a[KN] = {};
    for (int c = 0; c < nk; c++) {
        float v = vals[(size_t)keep_idx[c] * DM + tid];
        #pragma unroll
        for (int k = 0; k < KN; k++) a[k] = fmaf(wmat[k][c], v, a[k]);
    }
    #pragma unroll
    for (int k = 0; k < KN; k++)
        nearest[(size_t)tok * FF + k * DM + tid] = a[k];
}

// ---------------- RMSNorm (in place on d_out) ----------------
__global__ void rmsnorm_kernel(float* __restrict__ out, const float* __restrict__ rms_w) {
    __shared__ float wsum[8];
    __shared__ float s_tot;
    int tok = blockIdx.x, tid = threadIdx.x;
    float* row = out + (size_t)tok * D;
    float v[4];
    float ss = 0.f;
    #pragma unroll
    for (int e = 0; e < 4; e++) { v[e] = row[tid + e * 256]; ss = fmaf(v[e], v[e], ss); }
    #pragma unroll
    for (int o = 16; o; o >>= 1) ss += __shfl_xor_sync(0xffffffffu, ss, o);
    if ((tid & 31) == 0) wsum[tid >> 5] = ss;
    __syncthreads();
    if (tid == 0) {
        float t = 0.f;
        #pragma unroll
        for (int w = 0; w < 8; w++) t += wsum[w];
        s_tot = t;
    }
    __syncthreads();
    float var = s_tot / (float)D;
    float rs = 1.0f / sqrtf(var + 1e-6f);
    #pragma unroll
    for (int e = 0; e < 4; e++) {
        int d = tid + e * 256;
        row[d] = rms_w[d] * (v[e] * rs);
    }
}

// ---------------- host launch ----------------
extern "C" void kernel_launch(void* const* d_in, const int* in_sizes, int n_in,
                              void* d_out, int out_size) {
    const float* x     = (const float*)d_in[0];
    const float* keys  = (const float*)d_in[1];
    const float* vals  = (const float*)d_in[2];
    const float* W_in  = (const float*)d_in[3];
    const float* b_in  = (const float*)d_in[4];
    const float* W_out = (const float*)d_in[5];
    const float* b_out = (const float*)d_in[6];
    const float* rms_w = (const float*)d_in[7];
    float* out = (float*)d_out;
    (void)in_sizes; (void)n_in; (void)out_size;

    float *qp, *q2p, *k2p, *np;
    int *cntp, *cidxp;
    cudaGetSymbolAddress((void**)&qp,    g_q);
    cudaGetSymbolAddress((void**)&q2p,   g_q2);
    cudaGetSymbolAddress((void**)&k2p,   g_k2);
    cudaGetSymbolAddress((void**)&np,    g_nearest);
    cudaGetSymbolAddress((void**)&cntp,  g_cnt);
    cudaGetSymbolAddress((void**)&cidxp, g_cidx);

    // 1. reset candidate counters
    init_cnt_kernel<<<(R + 255) / 256, 256>>>(cntp);
    // 2. k2 = sum(keys^2) per key
    rowsumsq_kernel<<<NKEYS / 8, 256>>>(keys, k2p, DKD);
    // 3. q = x @ W_in^T + b_in
    gemm_tn_kernel<<<dim3(R / 64, DKD / 64), 256>>>(x, W_in, b_in, qp, R, DKD, D);
    // 4. q2 = sum(q^2) per token
    rowsumsq_kernel<<<R / 8, 256>>>(qp, q2p, DKD);
    // 5. fused qk scan + candidate selection
    scan_kernel<<<dim3(R / TM, SPLITS), 256>>>(keys, qp, k2p, cntp, cidxp);
    // 6. exact rescore + 8-round recursion + value gather -> nearest
    recurse_kernel<<<R, 256>>>(keys, vals, qp, q2p, k2p, cntp, cidxp, np);
    // 7. out = nearest @ W_out^T + b_out
    gemm_tn_kernel<<<dim3(R / 64, D / 64), 256>>>(np, W_out, b_out, out, R, D, FF);
    // 8. RMSNorm * rms_w, in place
    rmsnorm_kernel<<<R, 256>>>(out, rms_w);
}

// round 3
// speedup vs baseline: 2.7723x; 2.7723x over previous
#include <cuda_runtime.h>
#include <cuda_bf16.h>
#include <math.h>
#include <stdint.h>

// Problem constants
#define R      4096      // B*T
#define D      1024
#define DKD    256       // DK
#define NKEYS  32768
#define DM     256
#define KN     8         // K_NEIGHBORS
#define FF     (KN*DM)   // 2048
#define CAP    1024
#define MAXKEEP 64
#define CUT_LG  131.0f   // exact-logit prune cut below row max
#define DELTA_S 8.0f     // scan-score threshold (bf16 scan slack)

// tensor scan tiling
#define TOKS   128
#define KEYT   128
#define KSPLIT 8
#define NT_TILES ((NKEYS / KSPLIT) / KEYT)   // 32
#define NCHUNK (NT_TILES * 4)                // 128 chunks of K=64

// ---------------- scratch (static device globals; no allocation) ----------------
__device__ __align__(16) float g_q[R * DKD];
__device__ __align__(16) float g_q2[R];
__device__ __align__(16) float g_k2[NKEYS];
__device__ __align__(16) int   g_cidx[(size_t)R * CAP];
__device__ __align__(16) int   g_cnt[R];
__device__ __align__(16) float g_nearest[(size_t)R * FF];
__device__ __align__(16) __nv_bfloat16 g_keys_bf[(size_t)NKEYS * DKD];
__device__ __align__(16) __nv_bfloat16 g_q_bf[(size_t)R * DKD];

// ---------------- PTX helpers (sm_103 baseline: mma.sync / ldmatrix / cp.async) ----
__device__ __forceinline__ uint32_t smem_u32(const void* p) {
    uint32_t a;
    asm("{ .reg .u64 t; cvta.to.shared.u64 t, %1; cvt.u32.u64 %0, t; }" : "=r"(a) : "l"(p));
    return a;
}
#define CP_ASYNC16(dst, src) \
    asm volatile("cp.async.cg.shared.global [%0], [%1], 16;" \
                 :: "r"((uint32_t)(dst)), "l"(__cvta_generic_to_global(src)) : "memory")
#define CP_COMMIT()    asm volatile("cp.async.commit_group;" ::: "memory")
#define CP_WAIT(n)     asm volatile("cp.async.wait_group %0;" :: "n"(n) : "memory")

#define LDSM_X4(r0, r1, r2, r3, addr) \
    asm volatile("ldmatrix.sync.aligned.m8n8.x4.shared.b16 {%0,%1,%2,%3}, [%4];" \
                 : "=r"(r0), "=r"(r1), "=r"(r2), "=r"(r3) : "r"(addr))

#define MMA16816(d, a, b) \
    asm volatile("mma.sync.aligned.m16n8k16.row.col.f32.bf16.bf16.f32 " \
                 "{%0,%1,%2,%3}, {%4,%5,%6,%7}, {%8,%9}, {%0,%1,%2,%3};" \
                 : "+f"((d)[0]), "+f"((d)[1]), "+f"((d)[2]), "+f"((d)[3]) \
                 : "r"((a)[0]), "r"((a)[1]), "r"((a)[2]), "r"((a)[3]), \
                   "r"((b)[0]), "r"((b)[1]))

// ordered-float encoding for unsigned atomicMax
__device__ __forceinline__ unsigned fenc(float f) {
    unsigned u = __float_as_uint(f);
    return (u & 0x80000000u) ? ~u : (u | 0x80000000u);
}
__device__ __forceinline__ float fdec(unsigned e) {
    return __uint_as_float((e & 0x80000000u) ? (e & 0x7fffffffu) : ~e);
}

// ---------------- init: zero candidate counters ----------------
__global__ void init_cnt_kernel(int* __restrict__ cnt) {
    int i = blockIdx.x * blockDim.x + threadIdx.x;
    if (i < R) cnt[i] = 0;
}

// ---------------- fp32 -> bf16 convert (vectorized) ----------------
__global__ void cvt_bf16_kernel(const float* __restrict__ src, __nv_bfloat16* __restrict__ dst, int n4) {
    int i = blockIdx.x * blockDim.x + threadIdx.x;
    if (i < n4) {
        float4 v = ((const float4*)src)[i];
        __nv_bfloat162* d = (__nv_bfloat162*)dst;
        d[i * 2 + 0] = __floats2bfloat162_rn(v.x, v.y);
        d[i * 2 + 1] = __floats2bfloat162_rn(v.z, v.w);
    }
}

// ---------------- row sum of squares (k2 and q2) ----------------
__global__ void rowsumsq_kernel(const float* __restrict__ src, float* __restrict__ dst, int cols) {
    int row  = blockIdx.x * 8 + (threadIdx.x >> 5);
    int lane = threadIdx.x & 31;
    const float* p = src + (size_t)row * cols;
    float s = 0.f;
    for (int e = lane; e < cols; e += 32) { float v = p[e]; s = fmaf(v, v, s); }
    #pragma unroll
    for (int o = 16; o; o >>= 1) s += __shfl_xor_sync(0xffffffffu, s, o);
    if (lane == 0) dst[row] = s;
}

// ---------------- generic tiled fp32 GEMM: C[m][n] = sum_k A[m][k]*B[n][k] + bias[n] ----
__global__ void gemm_tn_kernel(const float* __restrict__ A, const float* __restrict__ B,
                               const float* __restrict__ bias, float* __restrict__ C,
                               int M, int N, int K) {
    __shared__ float As[16][64];
    __shared__ float Bs[16][64];
    int m0 = blockIdx.x * 64, n0 = blockIdx.y * 64;
    int tid = threadIdx.x;
    int tx = tid & 15, ty = tid >> 4;
    int lr = tid >> 2;
    int lc = (tid & 3) * 4;
    float acc[4][4] = {};
    for (int k0 = 0; k0 < K; k0 += 16) {
        __syncthreads();
        float4 av = *(const float4*)&A[(size_t)(m0 + lr) * K + k0 + lc];
        float4 bv = *(const float4*)&B[(size_t)(n0 + lr) * K + k0 + lc];
        As[lc + 0][lr] = av.x; As[lc + 1][lr] = av.y; As[lc + 2][lr] = av.z; As[lc + 3][lr] = av.w;
        Bs[lc + 0][lr] = bv.x; Bs[lc + 1][lr] = bv.y; Bs[lc + 2][lr] = bv.z; Bs[lc + 3][lr] = bv.w;
        __syncthreads();
        #pragma unroll
        for (int kk = 0; kk < 16; kk++) {
            float4 a = *(const float4*)&As[kk][ty * 4];
            float4 b = *(const float4*)&Bs[kk][tx * 4];
            acc[0][0] = fmaf(a.x, b.x, acc[0][0]); acc[0][1] = fmaf(a.x, b.y, acc[0][1]);
            acc[0][2] = fmaf(a.x, b.z, acc[0][2]); acc[0][3] = fmaf(a.x, b.w, acc[0][3]);
            acc[1][0] = fmaf(a.y, b.x, acc[1][0]); acc[1][1] = fmaf(a.y, b.y, acc[1][1]);
            acc[1][2] = fmaf(a.y, b.z, acc[1][2]); acc[1][3] = fmaf(a.y, b.w, acc[1][3]);
            acc[2][0] = fmaf(a.z, b.x, acc[2][0]); acc[2][1] = fmaf(a.z, b.y, acc[2][1]);
            acc[2][2] = fmaf(a.z, b.z, acc[2][2]); acc[2][3] = fmaf(a.z, b.w, acc[2][3]);
            acc[3][0] = fmaf(a.w, b.x, acc[3][0]); acc[3][1] = fmaf(a.w, b.y, acc[3][1]);
            acc[3][2] = fmaf(a.w, b.z, acc[3][2]); acc[3][3] = fmaf(a.w, b.w, acc[3][3]);
        }
    }
    #pragma unroll
    for (int i = 0; i < 4; i++) {
        #pragma unroll
        for (int j = 0; j < 4; j++) {
            int n = n0 + tx * 4 + j;
            C[(size_t)(m0 + ty * 4 + i) * N + n] = acc[i][j] + bias[n];
        }
    }
}

// ---------------- tensor scan: bf16 mma.sync + threshold selection ----------------
// Dynamic SMEM layout (bytes):
#define SO_A    0                    // q tile: 128 rows x 512B (swizzled)          = 65536
#define SO_B0   65536                // key chunk buf0: 128 rows x 128B (swizzled)  = 16384
#define SO_B1   81920                // key chunk buf1                              = 16384
#define SO_K2   98304                // 128 floats
#define SO_SMAX 98816                // 128 unsigned
#define SMEM_SCAN 99328

__global__ void __launch_bounds__(256, 1) scan_mma_kernel(
    const __nv_bfloat16* __restrict__ qb, const __nv_bfloat16* __restrict__ kb,
    const float* __restrict__ k2buf, int* __restrict__ cnt, int* __restrict__ cidx)
{
    extern __shared__ char smem[];
    uint32_t sb = smem_u32(smem);
    float*    k2h  = (float*)(smem + SO_K2);
    unsigned* smax = (unsigned*)(smem + SO_SMAX);

    int tid  = threadIdx.x;
    int lane = tid & 31, wid = tid >> 5;
    int tok0 = blockIdx.x * TOKS;
    int keybase = blockIdx.y * (NKEYS / KSPLIT);
    int mbase = (wid >> 1) * 32;
    int nhalf = (wid & 1) * 64;

    if (tid < TOKS) smax[tid] = fenc(-1e30f);

    // ---- prologue: load A (q tile) + B chunk 0, one commit group ----
    {
        const char* abase = (const char*)(qb + (size_t)tok0 * DKD);
        for (int i = tid; i < 4096; i += 256) {        // 128 rows x 32 chunks of 16B
            int row = i >> 5, c16 = i & 31;
            int colb = c16 * 16;
            uint32_t sw = (uint32_t)(colb ^ ((row & 7) << 4));
            CP_ASYNC16(sb + SO_A + row * 512 + sw, abase + row * 512 + colb);
        }
        const char* bbase = (const char*)(kb + (size_t)keybase * DKD);
        for (int i = tid; i < 1024; i += 256) {        // 128 rows x 8 chunks of 16B
            int row = i >> 3, c16 = i & 7;
            int colb = c16 * 16;
            uint32_t sw = (uint32_t)(colb ^ ((row & 7) << 4));
            CP_ASYNC16(sb + SO_B0 + row * 128 + sw, bbase + row * 512 + colb);
        }
        CP_COMMIT();
    }

    float acc[2][8][4];

    for (int j = 0; j < NCHUNK; j++) {
        int t = j >> 2, c = j & 3;
        int key0 = keybase + t * KEYT;

        if (c == 0) {
            #pragma unroll
            for (int mt = 0; mt < 2; mt++)
                #pragma unroll
                for (int nt = 0; nt < 8; nt++)
                    #pragma unroll
                    for (int e = 0; e < 4; e++) acc[mt][nt][e] = 0.f;
        }

        // prefetch next chunk into the other buffer
        if (j + 1 < NCHUNK) {
            int tn = (j + 1) >> 2, cn = (j + 1) & 3;
            int keyn = keybase + tn * KEYT;
            uint32_t nb = ((j + 1) & 1) ? SO_B1 : SO_B0;
            const char* bbase = (const char*)(kb + (size_t)keyn * DKD) + cn * 128;
            for (int i = tid; i < 1024; i += 256) {
                int row = i >> 3, c16 = i & 7;
                int colb = c16 * 16;
                uint32_t sw = (uint32_t)(colb ^ ((row & 7) << 4));
                CP_ASYNC16(sb + nb + row * 128 + sw, bbase + row * 512 + colb);
            }
            CP_COMMIT();
            CP_WAIT(1);
        } else {
            CP_WAIT(0);
        }
        __syncthreads();

        if (c == 0 && tid < KEYT) k2h[tid] = 0.5f * k2buf[key0 + tid];

        // ---- compute chunk c (K = 64, four k16 steps) ----
        uint32_t bbuf = sb + ((j & 1) ? SO_B1 : SO_B0);
        #pragma unroll
        for (int kk = 0; kk < 4; kk++) {
            uint32_t a[2][4];
            #pragma unroll
            for (int mt = 0; mt < 2; mt++) {
                int row = mbase + mt * 16 + (lane & 15);
                int colb = c * 128 + kk * 32 + ((lane >> 4) << 4);
                uint32_t ad = sb + SO_A + row * 512 + (uint32_t)(colb ^ ((row & 7) << 4));
                LDSM_X4(a[mt][0], a[mt][1], a[mt][2], a[mt][3], ad);
            }
            uint32_t b[8][2];
            #pragma unroll
            for (int bt = 0; bt < 4; bt++) {
                int n = nhalf + bt * 16 + (lane & 7) + ((lane >> 4) << 3);
                int colb = kk * 32 + ((lane & 8) << 1);
                uint32_t bd = bbuf + n * 128 + (uint32_t)(colb ^ ((n & 7) << 4));
                LDSM_X4(b[bt * 2][0], b[bt * 2][1], b[bt * 2 + 1][0], b[bt * 2 + 1][1], bd);
            }
            #pragma unroll
            for (int mt = 0; mt < 2; mt++)
                #pragma unroll
                for (int nt = 0; nt < 8; nt++)
                    MMA16816(acc[mt][nt], a[mt], b[nt]);
        }
        __syncthreads();

        // ---- tile epilogue: scores, running max, selection ----
        if (c == 3) {
            // scores in place: s = acc - 0.5*k2
            float rm[2][2];
            #pragma unroll
            for (int mt = 0; mt < 2; mt++) { rm[mt][0] = -1e30f; rm[mt][1] = -1e30f; }
            #pragma unroll
            for (int mt = 0; mt < 2; mt++) {
                #pragma unroll
                for (int nt = 0; nt < 8; nt++) {
                    float kc0 = k2h[nhalf + nt * 8 + 2 * (lane & 3)];
                    float kc1 = k2h[nhalf + nt * 8 + 2 * (lane & 3) + 1];
                    acc[mt][nt][0] -= kc0; acc[mt][nt][1] -= kc1;
                    acc[mt][nt][2] -= kc0; acc[mt][nt][3] -= kc1;
                    rm[mt][0] = fmaxf(rm[mt][0], fmaxf(acc[mt][nt][0], acc[mt][nt][1]));
                    rm[mt][1] = fmaxf(rm[mt][1], fmaxf(acc[mt][nt][2], acc[mt][nt][3]));
                }
            }
            // quad reduce (lanes with same lane>>2 share a token row)
            #pragma unroll
            for (int mt = 0; mt < 2; mt++) {
                #pragma unroll
                for (int e = 0; e < 2; e++) {
                    float v = rm[mt][e];
                    v = fmaxf(v, __shfl_xor_sync(0xffffffffu, v, 1));
                    v = fmaxf(v, __shfl_xor_sync(0xffffffffu, v, 2));
                    rm[mt][e] = v;
                }
            }
            if ((lane & 3) == 0) {
                #pragma unroll
                for (int mt = 0; mt < 2; mt++) {
                    int r = mbase + mt * 16 + (lane >> 2);
                    atomicMax(&smax[r], fenc(rm[mt][0]));
                    atomicMax(&smax[r + 8], fenc(rm[mt][1]));
                }
            }
            __syncthreads();
            #pragma unroll
            for (int mt = 0; mt < 2; mt++) {
                int r0 = mbase + mt * 16 + (lane >> 2);
                float th0 = fdec(smax[r0]) - DELTA_S;
                float th1 = fdec(smax[r0 + 8]) - DELTA_S;
                int tokA = tok0 + r0, tokB = tokA + 8;
                #pragma unroll
                for (int nt = 0; nt < 8; nt++) {
                    int keyc = key0 + nhalf + nt * 8 + 2 * (lane & 3);
                    if (acc[mt][nt][0] > th0) {
                        int pos = atomicAdd(&cnt[tokA], 1);
                        if (pos < CAP) cidx[(size_t)tokA * CAP + pos] = keyc;
                    }
                    if (acc[mt][nt][1] > th0) {
                        int pos = atomicAdd(&cnt[tokA], 1);
                        if (pos < CAP) cidx[(size_t)tokA * CAP + pos] = keyc + 1;
                    }
                    if (acc[mt][nt][2] > th1) {
                        int pos = atomicAdd(&cnt[tokB], 1);
                        if (pos < CAP) cidx[(size_t)tokB * CAP + pos] = keyc;
                    }
                    if (acc[mt][nt][3] > th1) {
                        int pos = atomicAdd(&cnt[tokB], 1);
                        if (pos < CAP) cidx[(size_t)tokB * CAP + pos] = keyc + 1;
                    }
                }
            }
            __syncthreads();
        }
    }
}

// ---------------- exact rescore + 8-round softmax recursion + gather ----------------
__global__ void recurse_kernel(const float* __restrict__ keys, const float* __restrict__ vals,
                               const float* __restrict__ qbuf, const float* __restrict__ q2buf,
                               const float* __restrict__ k2buf, const int* __restrict__ cnt,
                               const int* __restrict__ cidx, float* __restrict__ nearest) {
    __shared__ float    qrow[DKD];
    __shared__ float    lg_all[CAP];
    __shared__ int      keep_idx[MAXKEEP];
    __shared__ float    keep_lg[MAXKEEP];
    __shared__ float    wmat[KN][MAXKEEP];
    __shared__ unsigned s_maxenc;
    __shared__ int      s_nkeep;

    int tok = blockIdx.x, tid = threadIdx.x;
    int lane = tid & 31, wid = tid >> 5;
    int n = min(cnt[tok], CAP);

    qrow[tid] = qbuf[(size_t)tok * DKD + tid];
    if (tid == 0) { s_maxenc = fenc(-1e30f); s_nkeep = 0; }
    __syncthreads();

    float q2 = q2buf[tok];
    for (int c = wid; c < n; c += 8) {
        int ki = cidx[(size_t)tok * CAP + c];
        const float* kp = keys + (size_t)ki * DKD;
        float p = 0.f;
        #pragma unroll
        for (int e = 0; e < 8; e++) { int d = lane + e * 32; p = fmaf(qrow[d], kp[d], p); }
        #pragma unroll
        for (int o = 16; o; o >>= 1) p += __shfl_xor_sync(0xffffffffu, p, o);
        if (lane == 0) {
            float lg = -(q2 - 2.0f * p + k2buf[ki]) / 0.1f;
            lg_all[c] = lg;
            atomicMax(&s_maxenc, fenc(lg));
        }
    }
    __syncthreads();
    float cut = fdec(s_maxenc) - CUT_LG;
    for (int c = tid; c < n; c += 256) {
        if (lg_all[c] >= cut) {
            int pos = atomicAdd(&s_nkeep, 1);
            if (pos < MAXKEEP) {
                keep_idx[pos] = cidx[(size_t)tok * CAP + c];
                keep_lg[pos]  = lg_all[c];
            }
        }
    }
    __syncthreads();
    int nk = min(s_nkeep, MAXKEEP);
    if (tid == 0) {
        for (int a = 1; a < nk; a++) {
            int ia = keep_idx[a]; float la = keep_lg[a];
            int b = a - 1;
            while (b >= 0 && keep_idx[b] > ia) {
                keep_idx[b + 1] = keep_idx[b]; keep_lg[b + 1] = keep_lg[b]; b--;
            }
            keep_idx[b + 1] = ia; keep_lg[b + 1] = la;
        }
    }
    __syncthreads();
    if (wid == 0) {
        for (int k = 0; k < KN; k++) {
            float lm = -1e30f;
            for (int c = lane; c < nk; c += 32) lm = fmaxf(lm, keep_lg[c]);
            #pragma unroll
            for (int o = 16; o; o >>= 1) lm = fmaxf(lm, __shfl_xor_sync(0xffffffffu, lm, o));
            float zs = 0.f;
            for (int c = lane; c < nk; c += 32) {
                float p = expf(keep_lg[c] - lm);
                wmat[k][c] = p;
                zs += p;
            }
            #pragma unroll
            for (int o = 16; o; o >>= 1) zs += __shfl_xor_sync(0xffffffffu, zs, o);
            float inv = 1.0f / zs;
            for (int c = lane; c < nk; c += 32) {
                float w = wmat[k][c] * inv;
                wmat[k][c] = w;
                keep_lg[c] += log1pf(-w + 1e-6f);
            }
            __syncwarp();
        }
    }
    __syncthreads();
    float a[KN] = {};
    for (int c = 0; c < nk; c++) {
        float v = vals[(size_t)keep_idx[c] * DM + tid];
        #pragma unroll
        for (int k = 0; k < KN; k++) a[k] = fmaf(wmat[k][c], v, a[k]);
    }
    #pragma unroll
    for (int k = 0; k < KN; k++)
        nearest[(size_t)tok * FF + k * DM + tid] = a[k];
}

// ---------------- RMSNorm (in place on d_out) ----------------
__global__ void rmsnorm_kernel(float* __restrict__ out, const float* __restrict__ rms_w) {
    __shared__ float wsum[8];
    __shared__ float s_tot;
    int tok = blockIdx.x, tid = threadIdx.x;
    float* row = out + (size_t)tok * D;
    float v[4];
    float ss = 0.f;
    #pragma unroll
    for (int e = 0; e < 4; e++) { v[e] = row[tid + e * 256]; ss = fmaf(v[e], v[e], ss); }
    #pragma unroll
    for (int o = 16; o; o >>= 1) ss += __shfl_xor_sync(0xffffffffu, ss, o);
    if ((tid & 31) == 0) wsum[tid >> 5] = ss;
    __syncthreads();
    if (tid == 0) {
        float t = 0.f;
        #pragma unroll
        for (int w = 0; w < 8; w++) t += wsum[w];
        s_tot = t;
    }
    __syncthreads();
    float var = s_tot / (float)D;
    float rs = 1.0f / sqrtf(var + 1e-6f);
    #pragma unroll
    for (int e = 0; e < 4; e++) {
        int d = tid + e * 256;
        row[d] = rms_w[d] * (v[e] * rs);
    }
}

// ---------------- host launch ----------------
extern "C" void kernel_launch(void* const* d_in, const int* in_sizes, int n_in,
                              void* d_out, int out_size) {
    const float* x     = (const float*)d_in[0];
    const float* keys  = (const float*)d_in[1];
    const float* vals  = (const float*)d_in[2];
    const float* W_in  = (const float*)d_in[3];
    const float* b_in  = (const float*)d_in[4];
    const float* W_out = (const float*)d_in[5];
    const float* b_out = (const float*)d_in[6];
    const float* rms_w = (const float*)d_in[7];
    float* out = (float*)d_out;
    (void)in_sizes; (void)n_in; (void)out_size;

    float *qp, *q2p, *k2p, *np;
    int *cntp, *cidxp;
    __nv_bfloat16 *kbp, *qbp;
    cudaGetSymbolAddress((void**)&qp,    g_q);
    cudaGetSymbolAddress((void**)&q2p,   g_q2);
    cudaGetSymbolAddress((void**)&k2p,   g_k2);
    cudaGetSymbolAddress((void**)&np,    g_nearest);
    cudaGetSymbolAddress((void**)&cntp,  g_cnt);
    cudaGetSymbolAddress((void**)&cidxp, g_cidx);
    cudaGetSymbolAddress((void**)&kbp,   g_keys_bf);
    cudaGetSymbolAddress((void**)&qbp,   g_q_bf);

    static int smem_set = 0;
    if (!smem_set) {
        cudaFuncSetAttribute(scan_mma_kernel, cudaFuncAttributeMaxDynamicSharedMemorySize, SMEM_SCAN);
        smem_set = 1;
    }

    // 1. reset candidate counters
    init_cnt_kernel<<<(R + 255) / 256, 256>>>(cntp);
    // 2. k2 = sum(keys^2); keys -> bf16
    rowsumsq_kernel<<<NKEYS / 8, 256>>>(keys, k2p, DKD);
    cvt_bf16_kernel<<<(NKEYS * DKD / 4 + 255) / 256, 256>>>(keys, kbp, NKEYS * DKD / 4);
    // 3. q = x @ W_in^T + b_in
    gemm_tn_kernel<<<dim3(R / 64, DKD / 64), 256>>>(x, W_in, b_in, qp, R, DKD, D);
    // 4. q2 = sum(q^2); q -> bf16
    rowsumsq_kernel<<<R / 8, 256>>>(qp, q2p, DKD);
    cvt_bf16_kernel<<<(R * DKD / 4 + 255) / 256, 256>>>(qp, qbp, R * DKD / 4);
    // 5. tensor-core qk scan + candidate selection (mma.sync bf16)
    scan_mma_kernel<<<dim3(R / TOKS, KSPLIT), 256, SMEM_SCAN>>>(qbp, kbp, k2p, cntp, cidxp);
    // 6. exact rescore + 8-round recursion + value gather -> nearest
    recurse_kernel<<<R, 256>>>(keys, vals, qp, q2p, k2p, cntp, cidxp, np);
    // 7. out = nearest @ W_out^T + b_out
    gemm_tn_kernel<<<dim3(R / 64, D / 64), 256>>>(np, W_out, b_out, out, R, D, FF);
    // 8. RMSNorm * rms_w, in place
    rmsnorm_kernel<<<R, 256>>>(out, rms_w);
}

// round 4
// speedup vs baseline: 3.9137x; 1.4117x over previous
#include <cuda_runtime.h>
#include <cuda_bf16.h>
#include <math.h>
#include <stdint.h>

// Problem constants
#define R      4096      // B*T
#define D      1024
#define DKD    256       // DK
#define NKEYS  32768
#define DM     256
#define KN     8         // K_NEIGHBORS
#define FF     (KN*DM)   // 2048
#define CAP    1024
#define MAXKEEP 64
#define CUT_LG  131.0f
#define DELTA_S 8.0f

// tensor scan tiling
#define TOKS   128
#define KEYT   128
#define KSPLIT 8
#define NT_TILES ((NKEYS / KSPLIT) / KEYT)   // 32
#define NCHUNK (NT_TILES * 4)                // 128 chunks of K=64

// ---------------- scratch (static device globals; no allocation) ----------------
__device__ __align__(16) float g_q[R * DKD];
__device__ __align__(16) float g_q2[R];
__device__ __align__(16) float g_k2[NKEYS];
__device__ __align__(16) int   g_cidx[(size_t)R * CAP];
__device__ __align__(16) int   g_cnt[R];
__device__ __align__(16) __nv_bfloat16 g_keys_bf[(size_t)NKEYS * DKD];
__device__ __align__(16) __nv_bfloat16 g_q_bf[(size_t)R * DKD];
// split-bf16 operands for the W_out GEMM
__device__ __align__(16) __nv_bfloat16 g_ah[(size_t)R * FF];
__device__ __align__(16) __nv_bfloat16 g_al[(size_t)R * FF];
__device__ __align__(16) __nv_bfloat16 g_wh[(size_t)D * FF];
__device__ __align__(16) __nv_bfloat16 g_wl[(size_t)D * FF];

// ---------------- PTX helpers (sm_103 baseline: mma.sync / ldmatrix / cp.async) ----
__device__ __forceinline__ uint32_t smem_u32(const void* p) {
    uint32_t a;
    asm("{ .reg .u64 t; cvta.to.shared.u64 t, %1; cvt.u32.u64 %0, t; }" : "=r"(a) : "l"(p));
    return a;
}
#define CP_ASYNC16(dst, src) \
    asm volatile("cp.async.cg.shared.global [%0], [%1], 16;" \
                 :: "r"((uint32_t)(dst)), "l"(__cvta_generic_to_global(src)) : "memory")
#define CP_COMMIT()    asm volatile("cp.async.commit_group;" ::: "memory")
#define CP_WAIT(n)     asm volatile("cp.async.wait_group %0;" :: "n"(n) : "memory")

#define LDSM_X4(r0, r1, r2, r3, addr) \
    asm volatile("ldmatrix.sync.aligned.m8n8.x4.shared.b16 {%0,%1,%2,%3}, [%4];" \
                 : "=r"(r0), "=r"(r1), "=r"(r2), "=r"(r3) : "r"(addr))

#define MMA16816(d, a, b) \
    asm volatile("mma.sync.aligned.m16n8k16.row.col.f32.bf16.bf16.f32 " \
                 "{%0,%1,%2,%3}, {%4,%5,%6,%7}, {%8,%9}, {%0,%1,%2,%3};" \
                 : "+f"((d)[0]), "+f"((d)[1]), "+f"((d)[2]), "+f"((d)[3]) \
                 : "r"((a)[0]), "r"((a)[1]), "r"((a)[2]), "r"((a)[3]), \
                   "r"((b)[0]), "r"((b)[1]))

// ordered-float encoding for unsigned atomicMax
__device__ __forceinline__ unsigned fenc(float f) {
    unsigned u = __float_as_uint(f);
    return (u & 0x80000000u) ? ~u : (u | 0x80000000u);
}
__device__ __forceinline__ float fdec(unsigned e) {
    return __uint_as_float((e & 0x80000000u) ? (e & 0x7fffffffu) : ~e);
}

// ---------------- init: zero candidate counters ----------------
__global__ void init_cnt_kernel(int* __restrict__ cnt) {
    int i = blockIdx.x * blockDim.x + threadIdx.x;
    if (i < R) cnt[i] = 0;
}

// ---------------- fp32 -> bf16 convert (vectorized) ----------------
__global__ void cvt_bf16_kernel(const float* __restrict__ src, __nv_bfloat16* __restrict__ dst, int n4) {
    int i = blockIdx.x * blockDim.x + threadIdx.x;
    if (i < n4) {
        float4 v = ((const float4*)src)[i];
        __nv_bfloat162* d = (__nv_bfloat162*)dst;
        d[i * 2 + 0] = __floats2bfloat162_rn(v.x, v.y);
        d[i * 2 + 1] = __floats2bfloat162_rn(v.z, v.w);
    }
}

// ---------------- fp32 -> split bf16 hi/lo ----------------
__global__ void cvt_split_kernel(const float* __restrict__ src,
                                 __nv_bfloat16* __restrict__ hi, __nv_bfloat16* __restrict__ lo,
                                 int n4) {
    int i = blockIdx.x * blockDim.x + threadIdx.x;
    if (i < n4) {
        float4 v = ((const float4*)src)[i];
        float h0 = __bfloat162float(__float2bfloat16_rn(v.x));
        float h1 = __bfloat162float(__float2bfloat16_rn(v.y));
        float h2 = __bfloat162float(__float2bfloat16_rn(v.z));
        float h3 = __bfloat162float(__float2bfloat16_rn(v.w));
        __nv_bfloat162* dh = (__nv_bfloat162*)hi;
        __nv_bfloat162* dl = (__nv_bfloat162*)lo;
        dh[i * 2 + 0] = __floats2bfloat162_rn(h0, h1);
        dh[i * 2 + 1] = __floats2bfloat162_rn(h2, h3);
        dl[i * 2 + 0] = __floats2bfloat162_rn(v.x - h0, v.y - h1);
        dl[i * 2 + 1] = __floats2bfloat162_rn(v.z - h2, v.w - h3);
    }
}

// ---------------- row sum of squares (k2 and q2) ----------------
__global__ void rowsumsq_kernel(const float* __restrict__ src, float* __restrict__ dst, int cols) {
    int row  = blockIdx.x * 8 + (threadIdx.x >> 5);
    int lane = threadIdx.x & 31;
    const float* p = src + (size_t)row * cols;
    float s = 0.f;
    for (int e = lane; e < cols; e += 32) { float v = p[e]; s = fmaf(v, v, s); }
    #pragma unroll
    for (int o = 16; o; o >>= 1) s += __shfl_xor_sync(0xffffffffu, s, o);
    if (lane == 0) dst[row] = s;
}

// ---------------- fp32 TN GEMM (q projection only): C = A@B^T + bias ----------------
__global__ void gemm_tn_kernel(const float* __restrict__ A, const float* __restrict__ B,
                               const float* __restrict__ bias, float* __restrict__ C,
                               int M, int N, int K) {
    __shared__ float As[16][64];
    __shared__ float Bs[16][64];
    int m0 = blockIdx.x * 64, n0 = blockIdx.y * 64;
    int tid = threadIdx.x;
    int tx = tid & 15, ty = tid >> 4;
    int lr = tid >> 2;
    int lc = (tid & 3) * 4;
    float acc[4][4] = {};
    for (int k0 = 0; k0 < K; k0 += 16) {
        __syncthreads();
        float4 av = *(const float4*)&A[(size_t)(m0 + lr) * K + k0 + lc];
        float4 bv = *(const float4*)&B[(size_t)(n0 + lr) * K + k0 + lc];
        As[lc + 0][lr] = av.x; As[lc + 1][lr] = av.y; As[lc + 2][lr] = av.z; As[lc + 3][lr] = av.w;
        Bs[lc + 0][lr] = bv.x; Bs[lc + 1][lr] = bv.y; Bs[lc + 2][lr] = bv.z; Bs[lc + 3][lr] = bv.w;
        __syncthreads();
        #pragma unroll
        for (int kk = 0; kk < 16; kk++) {
            float4 a = *(const float4*)&As[kk][ty * 4];
            float4 b = *(const float4*)&Bs[kk][tx * 4];
            acc[0][0] = fmaf(a.x, b.x, acc[0][0]); acc[0][1] = fmaf(a.x, b.y, acc[0][1]);
            acc[0][2] = fmaf(a.x, b.z, acc[0][2]); acc[0][3] = fmaf(a.x, b.w, acc[0][3]);
            acc[1][0] = fmaf(a.y, b.x, acc[1][0]); acc[1][1] = fmaf(a.y, b.y, acc[1][1]);
            acc[1][2] = fmaf(a.y, b.z, acc[1][2]); acc[1][3] = fmaf(a.y, b.w, acc[1][3]);
            acc[2][0] = fmaf(a.z, b.x, acc[2][0]); acc[2][1] = fmaf(a.z, b.y, acc[2][1]);
            acc[2][2] = fmaf(a.z, b.z, acc[2][2]); acc[2][3] = fmaf(a.z, b.w, acc[2][3]);
            acc[3][0] = fmaf(a.w, b.x, acc[3][0]); acc[3][1] = fmaf(a.w, b.y, acc[3][1]);
            acc[3][2] = fmaf(a.w, b.z, acc[3][2]); acc[3][3] = fmaf(a.w, b.w, acc[3][3]);
        }
    }
    #pragma unroll
    for (int i = 0; i < 4; i++) {
        #pragma unroll
        for (int j = 0; j < 4; j++) {
            int n = n0 + tx * 4 + j;
            C[(size_t)(m0 + ty * 4 + i) * N + n] = acc[i][j] + bias[n];
        }
    }
}

// ---------------- tensor scan: bf16 mma.sync + threshold selection ----------------
#define SO_A    0
#define SO_B0   65536
#define SO_B1   81920
#define SO_K2   98304
#define SO_SMAX 98816
#define SMEM_SCAN 99328

__global__ void __launch_bounds__(256, 1) scan_mma_kernel(
    const __nv_bfloat16* __restrict__ qb, const __nv_bfloat16* __restrict__ kb,
    const float* __restrict__ k2buf, int* __restrict__ cnt, int* __restrict__ cidx)
{
    extern __shared__ char smem[];
    uint32_t sb = smem_u32(smem);
    float*    k2h  = (float*)(smem + SO_K2);
    unsigned* smax = (unsigned*)(smem + SO_SMAX);

    int tid  = threadIdx.x;
    int lane = tid & 31, wid = tid >> 5;
    int tok0 = blockIdx.x * TOKS;
    int keybase = blockIdx.y * (NKEYS / KSPLIT);
    int mbase = (wid >> 1) * 32;
    int nhalf = (wid & 1) * 64;

    if (tid < TOKS) smax[tid] = fenc(-1e30f);

    {
        const char* abase = (const char*)(qb + (size_t)tok0 * DKD);
        for (int i = tid; i < 4096; i += 256) {
            int row = i >> 5, c16 = i & 31;
            int colb = c16 * 16;
            uint32_t sw = (uint32_t)(colb ^ ((row & 7) << 4));
            CP_ASYNC16(sb + SO_A + row * 512 + sw, abase + row * 512 + colb);
        }
        const char* bbase = (const char*)(kb + (size_t)keybase * DKD);
        for (int i = tid; i < 1024; i += 256) {
            int row = i >> 3, c16 = i & 7;
            int colb = c16 * 16;
            uint32_t sw = (uint32_t)(colb ^ ((row & 7) << 4));
            CP_ASYNC16(sb + SO_B0 + row * 128 + sw, bbase + row * 512 + colb);
        }
        CP_COMMIT();
    }

    float acc[2][8][4];

    for (int j = 0; j < NCHUNK; j++) {
        int t = j >> 2, c = j & 3;
        int key0 = keybase + t * KEYT;

        if (c == 0) {
            #pragma unroll
            for (int mt = 0; mt < 2; mt++)
                #pragma unroll
                for (int nt = 0; nt < 8; nt++)
                    #pragma unroll
                    for (int e = 0; e < 4; e++) acc[mt][nt][e] = 0.f;
        }

        if (j + 1 < NCHUNK) {
            int tn = (j + 1) >> 2, cn = (j + 1) & 3;
            int keyn = keybase + tn * KEYT;
            uint32_t nb = ((j + 1) & 1) ? SO_B1 : SO_B0;
            const char* bbase = (const char*)(kb + (size_t)keyn * DKD) + cn * 128;
            for (int i = tid; i < 1024; i += 256) {
                int row = i >> 3, c16 = i & 7;
                int colb = c16 * 16;
                uint32_t sw = (uint32_t)(colb ^ ((row & 7) << 4));
                CP_ASYNC16(sb + nb + row * 128 + sw, bbase + row * 512 + colb);
            }
            CP_COMMIT();
            CP_WAIT(1);
        } else {
            CP_WAIT(0);
        }
        __syncthreads();

        if (c == 0 && tid < KEYT) k2h[tid] = 0.5f * k2buf[key0 + tid];

        uint32_t bbuf = sb + ((j & 1) ? SO_B1 : SO_B0);
        #pragma unroll
        for (int kk = 0; kk < 4; kk++) {
            uint32_t a[2][4];
            #pragma unroll
            for (int mt = 0; mt < 2; mt++) {
                int row = mbase + mt * 16 + (lane & 15);
                int colb = c * 128 + kk * 32 + ((lane >> 4) << 4);
                uint32_t ad = sb + SO_A + row * 512 + (uint32_t)(colb ^ ((row & 7) << 4));
                LDSM_X4(a[mt][0], a[mt][1], a[mt][2], a[mt][3], ad);
            }
            uint32_t b[8][2];
            #pragma unroll
            for (int bt = 0; bt < 4; bt++) {
                int n = nhalf + bt * 16 + (lane & 7) + ((lane >> 4) << 3);
                int colb = kk * 32 + ((lane & 8) << 1);
                uint32_t bd = bbuf + n * 128 + (uint32_t)(colb ^ ((n & 7) << 4));
                LDSM_X4(b[bt * 2][0], b[bt * 2][1], b[bt * 2 + 1][0], b[bt * 2 + 1][1], bd);
            }
            #pragma unroll
            for (int mt = 0; mt < 2; mt++)
                #pragma unroll
                for (int nt = 0; nt < 8; nt++)
                    MMA16816(acc[mt][nt], a[mt], b[nt]);
        }
        __syncthreads();

        if (c == 3) {
            float rm[2][2];
            #pragma unroll
            for (int mt = 0; mt < 2; mt++) { rm[mt][0] = -1e30f; rm[mt][1] = -1e30f; }
            #pragma unroll
            for (int mt = 0; mt < 2; mt++) {
                #pragma unroll
                for (int nt = 0; nt < 8; nt++) {
                    float kc0 = k2h[nhalf + nt * 8 + 2 * (lane & 3)];
                    float kc1 = k2h[nhalf + nt * 8 + 2 * (lane & 3) + 1];
                    acc[mt][nt][0] -= kc0; acc[mt][nt][1] -= kc1;
                    acc[mt][nt][2] -= kc0; acc[mt][nt][3] -= kc1;
                    rm[mt][0] = fmaxf(rm[mt][0], fmaxf(acc[mt][nt][0], acc[mt][nt][1]));
                    rm[mt][1] = fmaxf(rm[mt][1], fmaxf(acc[mt][nt][2], acc[mt][nt][3]));
                }
            }
            #pragma unroll
            for (int mt = 0; mt < 2; mt++) {
                #pragma unroll
                for (int e = 0; e < 2; e++) {
                    float v = rm[mt][e];
                    v = fmaxf(v, __shfl_xor_sync(0xffffffffu, v, 1));
                    v = fmaxf(v, __shfl_xor_sync(0xffffffffu, v, 2));
                    rm[mt][e] = v;
                }
            }
            if ((lane & 3) == 0) {
                #pragma unroll
                for (int mt = 0; mt < 2; mt++) {
                    int r = mbase + mt * 16 + (lane >> 2);
                    atomicMax(&smax[r], fenc(rm[mt][0]));
                    atomicMax(&smax[r + 8], fenc(rm[mt][1]));
                }
            }
            __syncthreads();
            #pragma unroll
            for (int mt = 0; mt < 2; mt++) {
                int r0 = mbase + mt * 16 + (lane >> 2);
                float th0 = fdec(smax[r0]) - DELTA_S;
                float th1 = fdec(smax[r0 + 8]) - DELTA_S;
                int tokA = tok0 + r0, tokB = tokA + 8;
                #pragma unroll
                for (int nt = 0; nt < 8; nt++) {
                    int keyc = key0 + nhalf + nt * 8 + 2 * (lane & 3);
                    if (acc[mt][nt][0] > th0) {
                        int pos = atomicAdd(&cnt[tokA], 1);
                        if (pos < CAP) cidx[(size_t)tokA * CAP + pos] = keyc;
                    }
                    if (acc[mt][nt][1] > th0) {
                        int pos = atomicAdd(&cnt[tokA], 1);
                        if (pos < CAP) cidx[(size_t)tokA * CAP + pos] = keyc + 1;
                    }
                    if (acc[mt][nt][2] > th1) {
                        int pos = atomicAdd(&cnt[tokB], 1);
                        if (pos < CAP) cidx[(size_t)tokB * CAP + pos] = keyc;
                    }
                    if (acc[mt][nt][3] > th1) {
                        int pos = atomicAdd(&cnt[tokB], 1);
                        if (pos < CAP) cidx[(size_t)tokB * CAP + pos] = keyc + 1;
                    }
                }
            }
            __syncthreads();
        }
    }
}

// ---------------- exact rescore + 8-round recursion + gather (emits split bf16) ----
__global__ void recurse_kernel(const float* __restrict__ keys, const float* __restrict__ vals,
                               const float* __restrict__ qbuf, const float* __restrict__ q2buf,
                               const float* __restrict__ k2buf, const int* __restrict__ cnt,
                               const int* __restrict__ cidx,
                               __nv_bfloat16* __restrict__ ah, __nv_bfloat16* __restrict__ al) {
    __shared__ float    qrow[DKD];
    __shared__ float    lg_all[CAP];
    __shared__ int      keep_idx[MAXKEEP];
    __shared__ float    keep_lg[MAXKEEP];
    __shared__ float    wmat[KN][MAXKEEP];
    __shared__ unsigned s_maxenc;
    __shared__ int      s_nkeep;

    int tok = blockIdx.x, tid = threadIdx.x;
    int lane = tid & 31, wid = tid >> 5;
    int n = min(cnt[tok], CAP);

    qrow[tid] = qbuf[(size_t)tok * DKD + tid];
    if (tid == 0) { s_maxenc = fenc(-1e30f); s_nkeep = 0; }
    __syncthreads();

    float q2 = q2buf[tok];
    for (int c = wid; c < n; c += 8) {
        int ki = cidx[(size_t)tok * CAP + c];
        const float* kp = keys + (size_t)ki * DKD;
        float p = 0.f;
        #pragma unroll
        for (int e = 0; e < 8; e++) { int d = lane + e * 32; p = fmaf(qrow[d], kp[d], p); }
        #pragma unroll
        for (int o = 16; o; o >>= 1) p += __shfl_xor_sync(0xffffffffu, p, o);
        if (lane == 0) {
            float lg = -(q2 - 2.0f * p + k2buf[ki]) / 0.1f;
            lg_all[c] = lg;
            atomicMax(&s_maxenc, fenc(lg));
        }
    }
    __syncthreads();
    float cut = fdec(s_maxenc) - CUT_LG;
    for (int c = tid; c < n; c += 256) {
        if (lg_all[c] >= cut) {
            int pos = atomicAdd(&s_nkeep, 1);
            if (pos < MAXKEEP) {
                keep_idx[pos] = cidx[(size_t)tok * CAP + c];
                keep_lg[pos]  = lg_all[c];
            }
        }
    }
    __syncthreads();
    int nk = min(s_nkeep, MAXKEEP);
    if (tid == 0) {
        for (int a = 1; a < nk; a++) {
            int ia = keep_idx[a]; float la = keep_lg[a];
            int b = a - 1;
            while (b >= 0 && keep_idx[b] > ia) {
                keep_idx[b + 1] = keep_idx[b]; keep_lg[b + 1] = keep_lg[b]; b--;
            }
            keep_idx[b + 1] = ia; keep_lg[b + 1] = la;
        }
    }
    __syncthreads();
    if (wid == 0) {
        for (int k = 0; k < KN; k++) {
            float lm = -1e30f;
            for (int c = lane; c < nk; c += 32) lm = fmaxf(lm, keep_lg[c]);
            #pragma unroll
            for (int o = 16; o; o >>= 1) lm = fmaxf(lm, __shfl_xor_sync(0xffffffffu, lm, o));
            float zs = 0.f;
            for (int c = lane; c < nk; c += 32) {
                float p = expf(keep_lg[c] - lm);
                wmat[k][c] = p;
                zs += p;
            }
            #pragma unroll
            for (int o = 16; o; o >>= 1) zs += __shfl_xor_sync(0xffffffffu, zs, o);
            float inv = 1.0f / zs;
            for (int c = lane; c < nk; c += 32) {
                float w = wmat[k][c] * inv;
                wmat[k][c] = w;
                keep_lg[c] += log1pf(-w + 1e-6f);
            }
            __syncwarp();
        }
    }
    __syncthreads();
    float a[KN] = {};
    for (int c = 0; c < nk; c++) {
        float v = vals[(size_t)keep_idx[c] * DM + tid];
        #pragma unroll
        for (int k = 0; k < KN; k++) a[k] = fmaf(wmat[k][c], v, a[k]);
    }
    #pragma unroll
    for (int k = 0; k < KN; k++) {
        float v = a[k];
        __nv_bfloat16 h = __float2bfloat16_rn(v);
        float lo = v - __bfloat162float(h);
        size_t off = (size_t)tok * FF + k * DM + tid;
        ah[off] = h;
        al[off] = __float2bfloat16_rn(lo);
    }
}

// ---------------- W_out GEMM: split-bf16 tensor cores ----------------
// C[m][n] = sum_f A[m][f]*B[n][f] + bias[n], via Ah*Bh + Ah*Bl + Al*Bh
// tile 128x128, K chunks of 64, double buffered.
#define WO_AH0 0
#define WO_AL0 16384
#define WO_BH0 32768
#define WO_BL0 49152
#define WO_BUF 65536
#define WO_BIAS 131072
#define SMEM_WOUT 131584

__global__ void __launch_bounds__(256, 1) wout_mma_kernel(
    const __nv_bfloat16* __restrict__ ah, const __nv_bfloat16* __restrict__ al,
    const __nv_bfloat16* __restrict__ bh, const __nv_bfloat16* __restrict__ bl,
    const float* __restrict__ bias, float* __restrict__ C)
{
    extern __shared__ char smem[];
    uint32_t sb = smem_u32(smem);
    float* biash = (float*)(smem + WO_BIAS);

    int tid  = threadIdx.x;
    int lane = tid & 31, wid = tid >> 5;
    int m0 = blockIdx.x * 128, n0 = blockIdx.y * 128;
    int mbase = (wid >> 1) * 32;
    int nhalf = (wid & 1) * 64;

    if (tid < 128) biash[tid] = bias[n0 + tid];

    // tile loader: 128 rows x 64 bf16 (128B) from row-major [*, FF] source
    auto load_tile = [&](uint32_t dst, const __nv_bfloat16* src, int row0, int k0) {
        const char* base = (const char*)(src + (size_t)row0 * FF + k0);
        for (int i = tid; i < 1024; i += 256) {
            int row = i >> 3, c16 = i & 7;
            int colb = c16 * 16;
            uint32_t sw = (uint32_t)(colb ^ ((row & 7) << 4));
            CP_ASYNC16(sb + dst + row * 128 + sw, base + (size_t)row * (FF * 2) + colb);
        }
    };

    // prologue: chunk 0
    load_tile(WO_AH0, ah, m0, 0);
    load_tile(WO_AL0, al, m0, 0);
    load_tile(WO_BH0, bh, n0, 0);
    load_tile(WO_BL0, bl, n0, 0);
    CP_COMMIT();

    float acc[2][8][4] = {};

    const int NCH = FF / 64;   // 32
    for (int j = 0; j < NCH; j++) {
        uint32_t buf = (j & 1) ? WO_BUF : 0;
        if (j + 1 < NCH) {
            uint32_t nb = ((j + 1) & 1) ? WO_BUF : 0;
            int k0 = (j + 1) * 64;
            load_tile(nb + WO_AH0, ah, m0, k0);
            load_tile(nb + WO_AL0, al, m0, k0);
            load_tile(nb + WO_BH0, bh, n0, k0);
            load_tile(nb + WO_BL0, bl, n0, k0);
            CP_COMMIT();
            CP_WAIT(1);
        } else {
            CP_WAIT(0);
        }
        __syncthreads();

        #pragma unroll
        for (int kk = 0; kk < 4; kk++) {
            uint32_t afh[2][4], afl[2][4];
            #pragma unroll
            for (int mt = 0; mt < 2; mt++) {
                int row = mbase + mt * 16 + (lane & 15);
                int colb = kk * 32 + ((lane >> 4) << 4);
                uint32_t sw = (uint32_t)(colb ^ ((row & 7) << 4));
                LDSM_X4(afh[mt][0], afh[mt][1], afh[mt][2], afh[mt][3],
                        sb + buf + WO_AH0 + row * 128 + sw);
                LDSM_X4(afl[mt][0], afl[mt][1], afl[mt][2], afl[mt][3],
                        sb + buf + WO_AL0 + row * 128 + sw);
            }
            uint32_t bfh[8][2], bfl[8][2];
            #pragma unroll
            for (int bt = 0; bt < 4; bt++) {
                int nrow = nhalf + bt * 16 + (lane & 7) + ((lane >> 4) << 3);
                int colb = kk * 32 + ((lane & 8) << 1);
                uint32_t sw = (uint32_t)(colb ^ ((nrow & 7) << 4));
                LDSM_X4(bfh[bt * 2][0], bfh[bt * 2][1], bfh[bt * 2 + 1][0], bfh[bt * 2 + 1][1],
                        sb + buf + WO_BH0 + nrow * 128 + sw);
                LDSM_X4(bfl[bt * 2][0], bfl[bt * 2][1], bfl[bt * 2 + 1][0], bfl[bt * 2 + 1][1],
                        sb + buf + WO_BL0 + nrow * 128 + sw);
            }
            #pragma unroll
            for (int mt = 0; mt < 2; mt++)
                #pragma unroll
                for (int nt = 0; nt < 8; nt++) {
                    MMA16816(acc[mt][nt], afh[mt], bfh[nt]);
                    MMA16816(acc[mt][nt], afh[mt], bfl[nt]);
                    MMA16816(acc[mt][nt], afl[mt], bfh[nt]);
                }
        }
        __syncthreads();
    }

    // epilogue: add bias, store fp32
    #pragma unroll
    for (int mt = 0; mt < 2; mt++) {
        int r0 = m0 + mbase + mt * 16 + (lane >> 2);
        #pragma unroll
        for (int nt = 0; nt < 8; nt++) {
            int cl = nhalf + nt * 8 + 2 * (lane & 3);
            float b0 = biash[cl], b1 = biash[cl + 1];
            float2 v0 = make_float2(acc[mt][nt][0] + b0, acc[mt][nt][1] + b1);
            float2 v1 = make_float2(acc[mt][nt][2] + b0, acc[mt][nt][3] + b1);
            *(float2*)&C[(size_t)r0 * D + n0 + cl] = v0;
            *(float2*)&C[(size_t)(r0 + 8) * D + n0 + cl] = v1;
        }
    }
}

// ---------------- RMSNorm (in place on d_out) ----------------
__global__ void rmsnorm_kernel(float* __restrict__ out, const float* __restrict__ rms_w) {
    __shared__ float wsum[8];
    __shared__ float s_tot;
    int tok = blockIdx.x, tid = threadIdx.x;
    float* row = out + (size_t)tok * D;
    float v[4];
    float ss = 0.f;
    #pragma unroll
    for (int e = 0; e < 4; e++) { v[e] = row[tid + e * 256]; ss = fmaf(v[e], v[e], ss); }
    #pragma unroll
    for (int o = 16; o; o >>= 1) ss += __shfl_xor_sync(0xffffffffu, ss, o);
    if ((tid & 31) == 0) wsum[tid >> 5] = ss;
    __syncthreads();
    if (tid == 0) {
        float t = 0.f;
        #pragma unroll
        for (int w = 0; w < 8; w++) t += wsum[w];
        s_tot = t;
    }
    __syncthreads();
    float var = s_tot / (float)D;
    float rs = 1.0f / sqrtf(var + 1e-6f);
    #pragma unroll
    for (int e = 0; e < 4; e++) {
        int d = tid + e * 256;
        row[d] = rms_w[d] * (v[e] * rs);
    }
}

// ---------------- host launch ----------------
extern "C" void kernel_launch(void* const* d_in, const int* in_sizes, int n_in,
                              void* d_out, int out_size) {
    const float* x     = (const float*)d_in[0];
    const float* keys  = (const float*)d_in[1];
    const float* vals  = (const float*)d_in[2];
    const float* W_in  = (const float*)d_in[3];
    const float* b_in  = (const float*)d_in[4];
    const float* W_out = (const float*)d_in[5];
    const float* b_out = (const float*)d_in[6];
    const float* rms_w = (const float*)d_in[7];
    float* out = (float*)d_out;
    (void)in_sizes; (void)n_in; (void)out_size;

    float *qp, *q2p, *k2p;
    int *cntp, *cidxp;
    __nv_bfloat16 *kbp, *qbp, *ahp, *alp, *whp, *wlp;
    cudaGetSymbolAddress((void**)&qp,    g_q);
    cudaGetSymbolAddress((void**)&q2p,   g_q2);
    cudaGetSymbolAddress((void**)&k2p,   g_k2);
    cudaGetSymbolAddress((void**)&cntp,  g_cnt);
    cudaGetSymbolAddress((void**)&cidxp, g_cidx);
    cudaGetSymbolAddress((void**)&kbp,   g_keys_bf);
    cudaGetSymbolAddress((void**)&qbp,   g_q_bf);
    cudaGetSymbolAddress((void**)&ahp,   g_ah);
    cudaGetSymbolAddress((void**)&alp,   g_al);
    cudaGetSymbolAddress((void**)&whp,   g_wh);
    cudaGetSymbolAddress((void**)&wlp,   g_wl);

    static int smem_set = 0;
    if (!smem_set) {
        cudaFuncSetAttribute(scan_mma_kernel, cudaFuncAttributeMaxDynamicSharedMemorySize, SMEM_SCAN);
        cudaFuncSetAttribute(wout_mma_kernel, cudaFuncAttributeMaxDynamicSharedMemorySize, SMEM_WOUT);
        smem_set = 1;
    }

    // 1. reset candidate counters
    init_cnt_kernel<<<(R + 255) / 256, 256>>>(cntp);
    // 2. k2 = sum(keys^2); keys -> bf16; W_out -> split bf16
    rowsumsq_kernel<<<NKEYS / 8, 256>>>(keys, k2p, DKD);
    cvt_bf16_kernel<<<(NKEYS * DKD / 4 + 255) / 256, 256>>>(keys, kbp, NKEYS * DKD / 4);
    cvt_split_kernel<<<(D * FF / 4 + 255) / 256, 256>>>(W_out, whp, wlp, D * FF / 4);
    // 3. q = x @ W_in^T + b_in (fp32, feeds exact rescore)
    gemm_tn_kernel<<<dim3(R / 64, DKD / 64), 256>>>(x, W_in, b_in, qp, R, DKD, D);
    // 4. q2 = sum(q^2); q -> bf16
    rowsumsq_kernel<<<R / 8, 256>>>(qp, q2p, DKD);
    cvt_bf16_kernel<<<(R * DKD / 4 + 255) / 256, 256>>>(qp, qbp, R * DKD / 4);
    // 5. tensor-core qk scan + candidate selection
    scan_mma_kernel<<<dim3(R / TOKS, KSPLIT), 256, SMEM_SCAN>>>(qbp, kbp, k2p, cntp, cidxp);
    // 6. exact rescore + 8-round recursion + gather -> split-bf16 nearest
    recurse_kernel<<<R, 256>>>(keys, vals, qp, q2p, k2p, cntp, cidxp, ahp, alp);
    // 7. out = nearest @ W_out^T + b_out (split-bf16 tensor cores)
    wout_mma_kernel<<<dim3(R / 128, D / 128), 256, SMEM_WOUT>>>(ahp, alp, whp, wlp, b_out, out);
    // 8. RMSNorm * rms_w, in place
    rmsnorm_kernel<<<R, 256>>>(out, rms_w);
}

// round 5
// speedup vs baseline: 3.9416x; 1.0071x over previous
#include <cuda_runtime.h>
#include <cuda_bf16.h>
#include <cuda_fp8.h>
#include <math.h>
#include <stdint.h>

// Problem constants
#define R      4096      // B*T
#define D      1024
#define DKD    256       // DK
#define NKEYS  32768
#define DM     256
#define KN     8         // K_NEIGHBORS
#define FF     (KN*DM)   // 2048
#define CAP    1024
#define MAXKEEP 64
#define CUT_LG  131.0f
#define DELTA_S 14.0f    // fp8 scan: widened pre-filter threshold

// tensor scan tiling
#define TOKS   128
#define KEYT   128
#define KSPLIT 8
#define NT_TILES ((NKEYS / KSPLIT) / KEYT)   // 32

// ---------------- scratch (static device globals; no allocation) ----------------
__device__ __align__(16) float g_q[R * DKD];
__device__ __align__(16) float g_q2[R];
__device__ __align__(16) float g_k2[NKEYS];
__device__ __align__(16) int   g_cidx[(size_t)R * CAP];
__device__ __align__(16) int   g_cnt[R];
__device__ __align__(16) unsigned char g_keys_f8[(size_t)NKEYS * DKD];
__device__ __align__(16) unsigned char g_q_f8[(size_t)R * DKD];
// split-bf16 operands for the W_out GEMM
__device__ __align__(16) __nv_bfloat16 g_ah[(size_t)R * FF];
__device__ __align__(16) __nv_bfloat16 g_al[(size_t)R * FF];
__device__ __align__(16) __nv_bfloat16 g_wh[(size_t)D * FF];
__device__ __align__(16) __nv_bfloat16 g_wl[(size_t)D * FF];

// ---------------- PTX helpers ----------------
__device__ __forceinline__ uint32_t smem_u32(const void* p) {
    uint32_t a;
    asm("{ .reg .u64 t; cvta.to.shared.u64 t, %1; cvt.u32.u64 %0, t; }" : "=r"(a) : "l"(p));
    return a;
}
#define CP_ASYNC16(dst, src) \
    asm volatile("cp.async.cg.shared.global [%0], [%1], 16;" \
                 :: "r"((uint32_t)(dst)), "l"(__cvta_generic_to_global(src)) : "memory")
#define CP_COMMIT()    asm volatile("cp.async.commit_group;" ::: "memory")
#define CP_WAIT(n)     asm volatile("cp.async.wait_group %0;" :: "n"(n) : "memory")

#define LDSM_X4(r0, r1, r2, r3, addr) \
    asm volatile("ldmatrix.sync.aligned.m8n8.x4.shared.b16 {%0,%1,%2,%3}, [%4];" \
                 : "=r"(r0), "=r"(r1), "=r"(r2), "=r"(r3) : "r"(addr))

#define MMA16816(d, a, b) \
    asm volatile("mma.sync.aligned.m16n8k16.row.col.f32.bf16.bf16.f32 " \
                 "{%0,%1,%2,%3}, {%4,%5,%6,%7}, {%8,%9}, {%0,%1,%2,%3};" \
                 : "+f"((d)[0]), "+f"((d)[1]), "+f"((d)[2]), "+f"((d)[3]) \
                 : "r"((a)[0]), "r"((a)[1]), "r"((a)[2]), "r"((a)[3]), \
                   "r"((b)[0]), "r"((b)[1]))

#define MMA16832F8(d, a, b) \
    asm volatile("mma.sync.aligned.m16n8k32.row.col.f32.e4m3.e4m3.f32 " \
                 "{%0,%1,%2,%3}, {%4,%5,%6,%7}, {%8,%9}, {%0,%1,%2,%3};" \
                 : "+f"((d)[0]), "+f"((d)[1]), "+f"((d)[2]), "+f"((d)[3]) \
                 : "r"((a)[0]), "r"((a)[1]), "r"((a)[2]), "r"((a)[3]), \
                   "r"((b)[0]), "r"((b)[1]))

// ordered-float encoding for unsigned atomicMax
__device__ __forceinline__ unsigned fenc(float f) {
    unsigned u = __float_as_uint(f);
    return (u & 0x80000000u) ? ~u : (u | 0x80000000u);
}
__device__ __forceinline__ float fdec(unsigned e) {
    return __uint_as_float((e & 0x80000000u) ? (e & 0x7fffffffu) : ~e);
}

// ---------------- init: zero candidate counters ----------------
__global__ void init_cnt_kernel(int* __restrict__ cnt) {
    int i = blockIdx.x * blockDim.x + threadIdx.x;
    if (i < R) cnt[i] = 0;
}

// ---------------- fused: row sum-of-squares + fp32 -> e4m3 convert (256 cols) ----
__global__ void prep_fp8_kernel(const float* __restrict__ src, unsigned char* __restrict__ dst,
                                float* __restrict__ sumsq) {
    int row  = blockIdx.x * 8 + (threadIdx.x >> 5);
    int lane = threadIdx.x & 31;
    const float4* p = (const float4*)(src + (size_t)row * DKD);
    float4 v0 = p[lane * 2], v1 = p[lane * 2 + 1];
    float s = v0.x * v0.x;
    s = fmaf(v0.y, v0.y, s); s = fmaf(v0.z, v0.z, s); s = fmaf(v0.w, v0.w, s);
    s = fmaf(v1.x, v1.x, s); s = fmaf(v1.y, v1.y, s);
    s = fmaf(v1.z, v1.z, s); s = fmaf(v1.w, v1.w, s);
    #pragma unroll
    for (int o = 16; o; o >>= 1) s += __shfl_xor_sync(0xffffffffu, s, o);
    if (lane == 0) sumsq[row] = s;
    uint32_t p0 = __nv_cvt_float2_to_fp8x2(make_float2(v0.x, v0.y), __NV_SATFINITE, __NV_E4M3);
    uint32_t p1 = __nv_cvt_float2_to_fp8x2(make_float2(v0.z, v0.w), __NV_SATFINITE, __NV_E4M3);
    uint32_t p2 = __nv_cvt_float2_to_fp8x2(make_float2(v1.x, v1.y), __NV_SATFINITE, __NV_E4M3);
    uint32_t p3 = __nv_cvt_float2_to_fp8x2(make_float2(v1.z, v1.w), __NV_SATFINITE, __NV_E4M3);
    uint2 w;
    w.x = (p0 & 0xffffu) | (p1 << 16);
    w.y = (p2 & 0xffffu) | (p3 << 16);
    *(uint2*)(dst + (size_t)row * DKD + lane * 8) = w;
}

// ---------------- fp32 -> split bf16 hi/lo ----------------
__global__ void cvt_split_kernel(const float* __restrict__ src,
                                 __nv_bfloat16* __restrict__ hi, __nv_bfloat16* __restrict__ lo,
                                 int n4) {
    int i = blockIdx.x * blockDim.x + threadIdx.x;
    if (i < n4) {
        float4 v = ((const float4*)src)[i];
        float h0 = __bfloat162float(__float2bfloat16_rn(v.x));
        float h1 = __bfloat162float(__float2bfloat16_rn(v.y));
        float h2 = __bfloat162float(__float2bfloat16_rn(v.z));
        float h3 = __bfloat162float(__float2bfloat16_rn(v.w));
        __nv_bfloat162* dh = (__nv_bfloat162*)hi;
        __nv_bfloat162* dl = (__nv_bfloat162*)lo;
        dh[i * 2 + 0] = __floats2bfloat162_rn(h0, h1);
        dh[i * 2 + 1] = __floats2bfloat162_rn(h2, h3);
        dl[i * 2 + 0] = __floats2bfloat162_rn(v.x - h0, v.y - h1);
        dl[i * 2 + 1] = __floats2bfloat162_rn(v.z - h2, v.w - h3);
    }
}

// ---------------- fp32 TN GEMM (q projection only): C = A@B^T + bias ----------------
__global__ void gemm_tn_kernel(const float* __restrict__ A, const float* __restrict__ B,
                               const float* __restrict__ bias, float* __restrict__ C,
                               int M, int N, int K) {
    __shared__ float As[16][64];
    __shared__ float Bs[16][64];
    int m0 = blockIdx.x * 64, n0 = blockIdx.y * 64;
    int tid = threadIdx.x;
    int tx = tid & 15, ty = tid >> 4;
    int lr = tid >> 2;
    int lc = (tid & 3) * 4;
    float acc[4][4] = {};
    for (int k0 = 0; k0 < K; k0 += 16) {
        __syncthreads();
        float4 av = *(const float4*)&A[(size_t)(m0 + lr) * K + k0 + lc];
        float4 bv = *(const float4*)&B[(size_t)(n0 + lr) * K + k0 + lc];
        As[lc + 0][lr] = av.x; As[lc + 1][lr] = av.y; As[lc + 2][lr] = av.z; As[lc + 3][lr] = av.w;
        Bs[lc + 0][lr] = bv.x; Bs[lc + 1][lr] = bv.y; Bs[lc + 2][lr] = bv.z; Bs[lc + 3][lr] = bv.w;
        __syncthreads();
        #pragma unroll
        for (int kk = 0; kk < 16; kk++) {
            float4 a = *(const float4*)&As[kk][ty * 4];
            float4 b = *(const float4*)&Bs[kk][tx * 4];
            acc[0][0] = fmaf(a.x, b.x, acc[0][0]); acc[0][1] = fmaf(a.x, b.y, acc[0][1]);
            acc[0][2] = fmaf(a.x, b.z, acc[0][2]); acc[0][3] = fmaf(a.x, b.w, acc[0][3]);
            acc[1][0] = fmaf(a.y, b.x, acc[1][0]); acc[1][1] = fmaf(a.y, b.y, acc[1][1]);
            acc[1][2] = fmaf(a.y, b.z, acc[1][2]); acc[1][3] = fmaf(a.y, b.w, acc[1][3]);
            acc[2][0] = fmaf(a.z, b.x, acc[2][0]); acc[2][1] = fmaf(a.z, b.y, acc[2][1]);
            acc[2][2] = fmaf(a.z, b.z, acc[2][2]); acc[2][3] = fmaf(a.z, b.w, acc[2][3]);
            acc[3][0] = fmaf(a.w, b.x, acc[3][0]); acc[3][1] = fmaf(a.w, b.y, acc[3][1]);
            acc[3][2] = fmaf(a.w, b.z, acc[3][2]); acc[3][3] = fmaf(a.w, b.w, acc[3][3]);
        }
    }
    #pragma unroll
    for (int i = 0; i < 4; i++) {
        #pragma unroll
        for (int j = 0; j < 4; j++) {
            int n = n0 + tx * 4 + j;
            C[(size_t)(m0 + ty * 4 + i) * N + n] = acc[i][j] + bias[n];
        }
    }
}

// ---------------- fp8 tensor scan: e4m3 mma.sync + threshold selection ----------------
// SMEM layout (bytes): A 128x256B @0, B0 @32768, B1 @65536, k2 @98304, smax @98816
#define SO_A    0
#define SO_B0   32768
#define SO_B1   65536
#define SO_K2   98304
#define SO_SMAX 98816
#define SMEM_SCAN 99328

__global__ void __launch_bounds__(256, 2) scan_mma_kernel(
    const unsigned char* __restrict__ qf, const unsigned char* __restrict__ kf,
    const float* __restrict__ k2buf, int* __restrict__ cnt, int* __restrict__ cidx)
{
    extern __shared__ char smem[];
    uint32_t sb = smem_u32(smem);
    float*    k2h  = (float*)(smem + SO_K2);
    unsigned* smax = (unsigned*)(smem + SO_SMAX);

    int tid  = threadIdx.x;
    int lane = tid & 31, wid = tid >> 5;
    int tok0 = blockIdx.x * TOKS;
    int keybase = blockIdx.y * (NKEYS / KSPLIT);
    int mbase = (wid >> 1) * 32;
    int nhalf = (wid & 1) * 64;

    if (tid < TOKS) smax[tid] = fenc(-1e30f);

    // prologue: A tile (128 x 256B) + B tile 0, swizzled rows
    {
        const char* abase = (const char*)(qf + (size_t)tok0 * DKD);
        const char* bbase = (const char*)(kf + (size_t)keybase * DKD);
        for (int i = tid; i < 2048; i += 256) {
            int row = i >> 4, c16 = i & 15;
            int colb = c16 * 16;
            uint32_t sw = (uint32_t)(colb ^ ((row & 7) << 4));
            CP_ASYNC16(sb + SO_A + row * 256 + sw, abase + row * 256 + colb);
            CP_ASYNC16(sb + SO_B0 + row * 256 + sw, bbase + row * 256 + colb);
        }
        CP_COMMIT();
    }

    float acc[2][8][4];

    for (int t = 0; t < NT_TILES; t++) {
        int key0 = keybase + t * KEYT;

        // prefetch next B tile into the other buffer
        if (t + 1 < NT_TILES) {
            uint32_t nb = ((t + 1) & 1) ? SO_B1 : SO_B0;
            const char* bbase = (const char*)(kf + (size_t)(key0 + KEYT) * DKD);
            for (int i = tid; i < 2048; i += 256) {
                int row = i >> 4, c16 = i & 15;
                int colb = c16 * 16;
                uint32_t sw = (uint32_t)(colb ^ ((row & 7) << 4));
                CP_ASYNC16(sb + nb + row * 256 + sw, bbase + row * 256 + colb);
            }
            CP_COMMIT();
            CP_WAIT(1);
        } else {
            CP_WAIT(0);
        }
        __syncthreads();

        if (tid < KEYT) k2h[tid] = 0.5f * k2buf[key0 + tid];

        #pragma unroll
        for (int mt = 0; mt < 2; mt++)
            #pragma unroll
            for (int nt = 0; nt < 8; nt++)
                #pragma unroll
                for (int e = 0; e < 4; e++) acc[mt][nt][e] = 0.f;

        // K = 256 fp8 in 8 k32 steps
        uint32_t bbuf = sb + ((t & 1) ? SO_B1 : SO_B0);
        #pragma unroll
        for (int kk = 0; kk < 8; kk++) {
            uint32_t a[2][4];
            #pragma unroll
            for (int mt = 0; mt < 2; mt++) {
                int row = mbase + mt * 16 + (lane & 15);
                int colb = kk * 32 + ((lane >> 4) << 4);
                uint32_t ad = sb + SO_A + row * 256 + (uint32_t)(colb ^ ((row & 7) << 4));
                LDSM_X4(a[mt][0], a[mt][1], a[mt][2], a[mt][3], ad);
            }
            uint32_t b[8][2];
            #pragma unroll
            for (int bt = 0; bt < 4; bt++) {
                int n = nhalf + bt * 16 + (lane & 7) + ((lane >> 4) << 3);
                int colb = kk * 32 + ((lane & 8) << 1);
                uint32_t bd = bbuf + n * 256 + (uint32_t)(colb ^ ((n & 7) << 4));
                LDSM_X4(b[bt * 2][0], b[bt * 2][1], b[bt * 2 + 1][0], b[bt * 2 + 1][1], bd);
            }
            #pragma unroll
            for (int mt = 0; mt < 2; mt++)
                #pragma unroll
                for (int nt = 0; nt < 8; nt++)
                    MMA16832F8(acc[mt][nt], a[mt], b[nt]);
        }
        __syncthreads();

        // epilogue: scores, running max, selection
        {
            float rm[2][2];
            #pragma unroll
            for (int mt = 0; mt < 2; mt++) { rm[mt][0] = -1e30f; rm[mt][1] = -1e30f; }
            #pragma unroll
            for (int mt = 0; mt < 2; mt++) {
                #pragma unroll
                for (int nt = 0; nt < 8; nt++) {
                    float kc0 = k2h[nhalf + nt * 8 + 2 * (lane & 3)];
                    float kc1 = k2h[nhalf + nt * 8 + 2 * (lane & 3) + 1];
                    acc[mt][nt][0] -= kc0; acc[mt][nt][1] -= kc1;
                    acc[mt][nt][2] -= kc0; acc[mt][nt][3] -= kc1;
                    rm[mt][0] = fmaxf(rm[mt][0], fmaxf(acc[mt][nt][0], acc[mt][nt][1]));
                    rm[mt][1] = fmaxf(rm[mt][1], fmaxf(acc[mt][nt][2], acc[mt][nt][3]));
                }
            }
            #pragma unroll
            for (int mt = 0; mt < 2; mt++) {
                #pragma unroll
                for (int e = 0; e < 2; e++) {
                    float v = rm[mt][e];
                    v = fmaxf(v, __shfl_xor_sync(0xffffffffu, v, 1));
                    v = fmaxf(v, __shfl_xor_sync(0xffffffffu, v, 2));
                    rm[mt][e] = v;
                }
            }
            if ((lane & 3) == 0) {
                #pragma unroll
                for (int mt = 0; mt < 2; mt++) {
                    int r = mbase + mt * 16 + (lane >> 2);
                    atomicMax(&smax[r], fenc(rm[mt][0]));
                    atomicMax(&smax[r + 8], fenc(rm[mt][1]));
                }
            }
            __syncthreads();
            #pragma unroll
            for (int mt = 0; mt < 2; mt++) {
                int r0 = mbase + mt * 16 + (lane >> 2);
                float th0 = fdec(smax[r0]) - DELTA_S;
                float th1 = fdec(smax[r0 + 8]) - DELTA_S;
                int tokA = tok0 + r0, tokB = tokA + 8;
                #pragma unroll
                for (int nt = 0; nt < 8; nt++) {
                    int keyc = key0 + nhalf + nt * 8 + 2 * (lane & 3);
                    if (acc[mt][nt][0] > th0) {
                        int pos = atomicAdd(&cnt[tokA], 1);
                        if (pos < CAP) cidx[(size_t)tokA * CAP + pos] = keyc;
                    }
                    if (acc[mt][nt][1] > th0) {
                        int pos = atomicAdd(&cnt[tokA], 1);
                        if (pos < CAP) cidx[(size_t)tokA * CAP + pos] = keyc + 1;
                    }
                    if (acc[mt][nt][2] > th1) {
                        int pos = atomicAdd(&cnt[tokB], 1);
                        if (pos < CAP) cidx[(size_t)tokB * CAP + pos] = keyc;
                    }
                    if (acc[mt][nt][3] > th1) {
                        int pos = atomicAdd(&cnt[tokB], 1);
                        if (pos < CAP) cidx[(size_t)tokB * CAP + pos] = keyc + 1;
                    }
                }
            }
            __syncthreads();
        }
    }
}

// ---------------- exact rescore + 8-round recursion + gather (emits split bf16) ----
__global__ void recurse_kernel(const float* __restrict__ keys, const float* __restrict__ vals,
                               const float* __restrict__ qbuf, const float* __restrict__ q2buf,
                               const float* __restrict__ k2buf, const int* __restrict__ cnt,
                               const int* __restrict__ cidx,
                               __nv_bfloat16* __restrict__ ah, __nv_bfloat16* __restrict__ al) {
    __shared__ float    qrow[DKD];
    __shared__ float    lg_all[CAP];
    __shared__ int      keep_idx[MAXKEEP];
    __shared__ float    keep_lg[MAXKEEP];
    __shared__ float    wmat[KN][MAXKEEP];
    __shared__ unsigned s_maxenc;
    __shared__ int      s_nkeep;

    int tok = blockIdx.x, tid = threadIdx.x;
    int lane = tid & 31, wid = tid >> 5;
    int n = min(cnt[tok], CAP);

    qrow[tid] = qbuf[(size_t)tok * DKD + tid];
    if (tid == 0) { s_maxenc = fenc(-1e30f); s_nkeep = 0; }
    __syncthreads();

    float q2 = q2buf[tok];
    for (int c = wid; c < n; c += 8) {
        int ki = cidx[(size_t)tok * CAP + c];
        const float* kp = keys + (size_t)ki * DKD;
        float p = 0.f;
        #pragma unroll
        for (int e = 0; e < 8; e++) { int d = lane + e * 32; p = fmaf(qrow[d], kp[d], p); }
        #pragma unroll
        for (int o = 16; o; o >>= 1) p += __shfl_xor_sync(0xffffffffu, p, o);
        if (lane == 0) {
            float lg = -(q2 - 2.0f * p + k2buf[ki]) / 0.1f;
            lg_all[c] = lg;
            atomicMax(&s_maxenc, fenc(lg));
        }
    }
    __syncthreads();
    float cut = fdec(s_maxenc) - CUT_LG;
    for (int c = tid; c < n; c += 256) {
        if (lg_all[c] >= cut) {
            int pos = atomicAdd(&s_nkeep, 1);
            if (pos < MAXKEEP) {
                keep_idx[pos] = cidx[(size_t)tok * CAP + c];
                keep_lg[pos]  = lg_all[c];
            }
        }
    }
    __syncthreads();
    int nk = min(s_nkeep, MAXKEEP);
    if (tid == 0) {
        for (int a = 1; a < nk; a++) {
            int ia = keep_idx[a]; float la = keep_lg[a];
            int b = a - 1;
            while (b >= 0 && keep_idx[b] > ia) {
                keep_idx[b + 1] = keep_idx[b]; keep_lg[b + 1] = keep_lg[b]; b--;
            }
            keep_idx[b + 1] = ia; keep_lg[b + 1] = la;
        }
    }
    __syncthreads();
    if (wid == 0) {
        for (int k = 0; k < KN; k++) {
            float lm = -1e30f;
            for (int c = lane; c < nk; c += 32) lm = fmaxf(lm, keep_lg[c]);
            #pragma unroll
            for (int o = 16; o; o >>= 1) lm = fmaxf(lm, __shfl_xor_sync(0xffffffffu, lm, o));
            float zs = 0.f;
            for (int c = lane; c < nk; c += 32) {
                float p = expf(keep_lg[c] - lm);
                wmat[k][c] = p;
                zs += p;
            }
            #pragma unroll
            for (int o = 16; o; o >>= 1) zs += __shfl_xor_sync(0xffffffffu, zs, o);
            float inv = 1.0f / zs;
            for (int c = lane; c < nk; c += 32) {
                float w = wmat[k][c] * inv;
                wmat[k][c] = w;
                keep_lg[c] += log1pf(-w + 1e-6f);
            }
            __syncwarp();
        }
    }
    __syncthreads();
    float a[KN] = {};
    for (int c = 0; c < nk; c++) {
        float v = vals[(size_t)keep_idx[c] * DM + tid];
        #pragma unroll
        for (int k = 0; k < KN; k++) a[k] = fmaf(wmat[k][c], v, a[k]);
    }
    #pragma unroll
    for (int k = 0; k < KN; k++) {
        float v = a[k];
        __nv_bfloat16 h = __float2bfloat16_rn(v);
        float lo = v - __bfloat162float(h);
        size_t off = (size_t)tok * FF + k * DM + tid;
        ah[off] = h;
        al[off] = __float2bfloat16_rn(lo);
    }
}

// ---------------- W_out GEMM: split-bf16 tensor cores ----------------
#define WO_AH0 0
#define WO_AL0 16384
#define WO_BH0 32768
#define WO_BL0 49152
#define WO_BUF 65536
#define WO_BIAS 131072
#define SMEM_WOUT 131584

__global__ void __launch_bounds__(256, 1) wout_mma_kernel(
    const __nv_bfloat16* __restrict__ ah, const __nv_bfloat16* __restrict__ al,
    const __nv_bfloat16* __restrict__ bh, const __nv_bfloat16* __restrict__ bl,
    const float* __restrict__ bias, float* __restrict__ C)
{
    extern __shared__ char smem[];
    uint32_t sb = smem_u32(smem);
    float* biash = (float*)(smem + WO_BIAS);

    int tid  = threadIdx.x;
    int lane = tid & 31, wid = tid >> 5;
    int m0 = blockIdx.x * 128, n0 = blockIdx.y * 128;
    int mbase = (wid >> 1) * 32;
    int nhalf = (wid & 1) * 64;

    if (tid < 128) biash[tid] = bias[n0 + tid];

    auto load_tile = [&](uint32_t dst, const __nv_bfloat16* src, int row0, int k0) {
        const char* base = (const char*)(src + (size_t)row0 * FF + k0);
        for (int i = tid; i < 1024; i += 256) {
            int row = i >> 3, c16 = i & 7;
            int colb = c16 * 16;
            uint32_t sw = (uint32_t)(colb ^ ((row & 7) << 4));
            CP_ASYNC16(sb + dst + row * 128 + sw, base + (size_t)row * (FF * 2) + colb);
        }
    };

    load_tile(WO_AH0, ah, m0, 0);
    load_tile(WO_AL0, al, m0, 0);
    load_tile(WO_BH0, bh, n0, 0);
    load_tile(WO_BL0, bl, n0, 0);
    CP_COMMIT();

    float acc[2][8][4] = {};

    const int NCH = FF / 64;   // 32
    for (int j = 0; j < NCH; j++) {
        uint32_t buf = (j & 1) ? WO_BUF : 0;
        if (j + 1 < NCH) {
            uint32_t nb = ((j + 1) & 1) ? WO_BUF : 0;
            int k0 = (j + 1) * 64;
            load_tile(nb + WO_AH0, ah, m0, k0);
            load_tile(nb + WO_AL0, al, m0, k0);
            load_tile(nb + WO_BH0, bh, n0, k0);
            load_tile(nb + WO_BL0, bl, n0, k0);
            CP_COMMIT();
            CP_WAIT(1);
        } else {
            CP_WAIT(0);
        }
        __syncthreads();

        #pragma unroll
        for (int kk = 0; kk < 4; kk++) {
            uint32_t afh[2][4], afl[2][4];
            #pragma unroll
            for (int mt = 0; mt < 2; mt++) {
                int row = mbase + mt * 16 + (lane & 15);
                int colb = kk * 32 + ((lane >> 4) << 4);
                uint32_t sw = (uint32_t)(colb ^ ((row & 7) << 4));
                LDSM_X4(afh[mt][0], afh[mt][1], afh[mt][2], afh[mt][3],
                        sb + buf + WO_AH0 + row * 128 + sw);
                LDSM_X4(afl[mt][0], afl[mt][1], afl[mt][2], afl[mt][3],
                        sb + buf + WO_AL0 + row * 128 + sw);
            }
            uint32_t bfh[8][2], bfl[8][2];
            #pragma unroll
            for (int bt = 0; bt < 4; bt++) {
                int nrow = nhalf + bt * 16 + (lane & 7) + ((lane >> 4) << 3);
                int colb = kk * 32 + ((lane & 8) << 1);
                uint32_t sw = (uint32_t)(colb ^ ((nrow & 7) << 4));
                LDSM_X4(bfh[bt * 2][0], bfh[bt * 2][1], bfh[bt * 2 + 1][0], bfh[bt * 2 + 1][1],
                        sb + buf + WO_BH0 + nrow * 128 + sw);
                LDSM_X4(bfl[bt * 2][0], bfl[bt * 2][1], bfl[bt * 2 + 1][0], bfl[bt * 2 + 1][1],
                        sb + buf + WO_BL0 + nrow * 128 + sw);
            }
            #pragma unroll
            for (int mt = 0; mt < 2; mt++)
                #pragma unroll
                for (int nt = 0; nt < 8; nt++) {
                    MMA16816(acc[mt][nt], afh[mt], bfh[nt]);
                    MMA16816(acc[mt][nt], afh[mt], bfl[nt]);
                    MMA16816(acc[mt][nt], afl[mt], bfh[nt]);
                }
        }
        __syncthreads();
    }

    #pragma unroll
    for (int mt = 0; mt < 2; mt++) {
        int r0 = m0 + mbase + mt * 16 + (lane >> 2);
        #pragma unroll
        for (int nt = 0; nt < 8; nt++) {
            int cl = nhalf + nt * 8 + 2 * (lane & 3);
            float b0 = biash[cl], b1 = biash[cl + 1];
            float2 v0 = make_float2(acc[mt][nt][0] + b0, acc[mt][nt][1] + b1);
            float2 v1 = make_float2(acc[mt][nt][2] + b0, acc[mt][nt][3] + b1);
            *(float2*)&C[(size_t)r0 * D + n0 + cl] = v0;
            *(float2*)&C[(size_t)(r0 + 8) * D + n0 + cl] = v1;
        }
    }
}

// ---------------- RMSNorm (in place on d_out) ----------------
__global__ void rmsnorm_kernel(float* __restrict__ out, const float* __restrict__ rms_w) {
    __shared__ float wsum[8];
    __shared__ float s_tot;
    int tok = blockIdx.x, tid = threadIdx.x;
    float* row = out + (size_t)tok * D;
    float v[4];
    float ss = 0.f;
    #pragma unroll
    for (int e = 0; e < 4; e++) { v[e] = row[tid + e * 256]; ss = fmaf(v[e], v[e], ss); }
    #pragma unroll
    for (int o = 16; o; o >>= 1) ss += __shfl_xor_sync(0xffffffffu, ss, o);
    if ((tid & 31) == 0) wsum[tid >> 5] = ss;
    __syncthreads();
    if (tid == 0) {
        float t = 0.f;
        #pragma unroll
        for (int w = 0; w < 8; w++) t += wsum[w];
        s_tot = t;
    }
    __syncthreads();
    float var = s_tot / (float)D;
    float rs = 1.0f / sqrtf(var + 1e-6f);
    #pragma unroll
    for (int e = 0; e < 4; e++) {
        int d = tid + e * 256;
        row[d] = rms_w[d] * (v[e] * rs);
    }
}

// ---------------- host launch ----------------
extern "C" void kernel_launch(void* const* d_in, const int* in_sizes, int n_in,
                              void* d_out, int out_size) {
    const float* x     = (const float*)d_in[0];
    const float* keys  = (const float*)d_in[1];
    const float* vals  = (const float*)d_in[2];
    const float* W_in  = (const float*)d_in[3];
    const float* b_in  = (const float*)d_in[4];
    const float* W_out = (const float*)d_in[5];
    const float* b_out = (const float*)d_in[6];
    const float* rms_w = (const float*)d_in[7];
    float* out = (float*)d_out;
    (void)in_sizes; (void)n_in; (void)out_size;

    float *qp, *q2p, *k2p;
    int *cntp, *cidxp;
    unsigned char *kfp, *qfp;
    __nv_bfloat16 *ahp, *alp, *whp, *wlp;
    cudaGetSymbolAddress((void**)&qp,    g_q);
    cudaGetSymbolAddress((void**)&q2p,   g_q2);
    cudaGetSymbolAddress((void**)&k2p,   g_k2);
    cudaGetSymbolAddress((void**)&cntp,  g_cnt);
    cudaGetSymbolAddress((void**)&cidxp, g_cidx);
    cudaGetSymbolAddress((void**)&kfp,   g_keys_f8);
    cudaGetSymbolAddress((void**)&qfp,   g_q_f8);
    cudaGetSymbolAddress((void**)&ahp,   g_ah);
    cudaGetSymbolAddress((void**)&alp,   g_al);
    cudaGetSymbolAddress((void**)&whp,   g_wh);
    cudaGetSymbolAddress((void**)&wlp,   g_wl);

    static int smem_set = 0;
    if (!smem_set) {
        cudaFuncSetAttribute(scan_mma_kernel, cudaFuncAttributeMaxDynamicSharedMemorySize, SMEM_SCAN);
        cudaFuncSetAttribute(wout_mma_kernel, cudaFuncAttributeMaxDynamicSharedMemorySize, SMEM_WOUT);
        smem_set = 1;
    }

    // 1. reset candidate counters
    init_cnt_kernel<<<(R + 255) / 256, 256>>>(cntp);
    // 2. keys: k2 + fp8 convert (fused); W_out -> split bf16
    prep_fp8_kernel<<<NKEYS / 8, 256>>>(keys, kfp, k2p);
    cvt_split_kernel<<<(D * FF / 4 + 255) / 256, 256>>>(W_out, whp, wlp, D * FF / 4);
    // 3. q = x @ W_in^T + b_in (fp32, feeds exact rescore)
    gemm_tn_kernel<<<dim3(R / 64, DKD / 64), 256>>>(x, W_in, b_in, qp, R, DKD, D);
    // 4. q: q2 + fp8 convert (fused)
    prep_fp8_kernel<<<R / 8, 256>>>(qp, qfp, q2p);
    // 5. fp8 tensor-core qk scan + candidate selection
    scan_mma_kernel<<<dim3(R / TOKS, KSPLIT), 256, SMEM_SCAN>>>(qfp, kfp, k2p, cntp, cidxp);
    // 6. exact rescore + 8-round recursion + gather -> split-bf16 nearest
    recurse_kernel<<<R, 256>>>(keys, vals, qp, q2p, k2p, cntp, cidxp, ahp, alp);
    // 7. out = nearest @ W_out^T + b_out (split-bf16 tensor cores)
    wout_mma_kernel<<<dim3(R / 128, D / 128), 256, SMEM_WOUT>>>(ahp, alp, whp, wlp, b_out, out);
    // 8. RMSNorm * rms_w, in place
    rmsnorm_kernel<<<R, 256>>>(out, rms_w);
}

// round 6
// speedup vs baseline: 4.0526x; 1.0282x over previous
#include <cuda_runtime.h>
#include <cuda_bf16.h>
#include <cuda_fp8.h>
#include <math.h>
#include <stdint.h>

// Problem constants
#define R      4096      // B*T
#define D      1024
#define DKD    256       // DK
#define NKEYS  32768
#define DM     256
#define KN     8         // K_NEIGHBORS
#define FF     (KN*DM)   // 2048
#define CAP    1024
#define MAXKEEP 64
#define CUT_LG  131.0f
#define DELTA_S 14.0f    // fp8 scan: widened pre-filter threshold

// tensor scan tiling
#define TOKS   128
#define KEYT   128
#define KSPLIT 8
#define NT_TILES ((NKEYS / KSPLIT) / KEYT)   // 32

// ---------------- scratch (static device globals; no allocation) ----------------
__device__ __align__(16) float g_q[R * DKD];
__device__ __align__(16) float g_q2[R];
__device__ __align__(16) float g_k2[NKEYS];
__device__ __align__(16) int   g_cidx[(size_t)R * CAP];
__device__ __align__(16) int   g_cnt[R];
__device__ __align__(16) unsigned char g_keys_f8[(size_t)NKEYS * DKD];
__device__ __align__(16) unsigned char g_q_f8[(size_t)R * DKD];
// split-bf16 operands for the W_out GEMM
__device__ __align__(16) __nv_bfloat16 g_ah[(size_t)R * FF];
__device__ __align__(16) __nv_bfloat16 g_al[(size_t)R * FF];
__device__ __align__(16) __nv_bfloat16 g_wh[(size_t)D * FF];
__device__ __align__(16) __nv_bfloat16 g_wl[(size_t)D * FF];

// ---------------- PTX helpers ----------------
__device__ __forceinline__ uint32_t smem_u32(const void* p) {
    uint32_t a;
    asm("{ .reg .u64 t; cvta.to.shared.u64 t, %1; cvt.u32.u64 %0, t; }" : "=r"(a) : "l"(p));
    return a;
}
#define CP_ASYNC16(dst, src) \
    asm volatile("cp.async.cg.shared.global [%0], [%1], 16;" \
                 :: "r"((uint32_t)(dst)), "l"(__cvta_generic_to_global(src)) : "memory")
#define CP_COMMIT()    asm volatile("cp.async.commit_group;" ::: "memory")
#define CP_WAIT(n)     asm volatile("cp.async.wait_group %0;" :: "n"(n) : "memory")

#define LDSM_X4(r0, r1, r2, r3, addr) \
    asm volatile("ldmatrix.sync.aligned.m8n8.x4.shared.b16 {%0,%1,%2,%3}, [%4];" \
                 : "=r"(r0), "=r"(r1), "=r"(r2), "=r"(r3) : "r"(addr))

#define MMA16816(d, a, b) \
    asm volatile("mma.sync.aligned.m16n8k16.row.col.f32.bf16.bf16.f32 " \
                 "{%0,%1,%2,%3}, {%4,%5,%6,%7}, {%8,%9}, {%0,%1,%2,%3};" \
                 : "+f"((d)[0]), "+f"((d)[1]), "+f"((d)[2]), "+f"((d)[3]) \
                 : "r"((a)[0]), "r"((a)[1]), "r"((a)[2]), "r"((a)[3]), \
                   "r"((b)[0]), "r"((b)[1]))

#define MMA16832F8(d, a, b) \
    asm volatile("mma.sync.aligned.m16n8k32.row.col.f32.e4m3.e4m3.f32 " \
                 "{%0,%1,%2,%3}, {%4,%5,%6,%7}, {%8,%9}, {%0,%1,%2,%3};" \
                 : "+f"((d)[0]), "+f"((d)[1]), "+f"((d)[2]), "+f"((d)[3]) \
                 : "r"((a)[0]), "r"((a)[1]), "r"((a)[2]), "r"((a)[3]), \
                   "r"((b)[0]), "r"((b)[1]))

// ordered-float encoding for unsigned atomicMax
__device__ __forceinline__ unsigned fenc(float f) {
    unsigned u = __float_as_uint(f);
    return (u & 0x80000000u) ? ~u : (u | 0x80000000u);
}
__device__ __forceinline__ float fdec(unsigned e) {
    return __uint_as_float((e & 0x80000000u) ? (e & 0x7fffffffu) : ~e);
}

// ---------------- init: zero candidate counters ----------------
__global__ void init_cnt_kernel(int* __restrict__ cnt) {
    int i = blockIdx.x * blockDim.x + threadIdx.x;
    if (i < R) cnt[i] = 0;
}

// ---------------- fused: row sum-of-squares + fp32 -> e4m3 convert (256 cols) ----
__global__ void prep_fp8_kernel(const float* __restrict__ src, unsigned char* __restrict__ dst,
                                float* __restrict__ sumsq) {
    int row  = blockIdx.x * 8 + (threadIdx.x >> 5);
    int lane = threadIdx.x & 31;
    const float4* p = (const float4*)(src + (size_t)row * DKD);
    float4 v0 = p[lane * 2], v1 = p[lane * 2 + 1];
    float s = v0.x * v0.x;
    s = fmaf(v0.y, v0.y, s); s = fmaf(v0.z, v0.z, s); s = fmaf(v0.w, v0.w, s);
    s = fmaf(v1.x, v1.x, s); s = fmaf(v1.y, v1.y, s);
    s = fmaf(v1.z, v1.z, s); s = fmaf(v1.w, v1.w, s);
    #pragma unroll
    for (int o = 16; o; o >>= 1) s += __shfl_xor_sync(0xffffffffu, s, o);
    if (lane == 0) sumsq[row] = s;
    uint32_t p0 = __nv_cvt_float2_to_fp8x2(make_float2(v0.x, v0.y), __NV_SATFINITE, __NV_E4M3);
    uint32_t p1 = __nv_cvt_float2_to_fp8x2(make_float2(v0.z, v0.w), __NV_SATFINITE, __NV_E4M3);
    uint32_t p2 = __nv_cvt_float2_to_fp8x2(make_float2(v1.x, v1.y), __NV_SATFINITE, __NV_E4M3);
    uint32_t p3 = __nv_cvt_float2_to_fp8x2(make_float2(v1.z, v1.w), __NV_SATFINITE, __NV_E4M3);
    uint2 w;
    w.x = (p0 & 0xffffu) | (p1 << 16);
    w.y = (p2 & 0xffffu) | (p3 << 16);
    *(uint2*)(dst + (size_t)row * DKD + lane * 8) = w;
}

// ---------------- fp32 -> split bf16 hi/lo ----------------
__global__ void cvt_split_kernel(const float* __restrict__ src,
                                 __nv_bfloat16* __restrict__ hi, __nv_bfloat16* __restrict__ lo,
                                 int n4) {
    int i = blockIdx.x * blockDim.x + threadIdx.x;
    if (i < n4) {
        float4 v = ((const float4*)src)[i];
        float h0 = __bfloat162float(__float2bfloat16_rn(v.x));
        float h1 = __bfloat162float(__float2bfloat16_rn(v.y));
        float h2 = __bfloat162float(__float2bfloat16_rn(v.z));
        float h3 = __bfloat162float(__float2bfloat16_rn(v.w));
        __nv_bfloat162* dh = (__nv_bfloat162*)hi;
        __nv_bfloat162* dl = (__nv_bfloat162*)lo;
        dh[i * 2 + 0] = __floats2bfloat162_rn(h0, h1);
        dh[i * 2 + 1] = __floats2bfloat162_rn(h2, h3);
        dl[i * 2 + 0] = __floats2bfloat162_rn(v.x - h0, v.y - h1);
        dl[i * 2 + 1] = __floats2bfloat162_rn(v.z - h2, v.w - h3);
    }
}

// ---------------- fp32 TN GEMM (q projection): register-prefetch double buffer ----
__global__ void gemm_tn_kernel(const float* __restrict__ A, const float* __restrict__ B,
                               const float* __restrict__ bias, float* __restrict__ C,
                               int M, int N, int K) {
    __shared__ float As[16][64];
    __shared__ float Bs[16][64];
    int m0 = blockIdx.x * 64, n0 = blockIdx.y * 64;
    int tid = threadIdx.x;
    int tx = tid & 15, ty = tid >> 4;
    int lr = tid >> 2;
    int lc = (tid & 3) * 4;
    float acc[4][4] = {};
    // prefetch chunk 0 into registers
    float4 av = *(const float4*)&A[(size_t)(m0 + lr) * K + lc];
    float4 bv = *(const float4*)&B[(size_t)(n0 + lr) * K + lc];
    for (int k0 = 0; k0 < K; k0 += 16) {
        As[lc + 0][lr] = av.x; As[lc + 1][lr] = av.y; As[lc + 2][lr] = av.z; As[lc + 3][lr] = av.w;
        Bs[lc + 0][lr] = bv.x; Bs[lc + 1][lr] = bv.y; Bs[lc + 2][lr] = bv.z; Bs[lc + 3][lr] = bv.w;
        __syncthreads();
        if (k0 + 16 < K) {   // prefetch next chunk, overlapped with compute below
            av = *(const float4*)&A[(size_t)(m0 + lr) * K + k0 + 16 + lc];
            bv = *(const float4*)&B[(size_t)(n0 + lr) * K + k0 + 16 + lc];
        }
        #pragma unroll
        for (int kk = 0; kk < 16; kk++) {
            float4 a = *(const float4*)&As[kk][ty * 4];
            float4 b = *(const float4*)&Bs[kk][tx * 4];
            acc[0][0] = fmaf(a.x, b.x, acc[0][0]); acc[0][1] = fmaf(a.x, b.y, acc[0][1]);
            acc[0][2] = fmaf(a.x, b.z, acc[0][2]); acc[0][3] = fmaf(a.x, b.w, acc[0][3]);
            acc[1][0] = fmaf(a.y, b.x, acc[1][0]); acc[1][1] = fmaf(a.y, b.y, acc[1][1]);
            acc[1][2] = fmaf(a.y, b.z, acc[1][2]); acc[1][3] = fmaf(a.y, b.w, acc[1][3]);
            acc[2][0] = fmaf(a.z, b.x, acc[2][0]); acc[2][1] = fmaf(a.z, b.y, acc[2][1]);
            acc[2][2] = fmaf(a.z, b.z, acc[2][2]); acc[2][3] = fmaf(a.z, b.w, acc[2][3]);
            acc[3][0] = fmaf(a.w, b.x, acc[3][0]); acc[3][1] = fmaf(a.w, b.y, acc[3][1]);
            acc[3][2] = fmaf(a.w, b.z, acc[3][2]); acc[3][3] = fmaf(a.w, b.w, acc[3][3]);
        }
        __syncthreads();
    }
    #pragma unroll
    for (int i = 0; i < 4; i++) {
        #pragma unroll
        for (int j = 0; j < 4; j++) {
            int n = n0 + tx * 4 + j;
            C[(size_t)(m0 + ty * 4 + i) * N + n] = acc[i][j] + bias[n];
        }
    }
}

// ---------------- fp8 tensor scan: e4m3 mma.sync + threshold selection ----------------
#define SO_A    0
#define SO_B0   32768
#define SO_B1   65536
#define SO_K2   98304
#define SO_SMAX 98816
#define SMEM_SCAN 99328

__global__ void __launch_bounds__(256, 2) scan_mma_kernel(
    const unsigned char* __restrict__ qf, const unsigned char* __restrict__ kf,
    const float* __restrict__ k2buf, int* __restrict__ cnt, int* __restrict__ cidx)
{
    extern __shared__ char smem[];
    uint32_t sb = smem_u32(smem);
    float*    k2h  = (float*)(smem + SO_K2);
    unsigned* smax = (unsigned*)(smem + SO_SMAX);

    int tid  = threadIdx.x;
    int lane = tid & 31, wid = tid >> 5;
    int tok0 = blockIdx.x * TOKS;
    int keybase = blockIdx.y * (NKEYS / KSPLIT);
    int mbase = (wid >> 1) * 32;
    int nhalf = (wid & 1) * 64;

    if (tid < TOKS) smax[tid] = fenc(-1e30f);

    // prologue: A tile (128 x 256B) + B tile 0, swizzled rows
    {
        const char* abase = (const char*)(qf + (size_t)tok0 * DKD);
        const char* bbase = (const char*)(kf + (size_t)keybase * DKD);
        for (int i = tid; i < 2048; i += 256) {
            int row = i >> 4, c16 = i & 15;
            int colb = c16 * 16;
            uint32_t sw = (uint32_t)(colb ^ ((row & 7) << 4));
            CP_ASYNC16(sb + SO_A + row * 256 + sw, abase + row * 256 + colb);
            CP_ASYNC16(sb + SO_B0 + row * 256 + sw, bbase + row * 256 + colb);
        }
        CP_COMMIT();
    }

    float acc[2][8][4];

    for (int t = 0; t < NT_TILES; t++) {
        int key0 = keybase + t * KEYT;

        if (t + 1 < NT_TILES) {
            uint32_t nb = ((t + 1) & 1) ? SO_B1 : SO_B0;
            const char* bbase = (const char*)(kf + (size_t)(key0 + KEYT) * DKD);
            for (int i = tid; i < 2048; i += 256) {
                int row = i >> 4, c16 = i & 15;
                int colb = c16 * 16;
                uint32_t sw = (uint32_t)(colb ^ ((row & 7) << 4));
                CP_ASYNC16(sb + nb + row * 256 + sw, bbase + row * 256 + colb);
            }
            CP_COMMIT();
            CP_WAIT(1);
        } else {
            CP_WAIT(0);
        }
        __syncthreads();

        if (tid < KEYT) k2h[tid] = 0.5f * k2buf[key0 + tid];

        #pragma unroll
        for (int mt = 0; mt < 2; mt++)
            #pragma unroll
            for (int nt = 0; nt < 8; nt++)
                #pragma unroll
                for (int e = 0; e < 4; e++) acc[mt][nt][e] = 0.f;

        uint32_t bbuf = sb + ((t & 1) ? SO_B1 : SO_B0);
        #pragma unroll
        for (int kk = 0; kk < 8; kk++) {
            uint32_t a[2][4];
            #pragma unroll
            for (int mt = 0; mt < 2; mt++) {
                int row = mbase + mt * 16 + (lane & 15);
                int colb = kk * 32 + ((lane >> 4) << 4);
                uint32_t ad = sb + SO_A + row * 256 + (uint32_t)(colb ^ ((row & 7) << 4));
                LDSM_X4(a[mt][0], a[mt][1], a[mt][2], a[mt][3], ad);
            }
            uint32_t b[8][2];
            #pragma unroll
            for (int bt = 0; bt < 4; bt++) {
                int n = nhalf + bt * 16 + (lane & 7) + ((lane >> 4) << 3);
                int colb = kk * 32 + ((lane & 8) << 1);
                uint32_t bd = bbuf + n * 256 + (uint32_t)(colb ^ ((n & 7) << 4));
                LDSM_X4(b[bt * 2][0], b[bt * 2][1], b[bt * 2 + 1][0], b[bt * 2 + 1][1], bd);
            }
            #pragma unroll
            for (int mt = 0; mt < 2; mt++)
                #pragma unroll
                for (int nt = 0; nt < 8; nt++)
                    MMA16832F8(acc[mt][nt], a[mt], b[nt]);
        }
        __syncthreads();

        // epilogue: scores, running max, selection
        {
            float rm[2][2];
            #pragma unroll
            for (int mt = 0; mt < 2; mt++) { rm[mt][0] = -1e30f; rm[mt][1] = -1e30f; }
            #pragma unroll
            for (int mt = 0; mt < 2; mt++) {
                #pragma unroll
                for (int nt = 0; nt < 8; nt++) {
                    float kc0 = k2h[nhalf + nt * 8 + 2 * (lane & 3)];
                    float kc1 = k2h[nhalf + nt * 8 + 2 * (lane & 3) + 1];
                    acc[mt][nt][0] -= kc0; acc[mt][nt][1] -= kc1;
                    acc[mt][nt][2] -= kc0; acc[mt][nt][3] -= kc1;
                    rm[mt][0] = fmaxf(rm[mt][0], fmaxf(acc[mt][nt][0], acc[mt][nt][1]));
                    rm[mt][1] = fmaxf(rm[mt][1], fmaxf(acc[mt][nt][2], acc[mt][nt][3]));
                }
            }
            #pragma unroll
            for (int mt = 0; mt < 2; mt++) {
                #pragma unroll
                for (int e = 0; e < 2; e++) {
                    float v = rm[mt][e];
                    v = fmaxf(v, __shfl_xor_sync(0xffffffffu, v, 1));
                    v = fmaxf(v, __shfl_xor_sync(0xffffffffu, v, 2));
                    rm[mt][e] = v;
                }
            }
            if ((lane & 3) == 0) {
                #pragma unroll
                for (int mt = 0; mt < 2; mt++) {
                    int r = mbase + mt * 16 + (lane >> 2);
                    atomicMax(&smax[r], fenc(rm[mt][0]));
                    atomicMax(&smax[r + 8], fenc(rm[mt][1]));
                }
            }
            __syncthreads();
            #pragma unroll
            for (int mt = 0; mt < 2; mt++) {
                int r0 = mbase + mt * 16 + (lane >> 2);
                float th0 = fdec(smax[r0]) - DELTA_S;
                float th1 = fdec(smax[r0 + 8]) - DELTA_S;
                int tokA = tok0 + r0, tokB = tokA + 8;
                #pragma unroll
                for (int nt = 0; nt < 8; nt++) {
                    int keyc = key0 + nhalf + nt * 8 + 2 * (lane & 3);
                    if (acc[mt][nt][0] > th0) {
                        int pos = atomicAdd(&cnt[tokA], 1);
                        if (pos < CAP) cidx[(size_t)tokA * CAP + pos] = keyc;
                    }
                    if (acc[mt][nt][1] > th0) {
                        int pos = atomicAdd(&cnt[tokA], 1);
                        if (pos < CAP) cidx[(size_t)tokA * CAP + pos] = keyc + 1;
                    }
                    if (acc[mt][nt][2] > th1) {
                        int pos = atomicAdd(&cnt[tokB], 1);
                        if (pos < CAP) cidx[(size_t)tokB * CAP + pos] = keyc;
                    }
                    if (acc[mt][nt][3] > th1) {
                        int pos = atomicAdd(&cnt[tokB], 1);
                        if (pos < CAP) cidx[(size_t)tokB * CAP + pos] = keyc + 1;
                    }
                }
            }
            __syncthreads();
        }
    }
}

// ---------------- exact rescore + 8-round recursion + gather (emits split bf16) ----
__global__ void recurse_kernel(const float* __restrict__ keys, const float* __restrict__ vals,
                               const float* __restrict__ qbuf, const float* __restrict__ q2buf,
                               const float* __restrict__ k2buf, const int* __restrict__ cnt,
                               const int* __restrict__ cidx,
                               __nv_bfloat16* __restrict__ ah, __nv_bfloat16* __restrict__ al) {
    __shared__ float    qrow[DKD];
    __shared__ float    lg_all[CAP];
    __shared__ int      keep_idx[MAXKEEP];
    __shared__ float    keep_lg[MAXKEEP];
    __shared__ float    wmat[KN][MAXKEEP];
    __shared__ unsigned s_maxenc;
    __shared__ int      s_nkeep;

    int tok = blockIdx.x, tid = threadIdx.x;
    int lane = tid & 31, wid = tid >> 5;
    int n = min(cnt[tok], CAP);

    qrow[tid] = qbuf[(size_t)tok * DKD + tid];
    if (tid == 0) { s_maxenc = fenc(-1e30f); s_nkeep = 0; }
    __syncthreads();

    float q2 = q2buf[tok];
    for (int c = wid; c < n; c += 8) {
        int ki = cidx[(size_t)tok * CAP + c];
        const float* kp = keys + (size_t)ki * DKD;
        float p = 0.f;
        #pragma unroll
        for (int e = 0; e < 8; e++) { int d = lane + e * 32; p = fmaf(qrow[d], kp[d], p); }
        #pragma unroll
        for (int o = 16; o; o >>= 1) p += __shfl_xor_sync(0xffffffffu, p, o);
        if (lane == 0) {
            float lg = -(q2 - 2.0f * p + k2buf[ki]) / 0.1f;
            lg_all[c] = lg;
            atomicMax(&s_maxenc, fenc(lg));
        }
    }
    __syncthreads();
    float cut = fdec(s_maxenc) - CUT_LG;
    for (int c = tid; c < n; c += 256) {
        if (lg_all[c] >= cut) {
            int pos = atomicAdd(&s_nkeep, 1);
            if (pos < MAXKEEP) {
                keep_idx[pos] = cidx[(size_t)tok * CAP + c];
                keep_lg[pos]  = lg_all[c];
            }
        }
    }
    __syncthreads();
    int nk = min(s_nkeep, MAXKEEP);
    // parallel rank sort by key index (indices unique -> deterministic)
    {
        int my = 0, rank = -1; float mylg = 0.f;
        if (tid < nk) {
            my = keep_idx[tid]; mylg = keep_lg[tid];
            rank = 0;
            for (int c = 0; c < nk; c++) rank += (keep_idx[c] < my);
        }
        __syncthreads();
        if (tid < nk) { keep_idx[rank] = my; keep_lg[rank] = mylg; }
        __syncthreads();
    }
    if (wid == 0) {
        for (int k = 0; k < KN; k++) {
            float lm = -1e30f;
            for (int c = lane; c < nk; c += 32) lm = fmaxf(lm, keep_lg[c]);
            #pragma unroll
            for (int o = 16; o; o >>= 1) lm = fmaxf(lm, __shfl_xor_sync(0xffffffffu, lm, o));
            float zs = 0.f;
            for (int c = lane; c < nk; c += 32) {
                float p = expf(keep_lg[c] - lm);
                wmat[k][c] = p;
                zs += p;
            }
            #pragma unroll
            for (int o = 16; o; o >>= 1) zs += __shfl_xor_sync(0xffffffffu, zs, o);
            float inv = 1.0f / zs;
            for (int c = lane; c < nk; c += 32) {
                float w = wmat[k][c] * inv;
                wmat[k][c] = w;
                keep_lg[c] += log1pf(-w + 1e-6f);
            }
            __syncwarp();
        }
    }
    __syncthreads();
    float a[KN] = {};
    for (int c = 0; c < nk; c++) {
        float v = vals[(size_t)keep_idx[c] * DM + tid];
        #pragma unroll
        for (int k = 0; k < KN; k++) a[k] = fmaf(wmat[k][c], v, a[k]);
    }
    #pragma unroll
    for (int k = 0; k < KN; k++) {
        float v = a[k];
        __nv_bfloat16 h = __float2bfloat16_rn(v);
        float lo = v - __bfloat162float(h);
        size_t off = (size_t)tok * FF + k * DM + tid;
        ah[off] = h;
        al[off] = __float2bfloat16_rn(lo);
    }
}

// ---------------- W_out GEMM: split-bf16 tensor cores, single buffer, 2 CTA/SM ----
#define WO_AH0 0
#define WO_AL0 16384
#define WO_BH0 32768
#define WO_BL0 49152
#define WO_BIAS 65536
#define SMEM_WOUT 66048

__global__ void __launch_bounds__(256, 2) wout_mma_kernel(
    const __nv_bfloat16* __restrict__ ah, const __nv_bfloat16* __restrict__ al,
    const __nv_bfloat16* __restrict__ bh, const __nv_bfloat16* __restrict__ bl,
    const float* __restrict__ bias, float* __restrict__ C)
{
    extern __shared__ char smem[];
    uint32_t sb = smem_u32(smem);
    float* biash = (float*)(smem + WO_BIAS);

    int tid  = threadIdx.x;
    int lane = tid & 31, wid = tid >> 5;
    int m0 = blockIdx.x * 128, n0 = blockIdx.y * 128;
    int mbase = (wid >> 1) * 32;
    int nhalf = (wid & 1) * 64;

    if (tid < 128) biash[tid] = bias[n0 + tid];

    auto load_tile = [&](uint32_t dst, const __nv_bfloat16* src, int row0, int k0) {
        const char* base = (const char*)(src + (size_t)row0 * FF + k0);
        for (int i = tid; i < 1024; i += 256) {
            int row = i >> 3, c16 = i & 7;
            int colb = c16 * 16;
            uint32_t sw = (uint32_t)(colb ^ ((row & 7) << 4));
            CP_ASYNC16(sb + dst + row * 128 + sw, base + (size_t)row * (FF * 2) + colb);
        }
    };

    float acc[2][8][4] = {};

    const int NCH = FF / 64;   // 32
    for (int j = 0; j < NCH; j++) {
        int k0 = j * 64;
        load_tile(WO_AH0, ah, m0, k0);
        load_tile(WO_AL0, al, m0, k0);
        load_tile(WO_BH0, bh, n0, k0);
        load_tile(WO_BL0, bl, n0, k0);
        CP_COMMIT();
        CP_WAIT(0);
        __syncthreads();

        #pragma unroll
        for (int kk = 0; kk < 4; kk++) {
            uint32_t afh[2][4], afl[2][4];
            #pragma unroll
            for (int mt = 0; mt < 2; mt++) {
                int row = mbase + mt * 16 + (lane & 15);
                int colb = kk * 32 + ((lane >> 4) << 4);
                uint32_t sw = (uint32_t)(colb ^ ((row & 7) << 4));
                LDSM_X4(afh[mt][0], afh[mt][1], afh[mt][2], afh[mt][3],
                        sb + WO_AH0 + row * 128 + sw);
                LDSM_X4(afl[mt][0], afl[mt][1], afl[mt][2], afl[mt][3],
                        sb + WO_AL0 + row * 128 + sw);
            }
            uint32_t bfh[8][2], bfl[8][2];
            #pragma unroll
            for (int bt = 0; bt < 4; bt++) {
                int nrow = nhalf + bt * 16 + (lane & 7) + ((lane >> 4) << 3);
                int colb = kk * 32 + ((lane & 8) << 1);
                uint32_t sw = (uint32_t)(colb ^ ((nrow & 7) << 4));
                LDSM_X4(bfh[bt * 2][0], bfh[bt * 2][1], bfh[bt * 2 + 1][0], bfh[bt * 2 + 1][1],
                        sb + WO_BH0 + nrow * 128 + sw);
                LDSM_X4(bfl[bt * 2][0], bfl[bt * 2][1], bfl[bt * 2 + 1][0], bfl[bt * 2 + 1][1],
                        sb + WO_BL0 + nrow * 128 + sw);
            }
            #pragma unroll
            for (int mt = 0; mt < 2; mt++)
                #pragma unroll
                for (int nt = 0; nt < 8; nt++) {
                    MMA16816(acc[mt][nt], afh[mt], bfh[nt]);
                    MMA16816(acc[mt][nt], afh[mt], bfl[nt]);
                    MMA16816(acc[mt][nt], afl[mt], bfh[nt]);
                }
        }
        __syncthreads();
    }

    #pragma unroll
    for (int mt = 0; mt < 2; mt++) {
        int r0 = m0 + mbase + mt * 16 + (lane >> 2);
        #pragma unroll
        for (int nt = 0; nt < 8; nt++) {
            int cl = nhalf + nt * 8 + 2 * (lane & 3);
            float b0 = biash[cl], b1 = biash[cl + 1];
            float2 v0 = make_float2(acc[mt][nt][0] + b0, acc[mt][nt][1] + b1);
            float2 v1 = make_float2(acc[mt][nt][2] + b0, acc[mt][nt][3] + b1);
            *(float2*)&C[(size_t)r0 * D + n0 + cl] = v0;
            *(float2*)&C[(size_t)(r0 + 8) * D + n0 + cl] = v1;
        }
    }
}

// ---------------- RMSNorm (in place on d_out) ----------------
__global__ void rmsnorm_kernel(float* __restrict__ out, const float* __restrict__ rms_w) {
    __shared__ float wsum[8];
    __shared__ float s_tot;
    int tok = blockIdx.x, tid = threadIdx.x;
    float* row = out + (size_t)tok * D;
    float v[4];
    float ss = 0.f;
    #pragma unroll
    for (int e = 0; e < 4; e++) { v[e] = row[tid + e * 256]; ss = fmaf(v[e], v[e], ss); }
    #pragma unroll
    for (int o = 16; o; o >>= 1) ss += __shfl_xor_sync(0xffffffffu, ss, o);
    if ((tid & 31) == 0) wsum[tid >> 5] = ss;
    __syncthreads();
    if (tid == 0) {
        float t = 0.f;
        #pragma unroll
        for (int w = 0; w < 8; w++) t += wsum[w];
        s_tot = t;
    }
    __syncthreads();
    float var = s_tot / (float)D;
    float rs = 1.0f / sqrtf(var + 1e-6f);
    #pragma unroll
    for (int e = 0; e < 4; e++) {
        int d = tid + e * 256;
        row[d] = rms_w[d] * (v[e] * rs);
    }
}

// ---------------- host launch ----------------
extern "C" void kernel_launch(void* const* d_in, const int* in_sizes, int n_in,
                              void* d_out, int out_size) {
    const float* x     = (const float*)d_in[0];
    const float* keys  = (const float*)d_in[1];
    const float* vals  = (const float*)d_in[2];
    const float* W_in  = (const float*)d_in[3];
    const float* b_in  = (const float*)d_in[4];
    const float* W_out = (const float*)d_in[5];
    const float* b_out = (const float*)d_in[6];
    const float* rms_w = (const float*)d_in[7];
    float* out = (float*)d_out;
    (void)in_sizes; (void)n_in; (void)out_size;

    float *qp, *q2p, *k2p;
    int *cntp, *cidxp;
    unsigned char *kfp, *qfp;
    __nv_bfloat16 *ahp, *alp, *whp, *wlp;
    cudaGetSymbolAddress((void**)&qp,    g_q);
    cudaGetSymbolAddress((void**)&q2p,   g_q2);
    cudaGetSymbolAddress((void**)&k2p,   g_k2);
    cudaGetSymbolAddress((void**)&cntp,  g_cnt);
    cudaGetSymbolAddress((void**)&cidxp, g_cidx);
    cudaGetSymbolAddress((void**)&kfp,   g_keys_f8);
    cudaGetSymbolAddress((void**)&qfp,   g_q_f8);
    cudaGetSymbolAddress((void**)&ahp,   g_ah);
    cudaGetSymbolAddress((void**)&alp,   g_al);
    cudaGetSymbolAddress((void**)&whp,   g_wh);
    cudaGetSymbolAddress((void**)&wlp,   g_wl);

    static int smem_set = 0;
    if (!smem_set) {
        cudaFuncSetAttribute(scan_mma_kernel, cudaFuncAttributeMaxDynamicSharedMemorySize, SMEM_SCAN);
        cudaFuncSetAttribute(wout_mma_kernel, cudaFuncAttributeMaxDynamicSharedMemorySize, SMEM_WOUT);
        smem_set = 1;
    }

    // 1. reset candidate counters
    init_cnt_kernel<<<(R + 255) / 256, 256>>>(cntp);
    // 2. keys: k2 + fp8 convert (fused); W_out -> split bf16
    prep_fp8_kernel<<<NKEYS / 8, 256>>>(keys, kfp, k2p);
    cvt_split_kernel<<<(D * FF / 4 + 255) / 256, 256>>>(W_out, whp, wlp, D * FF / 4);
    // 3. q = x @ W_in^T + b_in (fp32, feeds exact rescore)
    gemm_tn_kernel<<<dim3(R / 64, DKD / 64), 256>>>(x, W_in, b_in, qp, R, DKD, D);
    // 4. q: q2 + fp8 convert (fused)
    prep_fp8_kernel<<<R / 8, 256>>>(qp, qfp, q2p);
    // 5. fp8 tensor-core qk scan + candidate selection
    scan_mma_kernel<<<dim3(R / TOKS, KSPLIT), 256, SMEM_SCAN>>>(qfp, kfp, k2p, cntp, cidxp);
    // 6. exact rescore + 8-round recursion + gather -> split-bf16 nearest
    recurse_kernel<<<R, 256>>>(keys, vals, qp, q2p, k2p, cntp, cidxp, ahp, alp);
    // 7. out = nearest @ W_out^T + b_out (split-bf16 tensor cores, 2 CTA/SM)
    wout_mma_kernel<<<dim3(R / 128, D / 128), 256, SMEM_WOUT>>>(ahp, alp, whp, wlp, b_out, out);
    // 8. RMSNorm * rms_w, in place
    rmsnorm_kernel<<<R, 256>>>(out, rms_w);
}

// round 7
// speedup vs baseline: 4.6609x; 1.1501x over previous
#include <cuda_runtime.h>
#include <cuda_bf16.h>
#include <cuda_fp16.h>
#include <cuda_fp8.h>
#include <math.h>
#include <stdint.h>

// Problem constants
#define R      4096      // B*T
#define D      1024
#define DKD    256       // DK
#define NKEYS  32768
#define DM     256
#define KN     8         // K_NEIGHBORS
#define FF     (KN*DM)   // 2048
#define CAP    1024
#define MAXKEEP 64
#define CUT_LG  131.0f
#define DELTA_S 14.0f    // fp8 scan: widened pre-filter threshold

// tensor scan tiling
#define TOKS   128
#define KEYT   128
#define KSPLIT 8
#define NT_TILES ((NKEYS / KSPLIT) / KEYT)   // 32

// ---------------- scratch (static device globals; no allocation) ----------------
__device__ __align__(16) float g_q[R * DKD];
__device__ __align__(16) float g_q2[R];
__device__ __align__(16) float g_k2[NKEYS];
__device__ __align__(16) int   g_cidx[(size_t)R * CAP];
__device__ __align__(16) int   g_cnt[R];
__device__ __align__(16) unsigned char g_keys_f8[(size_t)NKEYS * DKD];
__device__ __align__(16) unsigned char g_q_f8[(size_t)R * DKD];
// fp16 operands for the W_out GEMM
__device__ __align__(16) __half g_a16[(size_t)R * FF];
__device__ __align__(16) __half g_w16[(size_t)D * FF];

// ---------------- PTX helpers ----------------
__device__ __forceinline__ uint32_t smem_u32(const void* p) {
    uint32_t a;
    asm("{ .reg .u64 t; cvta.to.shared.u64 t, %1; cvt.u32.u64 %0, t; }" : "=r"(a) : "l"(p));
    return a;
}
#define CP_ASYNC16(dst, src) \
    asm volatile("cp.async.cg.shared.global [%0], [%1], 16;" \
                 :: "r"((uint32_t)(dst)), "l"(__cvta_generic_to_global(src)) : "memory")
#define CP_COMMIT()    asm volatile("cp.async.commit_group;" ::: "memory")
#define CP_WAIT(n)     asm volatile("cp.async.wait_group %0;" :: "n"(n) : "memory")

#define LDSM_X4(r0, r1, r2, r3, addr) \
    asm volatile("ldmatrix.sync.aligned.m8n8.x4.shared.b16 {%0,%1,%2,%3}, [%4];" \
                 : "=r"(r0), "=r"(r1), "=r"(r2), "=r"(r3) : "r"(addr))

#define MMA16816H(d, a, b) \
    asm volatile("mma.sync.aligned.m16n8k16.row.col.f32.f16.f16.f32 " \
                 "{%0,%1,%2,%3}, {%4,%5,%6,%7}, {%8,%9}, {%0,%1,%2,%3};" \
                 : "+f"((d)[0]), "+f"((d)[1]), "+f"((d)[2]), "+f"((d)[3]) \
                 : "r"((a)[0]), "r"((a)[1]), "r"((a)[2]), "r"((a)[3]), \
                   "r"((b)[0]), "r"((b)[1]))

#define MMA16832F8(d, a, b) \
    asm volatile("mma.sync.aligned.m16n8k32.row.col.f32.e4m3.e4m3.f32 " \
                 "{%0,%1,%2,%3}, {%4,%5,%6,%7}, {%8,%9}, {%0,%1,%2,%3};" \
                 : "+f"((d)[0]), "+f"((d)[1]), "+f"((d)[2]), "+f"((d)[3]) \
                 : "r"((a)[0]), "r"((a)[1]), "r"((a)[2]), "r"((a)[3]), \
                   "r"((b)[0]), "r"((b)[1]))

// ordered-float encoding for unsigned atomicMax
__device__ __forceinline__ unsigned fenc(float f) {
    unsigned u = __float_as_uint(f);
    return (u & 0x80000000u) ? ~u : (u | 0x80000000u);
}
__device__ __forceinline__ float fdec(unsigned e) {
    return __uint_as_float((e & 0x80000000u) ? (e & 0x7fffffffu) : ~e);
}

// ---------------- init: zero candidate counters ----------------
__global__ void init_cnt_kernel(int* __restrict__ cnt) {
    int i = blockIdx.x * blockDim.x + threadIdx.x;
    if (i < R) cnt[i] = 0;
}

// ---------------- fused: row sum-of-squares + fp32 -> e4m3 convert (256 cols) ----
__global__ void prep_fp8_kernel(const float* __restrict__ src, unsigned char* __restrict__ dst,
                                float* __restrict__ sumsq) {
    int row  = blockIdx.x * 8 + (threadIdx.x >> 5);
    int lane = threadIdx.x & 31;
    const float4* p = (const float4*)(src + (size_t)row * DKD);
    float4 v0 = p[lane * 2], v1 = p[lane * 2 + 1];
    float s = v0.x * v0.x;
    s = fmaf(v0.y, v0.y, s); s = fmaf(v0.z, v0.z, s); s = fmaf(v0.w, v0.w, s);
    s = fmaf(v1.x, v1.x, s); s = fmaf(v1.y, v1.y, s);
    s = fmaf(v1.z, v1.z, s); s = fmaf(v1.w, v1.w, s);
    #pragma unroll
    for (int o = 16; o; o >>= 1) s += __shfl_xor_sync(0xffffffffu, s, o);
    if (lane == 0) sumsq[row] = s;
    uint32_t p0 = __nv_cvt_float2_to_fp8x2(make_float2(v0.x, v0.y), __NV_SATFINITE, __NV_E4M3);
    uint32_t p1 = __nv_cvt_float2_to_fp8x2(make_float2(v0.z, v0.w), __NV_SATFINITE, __NV_E4M3);
    uint32_t p2 = __nv_cvt_float2_to_fp8x2(make_float2(v1.x, v1.y), __NV_SATFINITE, __NV_E4M3);
    uint32_t p3 = __nv_cvt_float2_to_fp8x2(make_float2(v1.z, v1.w), __NV_SATFINITE, __NV_E4M3);
    uint2 w;
    w.x = (p0 & 0xffffu) | (p1 << 16);
    w.y = (p2 & 0xffffu) | (p3 << 16);
    *(uint2*)(dst + (size_t)row * DKD + lane * 8) = w;
}

// ---------------- fp32 -> fp16 convert (vectorized) ----------------
__global__ void cvt_fp16_kernel(const float* __restrict__ src, __half* __restrict__ dst, int n4) {
    int i = blockIdx.x * blockDim.x + threadIdx.x;
    if (i < n4) {
        float4 v = ((const float4*)src)[i];
        __half2* d = (__half2*)dst;
        d[i * 2 + 0] = __floats2half2_rn(v.x, v.y);
        d[i * 2 + 1] = __floats2half2_rn(v.z, v.w);
    }
}

// ---------------- fp32 TN GEMM (q projection): register-prefetch double buffer ----
__global__ void gemm_tn_kernel(const float* __restrict__ A, const float* __restrict__ B,
                               const float* __restrict__ bias, float* __restrict__ C,
                               int M, int N, int K) {
    __shared__ float As[16][64];
    __shared__ float Bs[16][64];
    int m0 = blockIdx.x * 64, n0 = blockIdx.y * 64;
    int tid = threadIdx.x;
    int tx = tid & 15, ty = tid >> 4;
    int lr = tid >> 2;
    int lc = (tid & 3) * 4;
    float acc[4][4] = {};
    float4 av = *(const float4*)&A[(size_t)(m0 + lr) * K + lc];
    float4 bv = *(const float4*)&B[(size_t)(n0 + lr) * K + lc];
    for (int k0 = 0; k0 < K; k0 += 16) {
        As[lc + 0][lr] = av.x; As[lc + 1][lr] = av.y; As[lc + 2][lr] = av.z; As[lc + 3][lr] = av.w;
        Bs[lc + 0][lr] = bv.x; Bs[lc + 1][lr] = bv.y; Bs[lc + 2][lr] = bv.z; Bs[lc + 3][lr] = bv.w;
        __syncthreads();
        if (k0 + 16 < K) {
            av = *(const float4*)&A[(size_t)(m0 + lr) * K + k0 + 16 + lc];
            bv = *(const float4*)&B[(size_t)(n0 + lr) * K + k0 + 16 + lc];
        }
        #pragma unroll
        for (int kk = 0; kk < 16; kk++) {
            float4 a = *(const float4*)&As[kk][ty * 4];
            float4 b = *(const float4*)&Bs[kk][tx * 4];
            acc[0][0] = fmaf(a.x, b.x, acc[0][0]); acc[0][1] = fmaf(a.x, b.y, acc[0][1]);
            acc[0][2] = fmaf(a.x, b.z, acc[0][2]); acc[0][3] = fmaf(a.x, b.w, acc[0][3]);
            acc[1][0] = fmaf(a.y, b.x, acc[1][0]); acc[1][1] = fmaf(a.y, b.y, acc[1][1]);
            acc[1][2] = fmaf(a.y, b.z, acc[1][2]); acc[1][3] = fmaf(a.y, b.w, acc[1][3]);
            acc[2][0] = fmaf(a.z, b.x, acc[2][0]); acc[2][1] = fmaf(a.z, b.y, acc[2][1]);
            acc[2][2] = fmaf(a.z, b.z, acc[2][2]); acc[2][3] = fmaf(a.z, b.w, acc[2][3]);
            acc[3][0] = fmaf(a.w, b.x, acc[3][0]); acc[3][1] = fmaf(a.w, b.y, acc[3][1]);
            acc[3][2] = fmaf(a.w, b.z, acc[3][2]); acc[3][3] = fmaf(a.w, b.w, acc[3][3]);
        }
        __syncthreads();
    }
    #pragma unroll
    for (int i = 0; i < 4; i++) {
        #pragma unroll
        for (int j = 0; j < 4; j++) {
            int n = n0 + tx * 4 + j;
            C[(size_t)(m0 + ty * 4 + i) * N + n] = acc[i][j] + bias[n];
        }
    }
}

// ---------------- fp8 tensor scan: e4m3 mma.sync + threshold selection ----------------
#define SO_A    0
#define SO_B0   32768
#define SO_B1   65536
#define SO_K2   98304
#define SO_SMAX 98816
#define SMEM_SCAN 99328

__global__ void __launch_bounds__(256, 2) scan_mma_kernel(
    const unsigned char* __restrict__ qf, const unsigned char* __restrict__ kf,
    const float* __restrict__ k2buf, int* __restrict__ cnt, int* __restrict__ cidx)
{
    extern __shared__ char smem[];
    uint32_t sb = smem_u32(smem);
    float*    k2h  = (float*)(smem + SO_K2);
    unsigned* smax = (unsigned*)(smem + SO_SMAX);

    int tid  = threadIdx.x;
    int lane = tid & 31, wid = tid >> 5;
    int tok0 = blockIdx.x * TOKS;
    int keybase = blockIdx.y * (NKEYS / KSPLIT);
    int mbase = (wid >> 1) * 32;
    int nhalf = (wid & 1) * 64;

    if (tid < TOKS) smax[tid] = fenc(-1e30f);

    {
        const char* abase = (const char*)(qf + (size_t)tok0 * DKD);
        const char* bbase = (const char*)(kf + (size_t)keybase * DKD);
        for (int i = tid; i < 2048; i += 256) {
            int row = i >> 4, c16 = i & 15;
            int colb = c16 * 16;
            uint32_t sw = (uint32_t)(colb ^ ((row & 7) << 4));
            CP_ASYNC16(sb + SO_A + row * 256 + sw, abase + row * 256 + colb);
            CP_ASYNC16(sb + SO_B0 + row * 256 + sw, bbase + row * 256 + colb);
        }
        CP_COMMIT();
    }

    float acc[2][8][4];

    for (int t = 0; t < NT_TILES; t++) {
        int key0 = keybase + t * KEYT;

        if (t + 1 < NT_TILES) {
            uint32_t nb = ((t + 1) & 1) ? SO_B1 : SO_B0;
            const char* bbase = (const char*)(kf + (size_t)(key0 + KEYT) * DKD);
            for (int i = tid; i < 2048; i += 256) {
                int row = i >> 4, c16 = i & 15;
                int colb = c16 * 16;
                uint32_t sw = (uint32_t)(colb ^ ((row & 7) << 4));
                CP_ASYNC16(sb + nb + row * 256 + sw, bbase + row * 256 + colb);
            }
            CP_COMMIT();
            CP_WAIT(1);
        } else {
            CP_WAIT(0);
        }
        __syncthreads();

        if (tid < KEYT) k2h[tid] = 0.5f * k2buf[key0 + tid];

        #pragma unroll
        for (int mt = 0; mt < 2; mt++)
            #pragma unroll
            for (int nt = 0; nt < 8; nt++)
                #pragma unroll
                for (int e = 0; e < 4; e++) acc[mt][nt][e] = 0.f;

        uint32_t bbuf = sb + ((t & 1) ? SO_B1 : SO_B0);
        #pragma unroll
        for (int kk = 0; kk < 8; kk++) {
            uint32_t a[2][4];
            #pragma unroll
            for (int mt = 0; mt < 2; mt++) {
                int row = mbase + mt * 16 + (lane & 15);
                int colb = kk * 32 + ((lane >> 4) << 4);
                uint32_t ad = sb + SO_A + row * 256 + (uint32_t)(colb ^ ((row & 7) << 4));
                LDSM_X4(a[mt][0], a[mt][1], a[mt][2], a[mt][3], ad);
            }
            uint32_t b[8][2];
            #pragma unroll
            for (int bt = 0; bt < 4; bt++) {
                int n = nhalf + bt * 16 + (lane & 7) + ((lane >> 4) << 3);
                int colb = kk * 32 + ((lane & 8) << 1);
                uint32_t bd = bbuf + n * 256 + (uint32_t)(colb ^ ((n & 7) << 4));
                LDSM_X4(b[bt * 2][0], b[bt * 2][1], b[bt * 2 + 1][0], b[bt * 2 + 1][1], bd);
            }
            #pragma unroll
            for (int mt = 0; mt < 2; mt++)
                #pragma unroll
                for (int nt = 0; nt < 8; nt++)
                    MMA16832F8(acc[mt][nt], a[mt], b[nt]);
        }
        __syncthreads();

        // epilogue: scores, running max, selection
        {
            float rm[2][2];
            #pragma unroll
            for (int mt = 0; mt < 2; mt++) { rm[mt][0] = -1e30f; rm[mt][1] = -1e30f; }
            #pragma unroll
            for (int mt = 0; mt < 2; mt++) {
                #pragma unroll
                for (int nt = 0; nt < 8; nt++) {
                    float kc0 = k2h[nhalf + nt * 8 + 2 * (lane & 3)];
                    float kc1 = k2h[nhalf + nt * 8 + 2 * (lane & 3) + 1];
                    acc[mt][nt][0] -= kc0; acc[mt][nt][1] -= kc1;
                    acc[mt][nt][2] -= kc0; acc[mt][nt][3] -= kc1;
                    rm[mt][0] = fmaxf(rm[mt][0], fmaxf(acc[mt][nt][0], acc[mt][nt][1]));
                    rm[mt][1] = fmaxf(rm[mt][1], fmaxf(acc[mt][nt][2], acc[mt][nt][3]));
                }
            }
            #pragma unroll
            for (int mt = 0; mt < 2; mt++) {
                #pragma unroll
                for (int e = 0; e < 2; e++) {
                    float v = rm[mt][e];
                    v = fmaxf(v, __shfl_xor_sync(0xffffffffu, v, 1));
                    v = fmaxf(v, __shfl_xor_sync(0xffffffffu, v, 2));
                    rm[mt][e] = v;
                }
            }
            if ((lane & 3) == 0) {
                #pragma unroll
                for (int mt = 0; mt < 2; mt++) {
                    int r = mbase + mt * 16 + (lane >> 2);
                    atomicMax(&smax[r], fenc(rm[mt][0]));
                    atomicMax(&smax[r + 8], fenc(rm[mt][1]));
                }
            }
            __syncthreads();
            #pragma unroll
            for (int mt = 0; mt < 2; mt++) {
                int r0 = mbase + mt * 16 + (lane >> 2);
                float th0 = fdec(smax[r0]) - DELTA_S;
                float th1 = fdec(smax[r0 + 8]) - DELTA_S;
                int tokA = tok0 + r0, tokB = tokA + 8;
                #pragma unroll
                for (int nt = 0; nt < 8; nt++) {
                    int keyc = key0 + nhalf + nt * 8 + 2 * (lane & 3);
                    if (acc[mt][nt][0] > th0) {
                        int pos = atomicAdd(&cnt[tokA], 1);
                        if (pos < CAP) cidx[(size_t)tokA * CAP + pos] = keyc;
                    }
                    if (acc[mt][nt][1] > th0) {
                        int pos = atomicAdd(&cnt[tokA], 1);
                        if (pos < CAP) cidx[(size_t)tokA * CAP + pos] = keyc + 1;
                    }
                    if (acc[mt][nt][2] > th1) {
                        int pos = atomicAdd(&cnt[tokB], 1);
                        if (pos < CAP) cidx[(size_t)tokB * CAP + pos] = keyc;
                    }
                    if (acc[mt][nt][3] > th1) {
                        int pos = atomicAdd(&cnt[tokB], 1);
                        if (pos < CAP) cidx[(size_t)tokB * CAP + pos] = keyc + 1;
                    }
                }
            }
            __syncthreads();
        }
    }
}

// ---------------- exact rescore + 8-round recursion + gather (emits fp16) ----------
__global__ void recurse_kernel(const float* __restrict__ keys, const float* __restrict__ vals,
                               const float* __restrict__ qbuf, const float* __restrict__ q2buf,
                               const float* __restrict__ k2buf, const int* __restrict__ cnt,
                               const int* __restrict__ cidx,
                               __half* __restrict__ a16) {
    __shared__ float    qrow[DKD];
    __shared__ float    lg_all[CAP];
    __shared__ int      keep_idx[MAXKEEP];
    __shared__ float    keep_lg[MAXKEEP];
    __shared__ float    wmat[KN][MAXKEEP];
    __shared__ unsigned s_maxenc;
    __shared__ int      s_nkeep;

    int tok = blockIdx.x, tid = threadIdx.x;
    int lane = tid & 31, wid = tid >> 5;
    int n = min(cnt[tok], CAP);

    qrow[tid] = qbuf[(size_t)tok * DKD + tid];
    if (tid == 0) { s_maxenc = fenc(-1e30f); s_nkeep = 0; }
    __syncthreads();

    float q2 = q2buf[tok];
    // exact fp32 rescore, float4-vectorized key loads
    float4 q0 = *(const float4*)&qrow[lane * 4];
    float4 q1 = *(const float4*)&qrow[128 + lane * 4];
    for (int c = wid; c < n; c += 8) {
        int ki = cidx[(size_t)tok * CAP + c];
        const float4* kp = (const float4*)(keys + (size_t)ki * DKD);
        float4 k0 = kp[lane];
        float4 k1 = kp[lane + 32];
        float p = q0.x * k0.x;
        p = fmaf(q0.y, k0.y, p); p = fmaf(q0.z, k0.z, p); p = fmaf(q0.w, k0.w, p);
        p = fmaf(q1.x, k1.x, p); p = fmaf(q1.y, k1.y, p);
        p = fmaf(q1.z, k1.z, p); p = fmaf(q1.w, k1.w, p);
        #pragma unroll
        for (int o = 16; o; o >>= 1) p += __shfl_xor_sync(0xffffffffu, p, o);
        if (lane == 0) {
            float lg = -(q2 - 2.0f * p + k2buf[ki]) / 0.1f;
            lg_all[c] = lg;
            atomicMax(&s_maxenc, fenc(lg));
        }
    }
    __syncthreads();
    float cut = fdec(s_maxenc) - CUT_LG;
    for (int c = tid; c < n; c += 256) {
        if (lg_all[c] >= cut) {
            int pos = atomicAdd(&s_nkeep, 1);
            if (pos < MAXKEEP) {
                keep_idx[pos] = cidx[(size_t)tok * CAP + c];
                keep_lg[pos]  = lg_all[c];
            }
        }
    }
    __syncthreads();
    int nk = min(s_nkeep, MAXKEEP);
    // parallel rank sort by key index (indices unique -> deterministic)
    {
        int my = 0, rank = -1; float mylg = 0.f;
        if (tid < nk) {
            my = keep_idx[tid]; mylg = keep_lg[tid];
            rank = 0;
            for (int c = 0; c < nk; c++) rank += (keep_idx[c] < my);
        }
        __syncthreads();
        if (tid < nk) { keep_idx[rank] = my; keep_lg[rank] = mylg; }
        __syncthreads();
    }
    if (wid == 0) {
        for (int k = 0; k < KN; k++) {
            float lm = -1e30f;
            for (int c = lane; c < nk; c += 32) lm = fmaxf(lm, keep_lg[c]);
            #pragma unroll
            for (int o = 16; o; o >>= 1) lm = fmaxf(lm, __shfl_xor_sync(0xffffffffu, lm, o));
            float zs = 0.f;
            for (int c = lane; c < nk; c += 32) {
                float p = expf(keep_lg[c] - lm);
                wmat[k][c] = p;
                zs += p;
            }
            #pragma unroll
            for (int o = 16; o; o >>= 1) zs += __shfl_xor_sync(0xffffffffu, zs, o);
            float inv = 1.0f / zs;
            for (int c = lane; c < nk; c += 32) {
                float w = wmat[k][c] * inv;
                wmat[k][c] = w;
                keep_lg[c] += log1pf(-w + 1e-6f);
            }
            __syncwarp();
        }
    }
    __syncthreads();
    float a[KN] = {};
    for (int c = 0; c < nk; c++) {
        float v = vals[(size_t)keep_idx[c] * DM + tid];
        #pragma unroll
        for (int k = 0; k < KN; k++) a[k] = fmaf(wmat[k][c], v, a[k]);
    }
    #pragma unroll
    for (int k = 0; k < KN; k++)
        a16[(size_t)tok * FF + k * DM + tid] = __float2half_rn(a[k]);
}

// ---------------- W_out GEMM: fp16 tensor cores, double buffer, 2 CTA/SM ----------
#define WO_A    0
#define WO_B    16384
#define WO_BUF  32768
#define WO_BIAS 65536
#define SMEM_WOUT 66048

__global__ void __launch_bounds__(256, 2) wout_mma_kernel(
    const __half* __restrict__ a16, const __half* __restrict__ w16,
    const float* __restrict__ bias, float* __restrict__ C)
{
    extern __shared__ char smem[];
    uint32_t sb = smem_u32(smem);
    float* biash = (float*)(smem + WO_BIAS);

    int tid  = threadIdx.x;
    int lane = tid & 31, wid = tid >> 5;
    int m0 = blockIdx.x * 128, n0 = blockIdx.y * 128;
    int mbase = (wid >> 1) * 32;
    int nhalf = (wid & 1) * 64;

    if (tid < 128) biash[tid] = bias[n0 + tid];

    auto load_tile = [&](uint32_t dst, const __half* src, int row0, int k0) {
        const char* base = (const char*)(src + (size_t)row0 * FF + k0);
        for (int i = tid; i < 1024; i += 256) {
            int row = i >> 3, c16 = i & 7;
            int colb = c16 * 16;
            uint32_t sw = (uint32_t)(colb ^ ((row & 7) << 4));
            CP_ASYNC16(sb + dst + row * 128 + sw, base + (size_t)row * (FF * 2) + colb);
        }
    };

    // prologue: chunk 0
    load_tile(WO_A, a16, m0, 0);
    load_tile(WO_B, w16, n0, 0);
    CP_COMMIT();

    float acc[2][8][4] = {};

    const int NCH = FF / 64;   // 32
    for (int j = 0; j < NCH; j++) {
        uint32_t buf = (j & 1) ? WO_BUF : 0;
        if (j + 1 < NCH) {
            uint32_t nb = ((j + 1) & 1) ? WO_BUF : 0;
            int k0 = (j + 1) * 64;
            load_tile(nb + WO_A, a16, m0, k0);
            load_tile(nb + WO_B, w16, n0, k0);
            CP_COMMIT();
            CP_WAIT(1);
        } else {
            CP_WAIT(0);
        }
        __syncthreads();

        #pragma unroll
        for (int kk = 0; kk < 4; kk++) {
            uint32_t af[2][4];
            #pragma unroll
            for (int mt = 0; mt < 2; mt++) {
                int row = mbase + mt * 16 + (lane & 15);
                int colb = kk * 32 + ((lane >> 4) << 4);
                uint32_t sw = (uint32_t)(colb ^ ((row & 7) << 4));
                LDSM_X4(af[mt][0], af[mt][1], af[mt][2], af[mt][3],
                        sb + buf + WO_A + row * 128 + sw);
            }
            uint32_t bf[8][2];
            #pragma unroll
            for (int bt = 0; bt < 4; bt++) {
                int nrow = nhalf + bt * 16 + (lane & 7) + ((lane >> 4) << 3);
                int colb = kk * 32 + ((lane & 8) << 1);
                uint32_t sw = (uint32_t)(colb ^ ((nrow & 7) << 4));
                LDSM_X4(bf[bt * 2][0], bf[bt * 2][1], bf[bt * 2 + 1][0], bf[bt * 2 + 1][1],
                        sb + buf + WO_B + nrow * 128 + sw);
            }
            #pragma unroll
            for (int mt = 0; mt < 2; mt++)
                #pragma unroll
                for (int nt = 0; nt < 8; nt++)
                    MMA16816H(acc[mt][nt], af[mt], bf[nt]);
        }
        __syncthreads();
    }

    #pragma unroll
    for (int mt = 0; mt < 2; mt++) {
        int r0 = m0 + mbase + mt * 16 + (lane >> 2);
        #pragma unroll
        for (int nt = 0; nt < 8; nt++) {
            int cl = nhalf + nt * 8 + 2 * (lane & 3);
            float b0 = biash[cl], b1 = biash[cl + 1];
            float2 v0 = make_float2(acc[mt][nt][0] + b0, acc[mt][nt][1] + b1);
            float2 v1 = make_float2(acc[mt][nt][2] + b0, acc[mt][nt][3] + b1);
            *(float2*)&C[(size_t)r0 * D + n0 + cl] = v0;
            *(float2*)&C[(size_t)(r0 + 8) * D + n0 + cl] = v1;
        }
    }
}

// ---------------- RMSNorm (in place on d_out) ----------------
__global__ void rmsnorm_kernel(float* __restrict__ out, const float* __restrict__ rms_w) {
    __shared__ float wsum[8];
    __shared__ float s_tot;
    int tok = blockIdx.x, tid = threadIdx.x;
    float* row = out + (size_t)tok * D;
    float v[4];
    float ss = 0.f;
    #pragma unroll
    for (int e = 0; e < 4; e++) { v[e] = row[tid + e * 256]; ss = fmaf(v[e], v[e], ss); }
    #pragma unroll
    for (int o = 16; o; o >>= 1) ss += __shfl_xor_sync(0xffffffffu, ss, o);
    if ((tid & 31) == 0) wsum[tid >> 5] = ss;
    __syncthreads();
    if (tid == 0) {
        float t = 0.f;
        #pragma unroll
        for (int w = 0; w < 8; w++) t += wsum[w];
        s_tot = t;
    }
    __syncthreads();
    float var = s_tot / (float)D;
    float rs = 1.0f / sqrtf(var + 1e-6f);
    #pragma unroll
    for (int e = 0; e < 4; e++) {
        int d = tid + e * 256;
        row[d] = rms_w[d] * (v[e] * rs);
    }
}

// ---------------- host launch ----------------
extern "C" void kernel_launch(void* const* d_in, const int* in_sizes, int n_in,
                              void* d_out, int out_size) {
    const float* x     = (const float*)d_in[0];
    const float* keys  = (const float*)d_in[1];
    const float* vals  = (const float*)d_in[2];
    const float* W_in  = (const float*)d_in[3];
    const float* b_in  = (const float*)d_in[4];
    const float* W_out = (const float*)d_in[5];
    const float* b_out = (const float*)d_in[6];
    const float* rms_w = (const float*)d_in[7];
    float* out = (float*)d_out;
    (void)in_sizes; (void)n_in; (void)out_size;

    float *qp, *q2p, *k2p;
    int *cntp, *cidxp;
    unsigned char *kfp, *qfp;
    __half *a16p, *w16p;
    cudaGetSymbolAddress((void**)&qp,    g_q);
    cudaGetSymbolAddress((void**)&q2p,   g_q2);
    cudaGetSymbolAddress((void**)&k2p,   g_k2);
    cudaGetSymbolAddress((void**)&cntp,  g_cnt);
    cudaGetSymbolAddress((void**)&cidxp, g_cidx);
    cudaGetSymbolAddress((void**)&kfp,   g_keys_f8);
    cudaGetSymbolAddress((void**)&qfp,   g_q_f8);
    cudaGetSymbolAddress((void**)&a16p,  g_a16);
    cudaGetSymbolAddress((void**)&w16p,  g_w16);

    static int smem_set = 0;
    if (!smem_set) {
        cudaFuncSetAttribute(scan_mma_kernel, cudaFuncAttributeMaxDynamicSharedMemorySize, SMEM_SCAN);
        cudaFuncSetAttribute(wout_mma_kernel, cudaFuncAttributeMaxDynamicSharedMemorySize, SMEM_WOUT);
        smem_set = 1;
    }

    // 1. reset candidate counters
    init_cnt_kernel<<<(R + 255) / 256, 256>>>(cntp);
    // 2. keys: k2 + fp8 convert (fused); W_out -> fp16
    prep_fp8_kernel<<<NKEYS / 8, 256>>>(keys, kfp, k2p);
    cvt_fp16_kernel<<<(D * FF / 4 + 255) / 256, 256>>>(W_out, w16p, D * FF / 4);
    // 3. q = x @ W_in^T + b_in (fp32, feeds exact rescore)
    gemm_tn_kernel<<<dim3(R / 64, DKD / 64), 256>>>(x, W_in, b_in, qp, R, DKD, D);
    // 4. q: q2 + fp8 convert (fused)
    prep_fp8_kernel<<<R / 8, 256>>>(qp, qfp, q2p);
    // 5. fp8 tensor-core qk scan + candidate selection
    scan_mma_kernel<<<dim3(R / TOKS, KSPLIT), 256, SMEM_SCAN>>>(qfp, kfp, k2p, cntp, cidxp);
    // 6. exact rescore + 8-round recursion + gather -> fp16 nearest
    recurse_kernel<<<R, 256>>>(keys, vals, qp, q2p, k2p, cntp, cidxp, a16p);
    // 7. out = nearest @ W_out^T + b_out (fp16 tensor cores, single MMA stream)
    wout_mma_kernel<<<dim3(R / 128, D / 128), 256, SMEM_WOUT>>>(a16p, w16p, b_out, out);
    // 8. RMSNorm * rms_w, in place
    rmsnorm_kernel<<<R, 256>>>(out, rms_w);
}

// round 8
// speedup vs baseline: 5.1276x; 1.1001x over previous
#include <cuda_runtime.h>
#include <cuda_bf16.h>
#include <cuda_fp16.h>
#include <cuda_fp8.h>
#include <math.h>
#include <stdint.h>

// Problem constants
#define R      4096      // B*T
#define D      1024
#define DKD    256       // DK
#define NKEYS  32768
#define DM     256
#define KN     8         // K_NEIGHBORS
#define FF     (KN*DM)   // 2048
#define CAP    1024
#define MAXKEEP 64
#define CUT_LG  131.0f
#define DELTA_S 13.5f    // fp8 scan pre-filter threshold (6.55 exact + fp8 noise margin)

// tensor scan tiling
#define TOKS   128
#define KEYT   128
#define KSPLIT 8
#define NT_TILES ((NKEYS / KSPLIT) / KEYT)   // 32

// ---------------- scratch (static device globals; no allocation) ----------------
__device__ __align__(16) float g_q[R * DKD];
__device__ __align__(16) float g_q2[R];
__device__ __align__(16) float g_k2[NKEYS];
__device__ __align__(16) int   g_cidx[(size_t)R * CAP];
__device__ __align__(16) int   g_cnt[R];
__device__ __align__(16) unsigned char g_keys_f8[(size_t)NKEYS * DKD];
__device__ __align__(16) unsigned char g_q_f8[(size_t)R * DKD];
// fp16 operands for the W_out GEMM
__device__ __align__(16) __half g_a16[(size_t)R * FF];
__device__ __align__(16) __half g_w16[(size_t)D * FF];
// split-fp16 operands for the q projection GEMM
__device__ __align__(16) __half g_xh[(size_t)R * D];
__device__ __align__(16) __half g_xl[(size_t)R * D];
__device__ __align__(16) __half g_wih[(size_t)DKD * D];
__device__ __align__(16) __half g_wil[(size_t)DKD * D];

// ---------------- PTX helpers ----------------
__device__ __forceinline__ uint32_t smem_u32(const void* p) {
    uint32_t a;
    asm("{ .reg .u64 t; cvta.to.shared.u64 t, %1; cvt.u32.u64 %0, t; }" : "=r"(a) : "l"(p));
    return a;
}
#define CP_ASYNC16(dst, src) \
    asm volatile("cp.async.cg.shared.global [%0], [%1], 16;" \
                 :: "r"((uint32_t)(dst)), "l"(__cvta_generic_to_global(src)) : "memory")
#define CP_COMMIT()    asm volatile("cp.async.commit_group;" ::: "memory")
#define CP_WAIT(n)     asm volatile("cp.async.wait_group %0;" :: "n"(n) : "memory")

#define LDSM_X4(r0, r1, r2, r3, addr) \
    asm volatile("ldmatrix.sync.aligned.m8n8.x4.shared.b16 {%0,%1,%2,%3}, [%4];" \
                 : "=r"(r0), "=r"(r1), "=r"(r2), "=r"(r3) : "r"(addr))

#define MMA16816H(d, a, b) \
    asm volatile("mma.sync.aligned.m16n8k16.row.col.f32.f16.f16.f32 " \
                 "{%0,%1,%2,%3}, {%4,%5,%6,%7}, {%8,%9}, {%0,%1,%2,%3};" \
                 : "+f"((d)[0]), "+f"((d)[1]), "+f"((d)[2]), "+f"((d)[3]) \
                 : "r"((a)[0]), "r"((a)[1]), "r"((a)[2]), "r"((a)[3]), \
                   "r"((b)[0]), "r"((b)[1]))

#define MMA16832F8(d, a, b) \
    asm volatile("mma.sync.aligned.m16n8k32.row.col.f32.e4m3.e4m3.f32 " \
                 "{%0,%1,%2,%3}, {%4,%5,%6,%7}, {%8,%9}, {%0,%1,%2,%3};" \
                 : "+f"((d)[0]), "+f"((d)[1]), "+f"((d)[2]), "+f"((d)[3]) \
                 : "r"((a)[0]), "r"((a)[1]), "r"((a)[2]), "r"((a)[3]), \
                   "r"((b)[0]), "r"((b)[1]))

// ordered-float encoding for unsigned atomicMax
__device__ __forceinline__ unsigned fenc(float f) {
    unsigned u = __float_as_uint(f);
    return (u & 0x80000000u) ? ~u : (u | 0x80000000u);
}
__device__ __forceinline__ float fdec(unsigned e) {
    return __uint_as_float((e & 0x80000000u) ? (e & 0x7fffffffu) : ~e);
}

// ---------------- fused: row sum-of-squares + fp32 -> e4m3 convert + cnt reset ----
__global__ void prep_fp8_kernel(const float* __restrict__ src, unsigned char* __restrict__ dst,
                                float* __restrict__ sumsq, int* __restrict__ cnt) {
    int row  = blockIdx.x * 8 + (threadIdx.x >> 5);
    int lane = threadIdx.x & 31;
    const float4* p = (const float4*)(src + (size_t)row * DKD);
    float4 v0 = p[lane * 2], v1 = p[lane * 2 + 1];
    float s = v0.x * v0.x;
    s = fmaf(v0.y, v0.y, s); s = fmaf(v0.z, v0.z, s); s = fmaf(v0.w, v0.w, s);
    s = fmaf(v1.x, v1.x, s); s = fmaf(v1.y, v1.y, s);
    s = fmaf(v1.z, v1.z, s); s = fmaf(v1.w, v1.w, s);
    #pragma unroll
    for (int o = 16; o; o >>= 1) s += __shfl_xor_sync(0xffffffffu, s, o);
    if (lane == 0) {
        sumsq[row] = s;
        if (cnt) cnt[row] = 0;
    }
    uint32_t p0 = __nv_cvt_float2_to_fp8x2(make_float2(v0.x, v0.y), __NV_SATFINITE, __NV_E4M3);
    uint32_t p1 = __nv_cvt_float2_to_fp8x2(make_float2(v0.z, v0.w), __NV_SATFINITE, __NV_E4M3);
    uint32_t p2 = __nv_cvt_float2_to_fp8x2(make_float2(v1.x, v1.y), __NV_SATFINITE, __NV_E4M3);
    uint32_t p3 = __nv_cvt_float2_to_fp8x2(make_float2(v1.z, v1.w), __NV_SATFINITE, __NV_E4M3);
    uint2 w;
    w.x = (p0 & 0xffffu) | (p1 << 16);
    w.y = (p2 & 0xffffu) | (p3 << 16);
    *(uint2*)(dst + (size_t)row * DKD + lane * 8) = w;
}

// ---------------- fp32 -> fp16 convert (vectorized) ----------------
__global__ void cvt_fp16_kernel(const float* __restrict__ src, __half* __restrict__ dst, int n4) {
    int i = blockIdx.x * blockDim.x + threadIdx.x;
    if (i < n4) {
        float4 v = ((const float4*)src)[i];
        __half2* d = (__half2*)dst;
        d[i * 2 + 0] = __floats2half2_rn(v.x, v.y);
        d[i * 2 + 1] = __floats2half2_rn(v.z, v.w);
    }
}

// ---------------- fp32 -> split fp16 hi/lo ----------------
__global__ void cvt_split16_kernel(const float* __restrict__ src,
                                   __half* __restrict__ hi, __half* __restrict__ lo,
                                   int n4) {
    int i = blockIdx.x * blockDim.x + threadIdx.x;
    if (i < n4) {
        float4 v = ((const float4*)src)[i];
        float h0 = __half2float(__float2half_rn(v.x));
        float h1 = __half2float(__float2half_rn(v.y));
        float h2 = __half2float(__float2half_rn(v.z));
        float h3 = __half2float(__float2half_rn(v.w));
        __half2* dh = (__half2*)hi;
        __half2* dl = (__half2*)lo;
        dh[i * 2 + 0] = __floats2half2_rn(h0, h1);
        dh[i * 2 + 1] = __floats2half2_rn(h2, h3);
        dl[i * 2 + 0] = __floats2half2_rn(v.x - h0, v.y - h1);
        dl[i * 2 + 1] = __floats2half2_rn(v.z - h2, v.w - h3);
    }
}

// ---------------- q projection: split-fp16 tensor MMA, q = x @ W_in^T + b_in ----
// M=4096, N=256, K=1024. Tile 64x64, K-chunks of 64, double buffer, 2 CTA/SM.
#define QI_AH   0
#define QI_AL   8192
#define QI_BH   16384
#define QI_BL   24576
#define QI_BUF  32768
#define QI_BIAS 65536
#define SMEM_QIN 65792

__global__ void __launch_bounds__(256, 2) qin_mma_kernel(
    const __half* __restrict__ xh, const __half* __restrict__ xl,
    const __half* __restrict__ wh, const __half* __restrict__ wl,
    const float* __restrict__ bias, float* __restrict__ C)
{
    extern __shared__ char smem[];
    uint32_t sb = smem_u32(smem);
    float* biash = (float*)(smem + QI_BIAS);

    int tid  = threadIdx.x;
    int lane = tid & 31, wid = tid >> 5;
    int m0 = blockIdx.x * 64, n0 = blockIdx.y * 64;
    int mbase = (wid >> 1) * 16;   // 4 m-warps of 16 rows
    int nbase = (wid & 1) * 32;    // 2 n-warps of 32 cols

    if (tid < 64) biash[tid] = bias[n0 + tid];

    // tile loader: 64 rows x 64 fp16 (128B per row), K row-stride = D elems
    auto load_tile = [&](uint32_t dst, const __half* src, int row0, int k0) {
        const char* base = (const char*)(src + (size_t)row0 * D + k0);
        for (int i = tid; i < 512; i += 256) {
            int row = i >> 3, c16 = i & 7;
            int colb = c16 * 16;
            uint32_t sw = (uint32_t)(colb ^ ((row & 7) << 4));
            CP_ASYNC16(sb + dst + row * 128 + sw, base + (size_t)row * (D * 2) + colb);
        }
    };

    // prologue: chunk 0
    load_tile(QI_AH, xh, m0, 0);
    load_tile(QI_AL, xl, m0, 0);
    load_tile(QI_BH, wh, n0, 0);
    load_tile(QI_BL, wl, n0, 0);
    CP_COMMIT();

    float acc[4][4] = {};

    const int NCH = D / 64;   // 16
    for (int j = 0; j < NCH; j++) {
        uint32_t buf = (j & 1) ? QI_BUF : 0;
        if (j + 1 < NCH) {
            uint32_t nb = ((j + 1) & 1) ? QI_BUF : 0;
            int k0 = (j + 1) * 64;
            load_tile(nb + QI_AH, xh, m0, k0);
            load_tile(nb + QI_AL, xl, m0, k0);
            load_tile(nb + QI_BH, wh, n0, k0);
            load_tile(nb + QI_BL, wl, n0, k0);
            CP_COMMIT();
            CP_WAIT(1);
        } else {
            CP_WAIT(0);
        }
        __syncthreads();

        #pragma unroll
        for (int kk = 0; kk < 4; kk++) {
            uint32_t afh[4], afl[4];
            {
                int row = mbase + (lane & 15);
                int colb = kk * 32 + ((lane >> 4) << 4);
                uint32_t sw = (uint32_t)(colb ^ ((row & 7) << 4));
                LDSM_X4(afh[0], afh[1], afh[2], afh[3], sb + buf + QI_AH + row * 128 + sw);
                LDSM_X4(afl[0], afl[1], afl[2], afl[3], sb + buf + QI_AL + row * 128 + sw);
            }
            uint32_t bfh[4][2], bfl[4][2];
            #pragma unroll
            for (int bt = 0; bt < 2; bt++) {
                int nrow = nbase + bt * 16 + (lane & 7) + ((lane >> 4) << 3);
                int colb = kk * 32 + ((lane & 8) << 1);
                uint32_t sw = (uint32_t)(colb ^ ((nrow & 7) << 4));
                LDSM_X4(bfh[bt * 2][0], bfh[bt * 2][1], bfh[bt * 2 + 1][0], bfh[bt * 2 + 1][1],
                        sb + buf + QI_BH + nrow * 128 + sw);
                LDSM_X4(bfl[bt * 2][0], bfl[bt * 2][1], bfl[bt * 2 + 1][0], bfl[bt * 2 + 1][1],
                        sb + buf + QI_BL + nrow * 128 + sw);
            }
            #pragma unroll
            for (int nt = 0; nt < 4; nt++) {
                MMA16816H(acc[nt], afh, bfh[nt]);
                MMA16816H(acc[nt], afh, bfl[nt]);
                MMA16816H(acc[nt], afl, bfh[nt]);
            }
        }
        __syncthreads();
    }

    // epilogue: add bias, store fp32 q
    int r0 = m0 + mbase + (lane >> 2);
    #pragma unroll
    for (int nt = 0; nt < 4; nt++) {
        int cl = nbase + nt * 8 + 2 * (lane & 3);
        float b0 = biash[cl], b1 = biash[cl + 1];
        float2 v0 = make_float2(acc[nt][0] + b0, acc[nt][1] + b1);
        float2 v1 = make_float2(acc[nt][2] + b0, acc[nt][3] + b1);
        *(float2*)&C[(size_t)r0 * DKD + n0 + cl] = v0;
        *(float2*)&C[(size_t)(r0 + 8) * DKD + n0 + cl] = v1;
    }
}

// ---------------- fp8 tensor scan: e4m3 mma.sync + threshold selection ----------------
#define SO_A    0
#define SO_B0   32768
#define SO_B1   65536
#define SO_K2   98304
#define SO_SMAX 98816
#define SMEM_SCAN 99328

__global__ void __launch_bounds__(256, 2) scan_mma_kernel(
    const unsigned char* __restrict__ qf, const unsigned char* __restrict__ kf,
    const float* __restrict__ k2buf, int* __restrict__ cnt, int* __restrict__ cidx)
{
    extern __shared__ char smem[];
    uint32_t sb = smem_u32(smem);
    float*    k2h  = (float*)(smem + SO_K2);
    unsigned* smax = (unsigned*)(smem + SO_SMAX);

    int tid  = threadIdx.x;
    int lane = tid & 31, wid = tid >> 5;
    int tok0 = blockIdx.x * TOKS;
    int keybase = blockIdx.y * (NKEYS / KSPLIT);
    int mbase = (wid >> 1) * 32;
    int nhalf = (wid & 1) * 64;

    if (tid < TOKS) smax[tid] = fenc(-1e30f);

    {
        const char* abase = (const char*)(qf + (size_t)tok0 * DKD);
        const char* bbase = (const char*)(kf + (size_t)keybase * DKD);
        for (int i = tid; i < 2048; i += 256) {
            int row = i >> 4, c16 = i & 15;
            int colb = c16 * 16;
            uint32_t sw = (uint32_t)(colb ^ ((row & 7) << 4));
            CP_ASYNC16(sb + SO_A + row * 256 + sw, abase + row * 256 + colb);
            CP_ASYNC16(sb + SO_B0 + row * 256 + sw, bbase + row * 256 + colb);
        }
        CP_COMMIT();
    }

    float acc[2][8][4];

    for (int t = 0; t < NT_TILES; t++) {
        int key0 = keybase + t * KEYT;

        if (t + 1 < NT_TILES) {
            uint32_t nb = ((t + 1) & 1) ? SO_B1 : SO_B0;
            const char* bbase = (const char*)(kf + (size_t)(key0 + KEYT) * DKD);
            for (int i = tid; i < 2048; i += 256) {
                int row = i >> 4, c16 = i & 15;
                int colb = c16 * 16;
                uint32_t sw = (uint32_t)(colb ^ ((row & 7) << 4));
                CP_ASYNC16(sb + nb + row * 256 + sw, bbase + row * 256 + colb);
            }
            CP_COMMIT();
            CP_WAIT(1);
        } else {
            CP_WAIT(0);
        }
        __syncthreads();

        if (tid < KEYT) k2h[tid] = 0.5f * k2buf[key0 + tid];

        #pragma unroll
        for (int mt = 0; mt < 2; mt++)
            #pragma unroll
            for (int nt = 0; nt < 8; nt++)
                #pragma unroll
                for (int e = 0; e < 4; e++) acc[mt][nt][e] = 0.f;

        uint32_t bbuf = sb + ((t & 1) ? SO_B1 : SO_B0);
        #pragma unroll
        for (int kk = 0; kk < 8; kk++) {
            uint32_t a[2][4];
            #pragma unroll
            for (int mt = 0; mt < 2; mt++) {
                int row = mbase + mt * 16 + (lane & 15);
                int colb = kk * 32 + ((lane >> 4) << 4);
                uint32_t ad = sb + SO_A + row * 256 + (uint32_t)(colb ^ ((row & 7) << 4));
                LDSM_X4(a[mt][0], a[mt][1], a[mt][2], a[mt][3], ad);
            }
            uint32_t b[8][2];
            #pragma unroll
            for (int bt = 0; bt < 4; bt++) {
                int n = nhalf + bt * 16 + (lane & 7) + ((lane >> 4) << 3);
                int colb = kk * 32 + ((lane & 8) << 1);
                uint32_t bd = bbuf + n * 256 + (uint32_t)(colb ^ ((n & 7) << 4));
                LDSM_X4(b[bt * 2][0], b[bt * 2][1], b[bt * 2 + 1][0], b[bt * 2 + 1][1], bd);
            }
            #pragma unroll
            for (int mt = 0; mt < 2; mt++)
                #pragma unroll
                for (int nt = 0; nt < 8; nt++)
                    MMA16832F8(acc[mt][nt], a[mt], b[nt]);
        }
        __syncthreads();

        // epilogue: scores, running max, selection
        {
            float rm[2][2];
            #pragma unroll
            for (int mt = 0; mt < 2; mt++) { rm[mt][0] = -1e30f; rm[mt][1] = -1e30f; }
            #pragma unroll
            for (int mt = 0; mt < 2; mt++) {
                #pragma unroll
                for (int nt = 0; nt < 8; nt++) {
                    float kc0 = k2h[nhalf + nt * 8 + 2 * (lane & 3)];
                    float kc1 = k2h[nhalf + nt * 8 + 2 * (lane & 3) + 1];
                    acc[mt][nt][0] -= kc0; acc[mt][nt][1] -= kc1;
                    acc[mt][nt][2] -= kc0; acc[mt][nt][3] -= kc1;
                    rm[mt][0] = fmaxf(rm[mt][0], fmaxf(acc[mt][nt][0], acc[mt][nt][1]));
                    rm[mt][1] = fmaxf(rm[mt][1], fmaxf(acc[mt][nt][2], acc[mt][nt][3]));
                }
            }
            #pragma unroll
            for (int mt = 0; mt < 2; mt++) {
                #pragma unroll
                for (int e = 0; e < 2; e++) {
                    float v = rm[mt][e];
                    v = fmaxf(v, __shfl_xor_sync(0xffffffffu, v, 1));
                    v = fmaxf(v, __shfl_xor_sync(0xffffffffu, v, 2));
                    rm[mt][e] = v;
                }
            }
            if ((lane & 3) == 0) {
                #pragma unroll
                for (int mt = 0; mt < 2; mt++) {
                    int r = mbase + mt * 16 + (lane >> 2);
                    atomicMax(&smax[r], fenc(rm[mt][0]));
                    atomicMax(&smax[r + 8], fenc(rm[mt][1]));
                }
            }
            __syncthreads();
            #pragma unroll
            for (int mt = 0; mt < 2; mt++) {
                int r0 = mbase + mt * 16 + (lane >> 2);
                float th0 = fdec(smax[r0]) - DELTA_S;
                float th1 = fdec(smax[r0 + 8]) - DELTA_S;
                int tokA = tok0 + r0, tokB = tokA + 8;
                #pragma unroll
                for (int nt = 0; nt < 8; nt++) {
                    int keyc = key0 + nhalf + nt * 8 + 2 * (lane & 3);
                    if (acc[mt][nt][0] > th0) {
                        int pos = atomicAdd(&cnt[tokA], 1);
                        if (pos < CAP) cidx[(size_t)tokA * CAP + pos] = keyc;
                    }
                    if (acc[mt][nt][1] > th0) {
                        int pos = atomicAdd(&cnt[tokA], 1);
                        if (pos < CAP) cidx[(size_t)tokA * CAP + pos] = keyc + 1;
                    }
                    if (acc[mt][nt][2] > th1) {
                        int pos = atomicAdd(&cnt[tokB], 1);
                        if (pos < CAP) cidx[(size_t)tokB * CAP + pos] = keyc;
                    }
                    if (acc[mt][nt][3] > th1) {
                        int pos = atomicAdd(&cnt[tokB], 1);
                        if (pos < CAP) cidx[(size_t)tokB * CAP + pos] = keyc + 1;
                    }
                }
            }
            // NOTE: no trailing __syncthreads — the post-CP_WAIT sync at the top of the
            // next iteration orders these smax/k2h reads against next-tile writes.
        }
    }
}

// ---------------- exact rescore + 8-round recursion + gather (emits fp16) ----------
__global__ void recurse_kernel(const float* __restrict__ keys, const float* __restrict__ vals,
                               const float* __restrict__ qbuf, const float* __restrict__ q2buf,
                               const float* __restrict__ k2buf, const int* __restrict__ cnt,
                               const int* __restrict__ cidx,
                               __half* __restrict__ a16) {
    __shared__ float    qrow[DKD];
    __shared__ float    lg_all[CAP];
    __shared__ int      keep_idx[MAXKEEP];
    __shared__ float    keep_lg[MAXKEEP];
    __shared__ float    wmat[KN][MAXKEEP];
    __shared__ unsigned s_maxenc;
    __shared__ int      s_nkeep;

    int tok = blockIdx.x, tid = threadIdx.x;
    int lane = tid & 31, wid = tid >> 5;
    int n = min(cnt[tok], CAP);

    qrow[tid] = qbuf[(size_t)tok * DKD + tid];
    if (tid == 0) { s_maxenc = fenc(-1e30f); s_nkeep = 0; }
    __syncthreads();

    float q2 = q2buf[tok];
    float4 q0 = *(const float4*)&qrow[lane * 4];
    float4 q1 = *(const float4*)&qrow[128 + lane * 4];
    for (int c = wid; c < n; c += 8) {
        int ki = cidx[(size_t)tok * CAP + c];
        const float4* kp = (const float4*)(keys + (size_t)ki * DKD);
        float4 k0 = kp[lane];
        float4 k1 = kp[lane + 32];
        float p = q0.x * k0.x;
        p = fmaf(q0.y, k0.y, p); p = fmaf(q0.z, k0.z, p); p = fmaf(q0.w, k0.w, p);
        p = fmaf(q1.x, k1.x, p); p = fmaf(q1.y, k1.y, p);
        p = fmaf(q1.z, k1.z, p); p = fmaf(q1.w, k1.w, p);
        #pragma unroll
        for (int o = 16; o; o >>= 1) p += __shfl_xor_sync(0xffffffffu, p, o);
        if (lane == 0) {
            float lg = -(q2 - 2.0f * p + k2buf[ki]) / 0.1f;
            lg_all[c] = lg;
            atomicMax(&s_maxenc, fenc(lg));
        }
    }
    __syncthreads();
    float cut = fdec(s_maxenc) - CUT_LG;
    for (int c = tid; c < n; c += 256) {
        if (lg_all[c] >= cut) {
            int pos = atomicAdd(&s_nkeep, 1);
            if (pos < MAXKEEP) {
                keep_idx[pos] = cidx[(size_t)tok * CAP + c];
                keep_lg[pos]  = lg_all[c];
            }
        }
    }
    __syncthreads();
    int nk = min(s_nkeep, MAXKEEP);
    // parallel rank sort by key index (indices unique -> deterministic)
    {
        int my = 0, rank = -1; float mylg = 0.f;
        if (tid < nk) {
            my = keep_idx[tid]; mylg = keep_lg[tid];
            rank = 0;
            for (int c = 0; c < nk; c++) rank += (keep_idx[c] < my);
        }
        __syncthreads();
        if (tid < nk) { keep_idx[rank] = my; keep_lg[rank] = mylg; }
        __syncthreads();
    }
    if (wid == 0) {
        for (int k = 0; k < KN; k++) {
            float lm = -1e30f;
            for (int c = lane; c < nk; c += 32) lm = fmaxf(lm, keep_lg[c]);
            #pragma unroll
            for (int o = 16; o; o >>= 1) lm = fmaxf(lm, __shfl_xor_sync(0xffffffffu, lm, o));
            float zs = 0.f;
            for (int c = lane; c < nk; c += 32) {
                float p = expf(keep_lg[c] - lm);
                wmat[k][c] = p;
                zs += p;
            }
            #pragma unroll
            for (int o = 16; o; o >>= 1) zs += __shfl_xor_sync(0xffffffffu, zs, o);
            float inv = 1.0f / zs;
            for (int c = lane; c < nk; c += 32) {
                float w = wmat[k][c] * inv;
                wmat[k][c] = w;
                keep_lg[c] += log1pf(-w + 1e-6f);
            }
            __syncwarp();
        }
    }
    __syncthreads();
    float a[KN] = {};
    for (int c = 0; c < nk; c++) {
        float v = vals[(size_t)keep_idx[c] * DM + tid];
        #pragma unroll
        for (int k = 0; k < KN; k++) a[k] = fmaf(wmat[k][c], v, a[k]);
    }
    #pragma unroll
    for (int k = 0; k < KN; k++)
        a16[(size_t)tok * FF + k * DM + tid] = __float2half_rn(a[k]);
}

// ---------------- W_out GEMM: fp16 tensor cores, double buffer, 2 CTA/SM ----------
#define WO_A    0
#define WO_B    16384
#define WO_BUF  32768
#define WO_BIAS 65536
#define SMEM_WOUT 66048

__global__ void __launch_bounds__(256, 2) wout_mma_kernel(
    const __half* __restrict__ a16, const __half* __restrict__ w16,
    const float* __restrict__ bias, float* __restrict__ C)
{
    extern __shared__ char smem[];
    uint32_t sb = smem_u32(smem);
    float* biash = (float*)(smem + WO_BIAS);

    int tid  = threadIdx.x;
    int lane = tid & 31, wid = tid >> 5;
    int m0 = blockIdx.x * 128, n0 = blockIdx.y * 128;
    int mbase = (wid >> 1) * 32;
    int nhalf = (wid & 1) * 64;

    if (tid < 128) biash[tid] = bias[n0 + tid];

    auto load_tile = [&](uint32_t dst, const __half* src, int row0, int k0) {
        const char* base = (const char*)(src + (size_t)row0 * FF + k0);
        for (int i = tid; i < 1024; i += 256) {
            int row = i >> 3, c16 = i & 7;
            int colb = c16 * 16;
            uint32_t sw = (uint32_t)(colb ^ ((row & 7) << 4));
            CP_ASYNC16(sb + dst + row * 128 + sw, base + (size_t)row * (FF * 2) + colb);
        }
    };

    load_tile(WO_A, a16, m0, 0);
    load_tile(WO_B, w16, n0, 0);
    CP_COMMIT();

    float acc[2][8][4] = {};

    const int NCH = FF / 64;   // 32
    for (int j = 0; j < NCH; j++) {
        uint32_t buf = (j & 1) ? WO_BUF : 0;
        if (j + 1 < NCH) {
            uint32_t nb = ((j + 1) & 1) ? WO_BUF : 0;
            int k0 = (j + 1) * 64;
            load_tile(nb + WO_A, a16, m0, k0);
            load_tile(nb + WO_B, w16, n0, k0);
            CP_COMMIT();
            CP_WAIT(1);
        } else {
            CP_WAIT(0);
        }
        __syncthreads();

        #pragma unroll
        for (int kk = 0; kk < 4; kk++) {
            uint32_t af[2][4];
            #pragma unroll
            for (int mt = 0; mt < 2; mt++) {
                int row = mbase + mt * 16 + (lane & 15);
                int colb = kk * 32 + ((lane >> 4) << 4);
                uint32_t sw = (uint32_t)(colb ^ ((row & 7) << 4));
                LDSM_X4(af[mt][0], af[mt][1], af[mt][2], af[mt][3],
                        sb + buf + WO_A + row * 128 + sw);
            }
            uint32_t bf[8][2];
            #pragma unroll
            for (int bt = 0; bt < 4; bt++) {
                int nrow = nhalf + bt * 16 + (lane & 7) + ((lane >> 4) << 3);
                int colb = kk * 32 + ((lane & 8) << 1);
                uint32_t sw = (uint32_t)(colb ^ ((nrow & 7) << 4));
                LDSM_X4(bf[bt * 2][0], bf[bt * 2][1], bf[bt * 2 + 1][0], bf[bt * 2 + 1][1],
                        sb + buf + WO_B + nrow * 128 + sw);
            }
            #pragma unroll
            for (int mt = 0; mt < 2; mt++)
                #pragma unroll
                for (int nt = 0; nt < 8; nt++)
                    MMA16816H(acc[mt][nt], af[mt], bf[nt]);
        }
        __syncthreads();
    }

    #pragma unroll
    for (int mt = 0; mt < 2; mt++) {
        int r0 = m0 + mbase + mt * 16 + (lane >> 2);
        #pragma unroll
        for (int nt = 0; nt < 8; nt++) {
            int cl = nhalf + nt * 8 + 2 * (lane & 3);
            float b0 = biash[cl], b1 = biash[cl + 1];
            float2 v0 = make_float2(acc[mt][nt][0] + b0, acc[mt][nt][1] + b1);
            float2 v1 = make_float2(acc[mt][nt][2] + b0, acc[mt][nt][3] + b1);
            *(float2*)&C[(size_t)r0 * D + n0 + cl] = v0;
            *(float2*)&C[(size_t)(r0 + 8) * D + n0 + cl] = v1;
        }
    }
}

// ---------------- RMSNorm (in place on d_out) ----------------
__global__ void rmsnorm_kernel(float* __restrict__ out, const float* __restrict__ rms_w) {
    __shared__ float wsum[8];
    __shared__ float s_tot;
    int tok = blockIdx.x, tid = threadIdx.x;
    float* row = out + (size_t)tok * D;
    float v[4];
    float ss = 0.f;
    #pragma unroll
    for (int e = 0; e < 4; e++) { v[e] = row[tid + e * 256]; ss = fmaf(v[e], v[e], ss); }
    #pragma unroll
    for (int o = 16; o; o >>= 1) ss += __shfl_xor_sync(0xffffffffu, ss, o);
    if ((tid & 31) == 0) wsum[tid >> 5] = ss;
    __syncthreads();
    if (tid == 0) {
        float t = 0.f;
        #pragma unroll
        for (int w = 0; w < 8; w++) t += wsum[w];
        s_tot = t;
    }
    __syncthreads();
    float var = s_tot / (float)D;
    float rs = 1.0f / sqrtf(var + 1e-6f);
    #pragma unroll
    for (int e = 0; e < 4; e++) {
        int d = tid + e * 256;
        row[d] = rms_w[d] * (v[e] * rs);
    }
}

// ---------------- host launch ----------------
extern "C" void kernel_launch(void* const* d_in, const int* in_sizes, int n_in,
                              void* d_out, int out_size) {
    const float* x     = (const float*)d_in[0];
    const float* keys  = (const float*)d_in[1];
    const float* vals  = (const float*)d_in[2];
    const float* W_in  = (const float*)d_in[3];
    const float* b_in  = (const float*)d_in[4];
    const float* W_out = (const float*)d_in[5];
    const float* b_out = (const float*)d_in[6];
    const float* rms_w = (const float*)d_in[7];
    float* out = (float*)d_out;
    (void)in_sizes; (void)n_in; (void)out_size;

    float *qp, *q2p, *k2p;
    int *cntp, *cidxp;
    unsigned char *kfp, *qfp;
    __half *a16p, *w16p, *xhp, *xlp, *wihp, *wilp;
    cudaGetSymbolAddress((void**)&qp,    g_q);
    cudaGetSymbolAddress((void**)&q2p,   g_q2);
    cudaGetSymbolAddress((void**)&k2p,   g_k2);
    cudaGetSymbolAddress((void**)&cntp,  g_cnt);
    cudaGetSymbolAddress((void**)&cidxp, g_cidx);
    cudaGetSymbolAddress((void**)&kfp,   g_keys_f8);
    cudaGetSymbolAddress((void**)&qfp,   g_q_f8);
    cudaGetSymbolAddress((void**)&a16p,  g_a16);
    cudaGetSymbolAddress((void**)&w16p,  g_w16);
    cudaGetSymbolAddress((void**)&xhp,   g_xh);
    cudaGetSymbolAddress((void**)&xlp,   g_xl);
    cudaGetSymbolAddress((void**)&wihp,  g_wih);
    cudaGetSymbolAddress((void**)&wilp,  g_wil);

    static int smem_set = 0;
    if (!smem_set) {
        cudaFuncSetAttribute(scan_mma_kernel, cudaFuncAttributeMaxDynamicSharedMemorySize, SMEM_SCAN);
        cudaFuncSetAttribute(wout_mma_kernel, cudaFuncAttributeMaxDynamicSharedMemorySize, SMEM_WOUT);
        cudaFuncSetAttribute(qin_mma_kernel,  cudaFuncAttributeMaxDynamicSharedMemorySize, SMEM_QIN);
        smem_set = 1;
    }

    // 1. keys: k2 + fp8 convert; W_out -> fp16; x,W_in -> split fp16
    prep_fp8_kernel<<<NKEYS / 8, 256>>>(keys, kfp, k2p, nullptr);
    cvt_fp16_kernel<<<(D * FF / 4 + 255) / 256, 256>>>(W_out, w16p, D * FF / 4);
    cvt_split16_kernel<<<(R * D / 4 + 255) / 256, 256>>>(x, xhp, xlp, R * D / 4);
    cvt_split16_kernel<<<(DKD * D / 4 + 255) / 256, 256>>>(W_in, wihp, wilp, DKD * D / 4);
    // 2. q = x @ W_in^T + b_in (split-fp16 tensor cores, fp32-exact)
    qin_mma_kernel<<<dim3(R / 64, DKD / 64), 256, SMEM_QIN>>>(xhp, xlp, wihp, wilp, b_in, qp);
    // 3. q: q2 + fp8 convert + cnt reset (fused)
    prep_fp8_kernel<<<R / 8, 256>>>(qp, qfp, q2p, cntp);
    // 4. fp8 tensor-core qk scan + candidate selection
    scan_mma_kernel<<<dim3(R / TOKS, KSPLIT), 256, SMEM_SCAN>>>(qfp, kfp, k2p, cntp, cidxp);
    // 5. exact rescore + 8-round recursion + gather -> fp16 nearest
    recurse_kernel<<<R, 256>>>(keys, vals, qp, q2p, k2p, cntp, cidxp, a16p);
    // 6. out = nearest @ W_out^T + b_out (fp16 tensor cores)
    wout_mma_kernel<<<dim3(R / 128, D / 128), 256, SMEM_WOUT>>>(a16p, w16p, b_out, out);
    // 7. RMSNorm * rms_w, in place
    rmsnorm_kernel<<<R, 256>>>(out, rms_w);
}

// round 9
// speedup vs baseline: 5.4122x; 1.0555x over previous
#include <cuda_runtime.h>
#include <cuda_bf16.h>
#include <cuda_fp16.h>
#include <cuda_fp8.h>
#include <math.h>
#include <stdint.h>

// Problem constants
#define R      4096      // B*T
#define D      1024
#define DKD    256       // DK
#define NKEYS  32768
#define DM     256
#define KN     8         // K_NEIGHBORS
#define FF     (KN*DM)   // 2048
#define CAP    1024
#define MAXKEEP 64
#define CUT_LG  131.0f
#define DELTA_S 13.5f    // fp8 scan pre-filter threshold (6.55 exact + fp8 noise margin)

// tensor scan tiling
#define TOKS   128
#define KEYT   128
#define KSPLIT 8
#define NT_TILES ((NKEYS / KSPLIT) / KEYT)   // 32

// ---------------- scratch (static device globals; no allocation) ----------------
__device__ __align__(16) float g_q[R * DKD];
__device__ __align__(16) float g_q2[R];
__device__ __align__(16) float g_k2[NKEYS];
__device__ __align__(16) int   g_cidx[(size_t)R * CAP];
__device__ __align__(16) int   g_cnt[R];
__device__ __align__(16) unsigned char g_keys_f8[(size_t)NKEYS * DKD];
__device__ __align__(16) unsigned char g_q_f8[(size_t)R * DKD];
// fp16 operands for the W_out GEMM
__device__ __align__(16) __half g_a16[(size_t)R * FF];
__device__ __align__(16) __half g_w16[(size_t)D * FF];
// split-fp16 operands for the q projection GEMM
__device__ __align__(16) __half g_xh[(size_t)R * D];
__device__ __align__(16) __half g_xl[(size_t)R * D];
__device__ __align__(16) __half g_wih[(size_t)DKD * D];
__device__ __align__(16) __half g_wil[(size_t)DKD * D];

// ---------------- PTX helpers ----------------
__device__ __forceinline__ uint32_t smem_u32(const void* p) {
    uint32_t a;
    asm("{ .reg .u64 t; cvta.to.shared.u64 t, %1; cvt.u32.u64 %0, t; }" : "=r"(a) : "l"(p));
    return a;
}
#define CP_ASYNC16(dst, src) \
    asm volatile("cp.async.cg.shared.global [%0], [%1], 16;" \
                 :: "r"((uint32_t)(dst)), "l"(__cvta_generic_to_global(src)) : "memory")
#define CP_COMMIT()    asm volatile("cp.async.commit_group;" ::: "memory")
#define CP_WAIT(n)     asm volatile("cp.async.wait_group %0;" :: "n"(n) : "memory")

#define LDSM_X4(r0, r1, r2, r3, addr) \
    asm volatile("ldmatrix.sync.aligned.m8n8.x4.shared.b16 {%0,%1,%2,%3}, [%4];" \
                 : "=r"(r0), "=r"(r1), "=r"(r2), "=r"(r3) : "r"(addr))

#define MMA16816H(d, a, b) \
    asm volatile("mma.sync.aligned.m16n8k16.row.col.f32.f16.f16.f32 " \
                 "{%0,%1,%2,%3}, {%4,%5,%6,%7}, {%8,%9}, {%0,%1,%2,%3};" \
                 : "+f"((d)[0]), "+f"((d)[1]), "+f"((d)[2]), "+f"((d)[3]) \
                 : "r"((a)[0]), "r"((a)[1]), "r"((a)[2]), "r"((a)[3]), \
                   "r"((b)[0]), "r"((b)[1]))

#define MMA16832F8(d, a, b) \
    asm volatile("mma.sync.aligned.m16n8k32.row.col.f32.e4m3.e4m3.f32 " \
                 "{%0,%1,%2,%3}, {%4,%5,%6,%7}, {%8,%9}, {%0,%1,%2,%3};" \
                 : "+f"((d)[0]), "+f"((d)[1]), "+f"((d)[2]), "+f"((d)[3]) \
                 : "r"((a)[0]), "r"((a)[1]), "r"((a)[2]), "r"((a)[3]), \
                   "r"((b)[0]), "r"((b)[1]))

// ordered-float encoding for unsigned atomicMax
__device__ __forceinline__ unsigned fenc(float f) {
    unsigned u = __float_as_uint(f);
    return (u & 0x80000000u) ? ~u : (u | 0x80000000u);
}
__device__ __forceinline__ float fdec(unsigned e) {
    return __uint_as_float((e & 0x80000000u) ? (e & 0x7fffffffu) : ~e);
}

// ---------------- fused: row sum-of-squares + fp32 -> e4m3 convert + cnt reset ----
__global__ void prep_fp8_kernel(const float* __restrict__ src, unsigned char* __restrict__ dst,
                                float* __restrict__ sumsq, int* __restrict__ cnt) {
    int row  = blockIdx.x * 8 + (threadIdx.x >> 5);
    int lane = threadIdx.x & 31;
    const float4* p = (const float4*)(src + (size_t)row * DKD);
    float4 v0 = p[lane * 2], v1 = p[lane * 2 + 1];
    float s = v0.x * v0.x;
    s = fmaf(v0.y, v0.y, s); s = fmaf(v0.z, v0.z, s); s = fmaf(v0.w, v0.w, s);
    s = fmaf(v1.x, v1.x, s); s = fmaf(v1.y, v1.y, s);
    s = fmaf(v1.z, v1.z, s); s = fmaf(v1.w, v1.w, s);
    #pragma unroll
    for (int o = 16; o; o >>= 1) s += __shfl_xor_sync(0xffffffffu, s, o);
    if (lane == 0) {
        sumsq[row] = s;
        if (cnt) cnt[row] = 0;
    }
    uint32_t p0 = __nv_cvt_float2_to_fp8x2(make_float2(v0.x, v0.y), __NV_SATFINITE, __NV_E4M3);
    uint32_t p1 = __nv_cvt_float2_to_fp8x2(make_float2(v0.z, v0.w), __NV_SATFINITE, __NV_E4M3);
    uint32_t p2 = __nv_cvt_float2_to_fp8x2(make_float2(v1.x, v1.y), __NV_SATFINITE, __NV_E4M3);
    uint32_t p3 = __nv_cvt_float2_to_fp8x2(make_float2(v1.z, v1.w), __NV_SATFINITE, __NV_E4M3);
    uint2 w;
    w.x = (p0 & 0xffffu) | (p1 << 16);
    w.y = (p2 & 0xffffu) | (p3 << 16);
    *(uint2*)(dst + (size_t)row * DKD + lane * 8) = w;
}

// ---------------- fp32 -> fp16 convert (vectorized) ----------------
__global__ void cvt_fp16_kernel(const float* __restrict__ src, __half* __restrict__ dst, int n4) {
    int i = blockIdx.x * blockDim.x + threadIdx.x;
    if (i < n4) {
        float4 v = ((const float4*)src)[i];
        __half2* d = (__half2*)dst;
        d[i * 2 + 0] = __floats2half2_rn(v.x, v.y);
        d[i * 2 + 1] = __floats2half2_rn(v.z, v.w);
    }
}

// ---------------- fp32 -> split fp16 hi/lo, two tensors in one launch ----------
__global__ void cvt_split16_dual_kernel(
    const float* __restrict__ srcA, __half* __restrict__ hiA, __half* __restrict__ loA, int n4a,
    const float* __restrict__ srcB, __half* __restrict__ hiB, __half* __restrict__ loB, int n4b) {
    int i = blockIdx.x * blockDim.x + threadIdx.x;
    const float* src; __half *hi, *lo; int idx;
    if (i < n4a)            { src = srcA; hi = hiA; lo = loA; idx = i; }
    else if (i < n4a + n4b) { src = srcB; hi = hiB; lo = loB; idx = i - n4a; }
    else return;
    float4 v = ((const float4*)src)[idx];
    float h0 = __half2float(__float2half_rn(v.x));
    float h1 = __half2float(__float2half_rn(v.y));
    float h2 = __half2float(__float2half_rn(v.z));
    float h3 = __half2float(__float2half_rn(v.w));
    __half2* dh = (__half2*)hi;
    __half2* dl = (__half2*)lo;
    dh[idx * 2 + 0] = __floats2half2_rn(h0, h1);
    dh[idx * 2 + 1] = __floats2half2_rn(h2, h3);
    dl[idx * 2 + 0] = __floats2half2_rn(v.x - h0, v.y - h1);
    dl[idx * 2 + 1] = __floats2half2_rn(v.z - h2, v.w - h3);
}

// ---------------- q projection: split-fp16 tensor MMA, q = x @ W_in^T + b_in ----
#define QI_AH   0
#define QI_AL   8192
#define QI_BH   16384
#define QI_BL   24576
#define QI_BUF  32768
#define QI_BIAS 65536
#define SMEM_QIN 65792

__global__ void __launch_bounds__(256, 2) qin_mma_kernel(
    const __half* __restrict__ xh, const __half* __restrict__ xl,
    const __half* __restrict__ wh, const __half* __restrict__ wl,
    const float* __restrict__ bias, float* __restrict__ C)
{
    extern __shared__ char smem[];
    uint32_t sb = smem_u32(smem);
    float* biash = (float*)(smem + QI_BIAS);

    int tid  = threadIdx.x;
    int lane = tid & 31, wid = tid >> 5;
    int m0 = blockIdx.x * 64, n0 = blockIdx.y * 64;
    int mbase = (wid >> 1) * 16;
    int nbase = (wid & 1) * 32;

    if (tid < 64) biash[tid] = bias[n0 + tid];

    auto load_tile = [&](uint32_t dst, const __half* src, int row0, int k0) {
        const char* base = (const char*)(src + (size_t)row0 * D + k0);
        for (int i = tid; i < 512; i += 256) {
            int row = i >> 3, c16 = i & 7;
            int colb = c16 * 16;
            uint32_t sw = (uint32_t)(colb ^ ((row & 7) << 4));
            CP_ASYNC16(sb + dst + row * 128 + sw, base + (size_t)row * (D * 2) + colb);
        }
    };

    load_tile(QI_AH, xh, m0, 0);
    load_tile(QI_AL, xl, m0, 0);
    load_tile(QI_BH, wh, n0, 0);
    load_tile(QI_BL, wl, n0, 0);
    CP_COMMIT();

    float acc[4][4] = {};

    const int NCH = D / 64;   // 16
    for (int j = 0; j < NCH; j++) {
        uint32_t buf = (j & 1) ? QI_BUF : 0;
        if (j + 1 < NCH) {
            uint32_t nb = ((j + 1) & 1) ? QI_BUF : 0;
            int k0 = (j + 1) * 64;
            load_tile(nb + QI_AH, xh, m0, k0);
            load_tile(nb + QI_AL, xl, m0, k0);
            load_tile(nb + QI_BH, wh, n0, k0);
            load_tile(nb + QI_BL, wl, n0, k0);
            CP_COMMIT();
            CP_WAIT(1);
        } else {
            CP_WAIT(0);
        }
        __syncthreads();

        #pragma unroll
        for (int kk = 0; kk < 4; kk++) {
            uint32_t afh[4], afl[4];
            {
                int row = mbase + (lane & 15);
                int colb = kk * 32 + ((lane >> 4) << 4);
                uint32_t sw = (uint32_t)(colb ^ ((row & 7) << 4));
                LDSM_X4(afh[0], afh[1], afh[2], afh[3], sb + buf + QI_AH + row * 128 + sw);
                LDSM_X4(afl[0], afl[1], afl[2], afl[3], sb + buf + QI_AL + row * 128 + sw);
            }
            uint32_t bfh[4][2], bfl[4][2];
            #pragma unroll
            for (int bt = 0; bt < 2; bt++) {
                int nrow = nbase + bt * 16 + (lane & 7) + ((lane >> 4) << 3);
                int colb = kk * 32 + ((lane & 8) << 1);
                uint32_t sw = (uint32_t)(colb ^ ((nrow & 7) << 4));
                LDSM_X4(bfh[bt * 2][0], bfh[bt * 2][1], bfh[bt * 2 + 1][0], bfh[bt * 2 + 1][1],
                        sb + buf + QI_BH + nrow * 128 + sw);
                LDSM_X4(bfl[bt * 2][0], bfl[bt * 2][1], bfl[bt * 2 + 1][0], bfl[bt * 2 + 1][1],
                        sb + buf + QI_BL + nrow * 128 + sw);
            }
            #pragma unroll
            for (int nt = 0; nt < 4; nt++) {
                MMA16816H(acc[nt], afh, bfh[nt]);
                MMA16816H(acc[nt], afh, bfl[nt]);
                MMA16816H(acc[nt], afl, bfh[nt]);
            }
        }
        __syncthreads();
    }

    int r0 = m0 + mbase + (lane >> 2);
    #pragma unroll
    for (int nt = 0; nt < 4; nt++) {
        int cl = nbase + nt * 8 + 2 * (lane & 3);
        float b0 = biash[cl], b1 = biash[cl + 1];
        float2 v0 = make_float2(acc[nt][0] + b0, acc[nt][1] + b1);
        float2 v1 = make_float2(acc[nt][2] + b0, acc[nt][3] + b1);
        *(float2*)&C[(size_t)r0 * DKD + n0 + cl] = v0;
        *(float2*)&C[(size_t)(r0 + 8) * DKD + n0 + cl] = v1;
    }
}

// ---------------- fp8 tensor scan: e4m3 mma.sync + threshold selection ----------------
#define SO_A    0
#define SO_B0   32768
#define SO_B1   65536
#define SO_K2   98304
#define SO_SMAX 98816
#define SMEM_SCAN 99328

__global__ void __launch_bounds__(256, 2) scan_mma_kernel(
    const unsigned char* __restrict__ qf, const unsigned char* __restrict__ kf,
    const float* __restrict__ k2buf, int* __restrict__ cnt, int* __restrict__ cidx)
{
    extern __shared__ char smem[];
    uint32_t sb = smem_u32(smem);
    float*    k2h  = (float*)(smem + SO_K2);
    unsigned* smax = (unsigned*)(smem + SO_SMAX);

    int tid  = threadIdx.x;
    int lane = tid & 31, wid = tid >> 5;
    int tok0 = blockIdx.x * TOKS;
    int keybase = blockIdx.y * (NKEYS / KSPLIT);
    int mbase = (wid >> 1) * 32;
    int nhalf = (wid & 1) * 64;

    if (tid < TOKS) smax[tid] = fenc(-1e30f);

    {
        const char* abase = (const char*)(qf + (size_t)tok0 * DKD);
        const char* bbase = (const char*)(kf + (size_t)keybase * DKD);
        for (int i = tid; i < 2048; i += 256) {
            int row = i >> 4, c16 = i & 15;
            int colb = c16 * 16;
            uint32_t sw = (uint32_t)(colb ^ ((row & 7) << 4));
            CP_ASYNC16(sb + SO_A + row * 256 + sw, abase + row * 256 + colb);
            CP_ASYNC16(sb + SO_B0 + row * 256 + sw, bbase + row * 256 + colb);
        }
        CP_COMMIT();
    }

    float acc[2][8][4];

    for (int t = 0; t < NT_TILES; t++) {
        int key0 = keybase + t * KEYT;

        if (t + 1 < NT_TILES) {
            uint32_t nb = ((t + 1) & 1) ? SO_B1 : SO_B0;
            const char* bbase = (const char*)(kf + (size_t)(key0 + KEYT) * DKD);
            for (int i = tid; i < 2048; i += 256) {
                int row = i >> 4, c16 = i & 15;
                int colb = c16 * 16;
                uint32_t sw = (uint32_t)(colb ^ ((row & 7) << 4));
                CP_ASYNC16(sb + nb + row * 256 + sw, bbase + row * 256 + colb);
            }
            CP_COMMIT();
            CP_WAIT(1);
        } else {
            CP_WAIT(0);
        }
        __syncthreads();

        if (tid < KEYT) k2h[tid] = 0.5f * k2buf[key0 + tid];

        #pragma unroll
        for (int mt = 0; mt < 2; mt++)
            #pragma unroll
            for (int nt = 0; nt < 8; nt++)
                #pragma unroll
                for (int e = 0; e < 4; e++) acc[mt][nt][e] = 0.f;

        uint32_t bbuf = sb + ((t & 1) ? SO_B1 : SO_B0);
        #pragma unroll
        for (int kk = 0; kk < 8; kk++) {
            uint32_t a[2][4];
            #pragma unroll
            for (int mt = 0; mt < 2; mt++) {
                int row = mbase + mt * 16 + (lane & 15);
                int colb = kk * 32 + ((lane >> 4) << 4);
                uint32_t ad = sb + SO_A + row * 256 + (uint32_t)(colb ^ ((row & 7) << 4));
                LDSM_X4(a[mt][0], a[mt][1], a[mt][2], a[mt][3], ad);
            }
            uint32_t b[8][2];
            #pragma unroll
            for (int bt = 0; bt < 4; bt++) {
                int n = nhalf + bt * 16 + (lane & 7) + ((lane >> 4) << 3);
                int colb = kk * 32 + ((lane & 8) << 1);
                uint32_t bd = bbuf + n * 256 + (uint32_t)(colb ^ ((n & 7) << 4));
                LDSM_X4(b[bt * 2][0], b[bt * 2][1], b[bt * 2 + 1][0], b[bt * 2 + 1][1], bd);
            }
            #pragma unroll
            for (int mt = 0; mt < 2; mt++)
                #pragma unroll
                for (int nt = 0; nt < 8; nt++)
                    MMA16832F8(acc[mt][nt], a[mt], b[nt]);
        }
        __syncthreads();

        // epilogue: scores, running max, selection
        {
            float rm[2][2];
            #pragma unroll
            for (int mt = 0; mt < 2; mt++) { rm[mt][0] = -1e30f; rm[mt][1] = -1e30f; }
            #pragma unroll
            for (int mt = 0; mt < 2; mt++) {
                #pragma unroll
                for (int nt = 0; nt < 8; nt++) {
                    float kc0 = k2h[nhalf + nt * 8 + 2 * (lane & 3)];
                    float kc1 = k2h[nhalf + nt * 8 + 2 * (lane & 3) + 1];
                    acc[mt][nt][0] -= kc0; acc[mt][nt][1] -= kc1;
                    acc[mt][nt][2] -= kc0; acc[mt][nt][3] -= kc1;
                    rm[mt][0] = fmaxf(rm[mt][0], fmaxf(acc[mt][nt][0], acc[mt][nt][1]));
                    rm[mt][1] = fmaxf(rm[mt][1], fmaxf(acc[mt][nt][2], acc[mt][nt][3]));
                }
            }
            #pragma unroll
            for (int mt = 0; mt < 2; mt++) {
                #pragma unroll
                for (int e = 0; e < 2; e++) {
                    float v = rm[mt][e];
                    v = fmaxf(v, __shfl_xor_sync(0xffffffffu, v, 1));
                    v = fmaxf(v, __shfl_xor_sync(0xffffffffu, v, 2));
                    rm[mt][e] = v;
                }
            }
            if ((lane & 3) == 0) {
                #pragma unroll
                for (int mt = 0; mt < 2; mt++) {
                    int r = mbase + mt * 16 + (lane >> 2);
                    atomicMax(&smax[r], fenc(rm[mt][0]));
                    atomicMax(&smax[r + 8], fenc(rm[mt][1]));
                }
            }
            __syncthreads();
            #pragma unroll
            for (int mt = 0; mt < 2; mt++) {
                int r0 = mbase + mt * 16 + (lane >> 2);
                float th0 = fdec(smax[r0]) - DELTA_S;
                float th1 = fdec(smax[r0 + 8]) - DELTA_S;
                int tokA = tok0 + r0, tokB = tokA + 8;
                #pragma unroll
                for (int nt = 0; nt < 8; nt++) {
                    int keyc = key0 + nhalf + nt * 8 + 2 * (lane & 3);
                    if (acc[mt][nt][0] > th0) {
                        int pos = atomicAdd(&cnt[tokA], 1);
                        if (pos < CAP) cidx[(size_t)tokA * CAP + pos] = keyc;
                    }
                    if (acc[mt][nt][1] > th0) {
                        int pos = atomicAdd(&cnt[tokA], 1);
                        if (pos < CAP) cidx[(size_t)tokA * CAP + pos] = keyc + 1;
                    }
                    if (acc[mt][nt][2] > th1) {
                        int pos = atomicAdd(&cnt[tokB], 1);
                        if (pos < CAP) cidx[(size_t)tokB * CAP + pos] = keyc;
                    }
                    if (acc[mt][nt][3] > th1) {
                        int pos = atomicAdd(&cnt[tokB], 1);
                        if (pos < CAP) cidx[(size_t)tokB * CAP + pos] = keyc + 1;
                    }
                }
            }
        }
    }
}

// ---------------- exact rescore + 8-round recursion + gather (emits fp16) ----------
__global__ void recurse_kernel(const float* __restrict__ keys, const float* __restrict__ vals,
                               const float* __restrict__ qbuf, const float* __restrict__ q2buf,
                               const float* __restrict__ k2buf, const int* __restrict__ cnt,
                               const int* __restrict__ cidx,
                               __half* __restrict__ a16) {
    __shared__ float    qrow[DKD];
    __shared__ int      cidx_sh[CAP];
    __shared__ float    lg_all[CAP];
    __shared__ int      keep_idx[MAXKEEP];
    __shared__ float    keep_lg[MAXKEEP];
    __shared__ float    wmat[KN][MAXKEEP];
    __shared__ unsigned s_maxenc;
    __shared__ int      s_nkeep;

    int tok = blockIdx.x, tid = threadIdx.x;
    int lane = tid & 31, wid = tid >> 5;
    int n = min(cnt[tok], CAP);

    qrow[tid] = qbuf[(size_t)tok * DKD + tid];
    if (tid == 0) { s_maxenc = fenc(-1e30f); s_nkeep = 0; }
    // stage candidate indices into smem (coalesced)
    for (int c = tid; c < n; c += 256) cidx_sh[c] = cidx[(size_t)tok * CAP + c];
    __syncthreads();

    float q2 = q2buf[tok];
    float4 q0 = *(const float4*)&qrow[lane * 4];
    float4 q1 = *(const float4*)&qrow[128 + lane * 4];
    // exact fp32 rescore, 2 candidates per warp iteration (MLP=2)
    for (int c0 = wid * 2; c0 < n; c0 += 16) {
        int kiA = cidx_sh[c0];
        bool hasB = (c0 + 1 < n);
        int kiB = hasB ? cidx_sh[c0 + 1] : kiA;
        const float4* kpA = (const float4*)(keys + (size_t)kiA * DKD);
        const float4* kpB = (const float4*)(keys + (size_t)kiB * DKD);
        float4 a0 = kpA[lane], a1 = kpA[lane + 32];
        float4 b0 = kpB[lane], b1 = kpB[lane + 32];
        float pA = q0.x * a0.x;
        pA = fmaf(q0.y, a0.y, pA); pA = fmaf(q0.z, a0.z, pA); pA = fmaf(q0.w, a0.w, pA);
        pA = fmaf(q1.x, a1.x, pA); pA = fmaf(q1.y, a1.y, pA);
        pA = fmaf(q1.z, a1.z, pA); pA = fmaf(q1.w, a1.w, pA);
        float pB = q0.x * b0.x;
        pB = fmaf(q0.y, b0.y, pB); pB = fmaf(q0.z, b0.z, pB); pB = fmaf(q0.w, b0.w, pB);
        pB = fmaf(q1.x, b1.x, pB); pB = fmaf(q1.y, b1.y, pB);
        pB = fmaf(q1.z, b1.z, pB); pB = fmaf(q1.w, b1.w, pB);
        #pragma unroll
        for (int o = 16; o; o >>= 1) {
            pA += __shfl_xor_sync(0xffffffffu, pA, o);
            pB += __shfl_xor_sync(0xffffffffu, pB, o);
        }
        if (lane == 0) {
            float lgA = -(q2 - 2.0f * pA + k2buf[kiA]) / 0.1f;
            lg_all[c0] = lgA;
            unsigned m = fenc(lgA);
            if (hasB) {
                float lgB = -(q2 - 2.0f * pB + k2buf[kiB]) / 0.1f;
                lg_all[c0 + 1] = lgB;
                unsigned mB = fenc(lgB);
                if (mB > m) m = mB;
            }
            atomicMax(&s_maxenc, m);
        }
    }
    __syncthreads();
    float cut = fdec(s_maxenc) - CUT_LG;
    for (int c = tid; c < n; c += 256) {
        if (lg_all[c] >= cut) {
            int pos = atomicAdd(&s_nkeep, 1);
            if (pos < MAXKEEP) {
                keep_idx[pos] = cidx_sh[c];
                keep_lg[pos]  = lg_all[c];
            }
        }
    }
    __syncthreads();
    int nk = min(s_nkeep, MAXKEEP);
    // parallel rank sort by key index (indices unique -> deterministic)
    {
        int my = 0, rank = -1; float mylg = 0.f;
        if (tid < nk) {
            my = keep_idx[tid]; mylg = keep_lg[tid];
            rank = 0;
            for (int c = 0; c < nk; c++) rank += (keep_idx[c] < my);
        }
        __syncthreads();
        if (tid < nk) { keep_idx[rank] = my; keep_lg[rank] = mylg; }
        __syncthreads();
    }
    if (wid == 0) {
        for (int k = 0; k < KN; k++) {
            float lm = -1e30f;
            for (int c = lane; c < nk; c += 32) lm = fmaxf(lm, keep_lg[c]);
            #pragma unroll
            for (int o = 16; o; o >>= 1) lm = fmaxf(lm, __shfl_xor_sync(0xffffffffu, lm, o));
            float zs = 0.f;
            for (int c = lane; c < nk; c += 32) {
                float p = expf(keep_lg[c] - lm);
                wmat[k][c] = p;
                zs += p;
            }
            #pragma unroll
            for (int o = 16; o; o >>= 1) zs += __shfl_xor_sync(0xffffffffu, zs, o);
            float inv = 1.0f / zs;
            for (int c = lane; c < nk; c += 32) {
                float w = wmat[k][c] * inv;
                wmat[k][c] = w;
                keep_lg[c] += log1pf(-w + 1e-6f);
            }
            __syncwarp();
        }
    }
    __syncthreads();
    float a[KN] = {};
    for (int c = 0; c < nk; c++) {
        float v = vals[(size_t)keep_idx[c] * DM + tid];
        #pragma unroll
        for (int k = 0; k < KN; k++) a[k] = fmaf(wmat[k][c], v, a[k]);
    }
    #pragma unroll
    for (int k = 0; k < KN; k++)
        a16[(size_t)tok * FF + k * DM + tid] = __float2half_rn(a[k]);
}

// ---------------- W_out GEMM: fp16 tensor cores, double buffer, 2 CTA/SM ----------
#define WO_A    0
#define WO_B    16384
#define WO_BUF  32768
#define WO_BIAS 65536
#define SMEM_WOUT 66048

__global__ void __launch_bounds__(256, 2) wout_mma_kernel(
    const __half* __restrict__ a16, const __half* __restrict__ w16,
    const float* __restrict__ bias, float* __restrict__ C)
{
    extern __shared__ char smem[];
    uint32_t sb = smem_u32(smem);
    float* biash = (float*)(smem + WO_BIAS);

    int tid  = threadIdx.x;
    int lane = tid & 31, wid = tid >> 5;
    int m0 = blockIdx.x * 128, n0 = blockIdx.y * 128;
    int mbase = (wid >> 1) * 32;
    int nhalf = (wid & 1) * 64;

    if (tid < 128) biash[tid] = bias[n0 + tid];

    auto load_tile = [&](uint32_t dst, const __half* src, int row0, int k0) {
        const char* base = (const char*)(src + (size_t)row0 * FF + k0);
        for (int i = tid; i < 1024; i += 256) {
            int row = i >> 3, c16 = i & 7;
            int colb = c16 * 16;
            uint32_t sw = (uint32_t)(colb ^ ((row & 7) << 4));
            CP_ASYNC16(sb + dst + row * 128 + sw, base + (size_t)row * (FF * 2) + colb);
        }
    };

    load_tile(WO_A, a16, m0, 0);
    load_tile(WO_B, w16, n0, 0);
    CP_COMMIT();

    float acc[2][8][4] = {};

    const int NCH = FF / 64;   // 32
    for (int j = 0; j < NCH; j++) {
        uint32_t buf = (j & 1) ? WO_BUF : 0;
        if (j + 1 < NCH) {
            uint32_t nb = ((j + 1) & 1) ? WO_BUF : 0;
            int k0 = (j + 1) * 64;
            load_tile(nb + WO_A, a16, m0, k0);
            load_tile(nb + WO_B, w16, n0, k0);
            CP_COMMIT();
            CP_WAIT(1);
        } else {
            CP_WAIT(0);
        }
        __syncthreads();

        #pragma unroll
        for (int kk = 0; kk < 4; kk++) {
            uint32_t af[2][4];
            #pragma unroll
            for (int mt = 0; mt < 2; mt++) {
                int row = mbase + mt * 16 + (lane & 15);
                int colb = kk * 32 + ((lane >> 4) << 4);
                uint32_t sw = (uint32_t)(colb ^ ((row & 7) << 4));
                LDSM_X4(af[mt][0], af[mt][1], af[mt][2], af[mt][3],
                        sb + buf + WO_A + row * 128 + sw);
            }
            uint32_t bf[8][2];
            #pragma unroll
            for (int bt = 0; bt < 4; bt++) {
                int nrow = nhalf + bt * 16 + (lane & 7) + ((lane >> 4) << 3);
                int colb = kk * 32 + ((lane & 8) << 1);
                uint32_t sw = (uint32_t)(colb ^ ((nrow & 7) << 4));
                LDSM_X4(bf[bt * 2][0], bf[bt * 2][1], bf[bt * 2 + 1][0], bf[bt * 2 + 1][1],
                        sb + buf + WO_B + nrow * 128 + sw);
            }
            #pragma unroll
            for (int mt = 0; mt < 2; mt++)
                #pragma unroll
                for (int nt = 0; nt < 8; nt++)
                    MMA16816H(acc[mt][nt], af[mt], bf[nt]);
        }
        __syncthreads();
    }

    #pragma unroll
    for (int mt = 0; mt < 2; mt++) {
        int r0 = m0 + mbase + mt * 16 + (lane >> 2);
        #pragma unroll
        for (int nt = 0; nt < 8; nt++) {
            int cl = nhalf + nt * 8 + 2 * (lane & 3);
            float b0 = biash[cl], b1 = biash[cl + 1];
            float2 v0 = make_float2(acc[mt][nt][0] + b0, acc[mt][nt][1] + b1);
            float2 v1 = make_float2(acc[mt][nt][2] + b0, acc[mt][nt][3] + b1);
            *(float2*)&C[(size_t)r0 * D + n0 + cl] = v0;
            *(float2*)&C[(size_t)(r0 + 8) * D + n0 + cl] = v1;
        }
    }
}

// ---------------- RMSNorm (in place on d_out) ----------------
__global__ void rmsnorm_kernel(float* __restrict__ out, const float* __restrict__ rms_w) {
    __shared__ float wsum[8];
    __shared__ float s_tot;
    int tok = blockIdx.x, tid = threadIdx.x;
    float* row = out + (size_t)tok * D;
    float v[4];
    float ss = 0.f;
    #pragma unroll
    for (int e = 0; e < 4; e++) { v[e] = row[tid + e * 256]; ss = fmaf(v[e], v[e], ss); }
    #pragma unroll
    for (int o = 16; o; o >>= 1) ss += __shfl_xor_sync(0xffffffffu, ss, o);
    if ((tid & 31) == 0) wsum[tid >> 5] = ss;
    __syncthreads();
    if (tid == 0) {
        float t = 0.f;
        #pragma unroll
        for (int w = 0; w < 8; w++) t += wsum[w];
        s_tot = t;
    }
    __syncthreads();
    float var = s_tot / (float)D;
    float rs = 1.0f / sqrtf(var + 1e-6f);
    #pragma unroll
    for (int e = 0; e < 4; e++) {
        int d = tid + e * 256;
        row[d] = rms_w[d] * (v[e] * rs);
    }
}

// ---------------- host launch ----------------
extern "C" void kernel_launch(void* const* d_in, const int* in_sizes, int n_in,
                              void* d_out, int out_size) {
    const float* x     = (const float*)d_in[0];
    const float* keys  = (const float*)d_in[1];
    const float* vals  = (const float*)d_in[2];
    const float* W_in  = (const float*)d_in[3];
    const float* b_in  = (const float*)d_in[4];
    const float* W_out = (const float*)d_in[5];
    const float* b_out = (const float*)d_in[6];
    const float* rms_w = (const float*)d_in[7];
    float* out = (float*)d_out;
    (void)in_sizes; (void)n_in; (void)out_size;

    float *qp, *q2p, *k2p;
    int *cntp, *cidxp;
    unsigned char *kfp, *qfp;
    __half *a16p, *w16p, *xhp, *xlp, *wihp, *wilp;
    cudaGetSymbolAddress((void**)&qp,    g_q);
    cudaGetSymbolAddress((void**)&q2p,   g_q2);
    cudaGetSymbolAddress((void**)&k2p,   g_k2);
    cudaGetSymbolAddress((void**)&cntp,  g_cnt);
    cudaGetSymbolAddress((void**)&cidxp, g_cidx);
    cudaGetSymbolAddress((void**)&kfp,   g_keys_f8);
    cudaGetSymbolAddress((void**)&qfp,   g_q_f8);
    cudaGetSymbolAddress((void**)&a16p,  g_a16);
    cudaGetSymbolAddress((void**)&w16p,  g_w16);
    cudaGetSymbolAddress((void**)&xhp,   g_xh);
    cudaGetSymbolAddress((void**)&xlp,   g_xl);
    cudaGetSymbolAddress((void**)&wihp,  g_wih);
    cudaGetSymbolAddress((void**)&wilp,  g_wil);

    static int smem_set = 0;
    if (!smem_set) {
        cudaFuncSetAttribute(scan_mma_kernel, cudaFuncAttributeMaxDynamicSharedMemorySize, SMEM_SCAN);
        cudaFuncSetAttribute(wout_mma_kernel, cudaFuncAttributeMaxDynamicSharedMemorySize, SMEM_WOUT);
        cudaFuncSetAttribute(qin_mma_kernel,  cudaFuncAttributeMaxDynamicSharedMemorySize, SMEM_QIN);
        smem_set = 1;
    }

    const int n4x = R * D / 4, n4w = DKD * D / 4;

    // 1. keys: k2 + fp8 convert; W_out -> fp16; x + W_in -> split fp16 (one launch)
    prep_fp8_kernel<<<NKEYS / 8, 256>>>(keys, kfp, k2p, nullptr);
    cvt_fp16_kernel<<<(D * FF / 4 + 255) / 256, 256>>>(W_out, w16p, D * FF / 4);
    cvt_split16_dual_kernel<<<(n4x + n4w + 255) / 256, 256>>>(x, xhp, xlp, n4x,
                                                              W_in, wihp, wilp, n4w);
    // 2. q = x @ W_in^T + b_in (split-fp16 tensor cores, fp32-exact)
    qin_mma_kernel<<<dim3(R / 64, DKD / 64), 256, SMEM_QIN>>>(xhp, xlp, wihp, wilp, b_in, qp);
    // 3. q: q2 + fp8 convert + cnt reset (fused)
    prep_fp8_kernel<<<R / 8, 256>>>(qp, qfp, q2p, cntp);
    // 4. fp8 tensor-core qk scan + candidate selection
    scan_mma_kernel<<<dim3(R / TOKS, KSPLIT), 256, SMEM_SCAN>>>(qfp, kfp, k2p, cntp, cidxp);
    // 5. exact rescore (pipelined) + 8-round recursion + gather -> fp16 nearest
    recurse_kernel<<<R, 256>>>(keys, vals, qp, q2p, k2p, cntp, cidxp, a16p);
    // 6. out = nearest @ W_out^T + b_out (fp16 tensor cores)
    wout_mma_kernel<<<dim3(R / 128, D / 128), 256, SMEM_WOUT>>>(a16p, w16p, b_out, out);
    // 7. RMSNorm * rms_w, in place
    rmsnorm_kernel<<<R, 256>>>(out, rms_w);
}